// round 1
// baseline (speedup 1.0000x reference)
#include <cuda_runtime.h>
#include <math.h>

// Shapes (fixed): B=4, N=256, D=256, H=8, HD=32, DFF=1024
// inputs: 0 h,1 e,2 We,3 be,4 Ws,5 bs,6 Wd,7 bd,8 Wb,9 bb,10 ln1_g,11 ln1_b,
//         12 Wqkv,13 bqkv,14 Wo,15 bo,16 ln2_g,17 ln2_b,18 W1,19 b1,20 W2,21 b2
// output: h2 [4,256,256] then e_new [4,256,256,256]

#define BN 1024            // B*N rows of node tensors
#define DD 256

// ---------------- scratch (static device globals; no allocs) ----------------
__device__ __align__(16) float g_Hs[BN * DD];
__device__ __align__(16) float g_Hd[BN * DD];
__device__ __align__(16) float g_x1[BN * DD];
__device__ __align__(16) float g_qkv[BN * 768];
__device__ __align__(16) float g_bias[4 * 8 * 256 * 256];
__device__ __align__(16) float g_o[BN * DD];
__device__ __align__(16) float g_h1[BN * DD];
__device__ __align__(16) float g_y[BN * DD];
__device__ __align__(16) float g_ffn[BN * 1024];

// ---------------- LayerNorm over last dim (256), one block per row ----------
__global__ __launch_bounds__(256) void ln_kernel(
    const float* __restrict__ in, const float* __restrict__ g,
    const float* __restrict__ b, float* __restrict__ out)
{
    int row = blockIdx.x;
    int t = threadIdx.x;
    float v = in[(size_t)row * 256 + t];
    __shared__ float red[8];

    float s = v;
    #pragma unroll
    for (int o = 16; o; o >>= 1) s += __shfl_xor_sync(0xffffffffu, s, o);
    if ((t & 31) == 0) red[t >> 5] = s;
    __syncthreads();
    float mean = (red[0] + red[1] + red[2] + red[3] +
                  red[4] + red[5] + red[6] + red[7]) * (1.0f / 256.0f);
    float d = v - mean;
    __syncthreads();
    s = d * d;
    #pragma unroll
    for (int o = 16; o; o >>= 1) s += __shfl_xor_sync(0xffffffffu, s, o);
    if ((t & 31) == 0) red[t >> 5] = s;
    __syncthreads();
    float var = (red[0] + red[1] + red[2] + red[3] +
                 red[4] + red[5] + red[6] + red[7]) * (1.0f / 256.0f);
    out[(size_t)row * 256 + t] = d * rsqrtf(var + 1e-5f) * g[t] + b[t];
}

// ---------------- generic fp32 GEMM: out = op(A@W + bias) [+ res] ----------
// A: [M,K], W: [K,Ncols], tile 64x64, 256 threads, 4x4 reg tile.
// OP: 0=none, 1=exact GELU
__device__ __forceinline__ float gelu_exact(float x) {
    return 0.5f * x * (1.0f + erff(x * 0.70710678118654752f));
}

template <int OP>
__global__ __launch_bounds__(256) void gemm64(
    const float* __restrict__ A, const float* __restrict__ W,
    const float* __restrict__ bias, const float* __restrict__ res,
    float* __restrict__ out, int K, int Ncols)
{
    __shared__ float As[64][16];
    __shared__ float Bs[16][64];
    const int tid = threadIdx.x;
    const int m0 = blockIdx.y * 64;
    const int c0 = blockIdx.x * 64;
    const int ty = tid >> 4;   // 0..15 (row group)
    const int tx = tid & 15;   // 0..15 (col group)

    float acc[4][4] = {};

    for (int k0 = 0; k0 < K; k0 += 16) {
        {   // A tile: 64x16
            int r = tid >> 2, q = tid & 3;
            *(float4*)&As[r][q * 4] =
                *(const float4*)(A + (size_t)(m0 + r) * K + k0 + q * 4);
        }
        {   // B tile: 16x64
            int kk = tid >> 4, q = tid & 15;
            *(float4*)&Bs[kk][q * 4] =
                *(const float4*)(W + (size_t)(k0 + kk) * Ncols + c0 + q * 4);
        }
        __syncthreads();
        #pragma unroll
        for (int k = 0; k < 16; ++k) {
            float a[4];
            #pragma unroll
            for (int r = 0; r < 4; ++r) a[r] = As[ty * 4 + r][k];
            float4 bv = *(float4*)&Bs[k][tx * 4];
            #pragma unroll
            for (int r = 0; r < 4; ++r) {
                acc[r][0] += a[r] * bv.x;
                acc[r][1] += a[r] * bv.y;
                acc[r][2] += a[r] * bv.z;
                acc[r][3] += a[r] * bv.w;
            }
        }
        __syncthreads();
    }

    float4 bs4 = *(const float4*)(bias + c0 + tx * 4);
    #pragma unroll
    for (int r = 0; r < 4; ++r) {
        int m = m0 + ty * 4 + r;
        float v0 = acc[r][0] + bs4.x;
        float v1 = acc[r][1] + bs4.y;
        float v2 = acc[r][2] + bs4.z;
        float v3 = acc[r][3] + bs4.w;
        if (OP == 1) {
            v0 = gelu_exact(v0); v1 = gelu_exact(v1);
            v2 = gelu_exact(v2); v3 = gelu_exact(v3);
        }
        if (res) {
            float4 rr = *(const float4*)(res + (size_t)m * Ncols + c0 + tx * 4);
            v0 += rr.x; v1 += rr.y; v2 += rr.z; v3 += rr.w;
        }
        *(float4*)(out + (size_t)m * Ncols + c0 + tx * 4) =
            make_float4(v0, v1, v2, v3);
    }
}

// ---------------- fused edge kernel --------------------------------------
// Per block: 64 consecutive rows m (same b,i; 64 j's) x full 256 cols.
// e_new[m, :] = relu(e[m,:]@We + be + Hs[b,i,:] + Hd[b,j,:])
// bias[b,h,i,j] = e_new[m,:].Wb[:,h] + bb[h]
// Thread (ty=warp 0..7, tx=lane): rows ty*8+r, cols c*32+tx (c=0..7).
__global__ __launch_bounds__(256, 2) void edge_kernel(
    const float* __restrict__ e, const float* __restrict__ We,
    const float* __restrict__ be, const float* __restrict__ Hs,
    const float* __restrict__ Hd, const float* __restrict__ Wb,
    const float* __restrict__ bb, float* __restrict__ e_new,
    float* __restrict__ bias)
{
    __shared__ float As[64][16];
    __shared__ float Bs[16][256];
    __shared__ float sHs[256];         // Hs row + be
    __shared__ float sWbT[8][256];     // Wb transposed [h][d]
    __shared__ float sbias[64][8];

    const int tid = threadIdx.x;
    const int m0 = blockIdx.x * 64;
    const int b  = m0 >> 16;
    const int i  = (m0 >> 8) & 255;
    const int j0 = m0 & 255;           // multiple of 64
    const int ty = tid >> 5;           // warp id = row group
    const int tx = tid & 31;           // lane = col lane

    for (int t = tid; t < 256; t += 256)
        sHs[t] = Hs[(((size_t)b * 256 + i) << 8) + t] + be[t];
    for (int idx = tid; idx < 2048; idx += 256) {
        int hh = idx >> 8, dc = idx & 255;
        sWbT[hh][dc] = Wb[dc * 8 + hh];
    }

    float acc[8][8] = {};
    const float* Arow = e + (size_t)m0 * 256;

    for (int k0 = 0; k0 < 256; k0 += 16) {
        {   // A tile 64x16
            int r = tid >> 2, q = tid & 3;
            *(float4*)&As[r][q * 4] =
                *(const float4*)(Arow + (size_t)r * 256 + k0 + q * 4);
        }
        #pragma unroll
        for (int p = 0; p < 4; ++p) {   // B tile 16x256
            int idx = tid + p * 256;
            int kk = idx >> 6, q = idx & 63;
            *(float4*)&Bs[kk][q * 4] =
                *(const float4*)(We + (size_t)(k0 + kk) * 256 + q * 4);
        }
        __syncthreads();
        #pragma unroll
        for (int k = 0; k < 16; ++k) {
            float a[8], bv[8];
            #pragma unroll
            for (int r = 0; r < 8; ++r) a[r] = As[ty * 8 + r][k];   // broadcast
            #pragma unroll
            for (int c = 0; c < 8; ++c) bv[c] = Bs[k][c * 32 + tx]; // conflict-free
            #pragma unroll
            for (int r = 0; r < 8; ++r)
                #pragma unroll
                for (int c = 0; c < 8; ++c)
                    acc[r][c] += a[r] * bv[c];
        }
        __syncthreads();
    }

    // epilogue
    #pragma unroll
    for (int r = 0; r < 8; ++r) {
        int row = ty * 8 + r;          // local j index
        int j = j0 + row;
        const float* hd = Hd + (((size_t)b * 256 + j) << 8);
        float* outr = e_new + ((size_t)m0 + row) * 256;
        float pb[8] = {};
        #pragma unroll
        for (int c = 0; c < 8; ++c) {
            int col = c * 32 + tx;
            float v = acc[r][c] + sHs[col] + hd[col];
            v = fmaxf(v, 0.0f);
            outr[col] = v;             // 128B coalesced per (r,c)
            #pragma unroll
            for (int hh = 0; hh < 8; ++hh)
                pb[hh] += v * sWbT[hh][col];
        }
        #pragma unroll
        for (int hh = 0; hh < 8; ++hh) {
            float s = pb[hh];
            #pragma unroll
            for (int off = 16; off; off >>= 1)
                s += __shfl_xor_sync(0xffffffffu, s, off);
            if (tx == 0) sbias[row][hh] = s;
        }
    }
    __syncthreads();
    for (int t = tid; t < 512; t += 256) {
        int hh = t >> 6, row = t & 63;
        bias[((((size_t)b * 8 + hh) * 256 + i) << 8) + j0 + row] =
            sbias[row][hh] + bb[hh];
    }
}

// ---------------- attention kernel ----------------------------------------
// grid: (b*H + h)*8 + tile  (tile of 32 query rows), 256 threads.
// thread: r = tid>>3 (query row in tile), s = tid&7 (handles j = jj*8+s).
__global__ __launch_bounds__(256) void attn_kernel(
    const float* __restrict__ qkv, const float* __restrict__ bias,
    float* __restrict__ o)
{
    extern __shared__ float sm[];
    float (*ks)[33] = (float(*)[33])sm;
    float (*vs)[33] = (float(*)[33])(sm + 256 * 33);
    float (*qs)[33] = (float(*)[33])(sm + 2 * 256 * 33);

    const int tid = threadIdx.x;
    const int tile = blockIdx.x & 7;
    const int bh = blockIdx.x >> 3;
    const int b = bh >> 3, hh = bh & 7;
    const int i0 = tile * 32;

    for (int idx = tid; idx < 2048; idx += 256) {
        int j = idx >> 3, q4 = idx & 7;
        const float* base = qkv + (size_t)(b * 256 + j) * 768 + hh * 32 + q4 * 4;
        float4 kk = *(const float4*)(base + 256);
        float4 vv = *(const float4*)(base + 512);
        ks[j][q4 * 4 + 0] = kk.x; ks[j][q4 * 4 + 1] = kk.y;
        ks[j][q4 * 4 + 2] = kk.z; ks[j][q4 * 4 + 3] = kk.w;
        vs[j][q4 * 4 + 0] = vv.x; vs[j][q4 * 4 + 1] = vv.y;
        vs[j][q4 * 4 + 2] = vv.z; vs[j][q4 * 4 + 3] = vv.w;
    }
    for (int idx = tid; idx < 1024; idx += 256) {
        int r = idx >> 5, d = idx & 31;
        qs[r][d] = qkv[(size_t)(b * 256 + i0 + r) * 768 + hh * 32 + d];
    }
    __syncthreads();

    const int r = tid >> 3, s = tid & 7;
    const int i = i0 + r;
    const float* brow = bias + ((((size_t)b * 8 + hh) * 256 + i) << 8);

    float sc[32];
    float mx = -1e30f;
    #pragma unroll
    for (int jj = 0; jj < 32; ++jj) {
        int j = jj * 8 + s;
        float a = 0.0f;
        #pragma unroll
        for (int d = 0; d < 32; ++d) a += qs[r][d] * ks[j][d];
        a = a * 0.17677669529663687f + brow[j];
        sc[jj] = a;
        mx = fmaxf(mx, a);
    }
    #pragma unroll
    for (int off = 4; off; off >>= 1)
        mx = fmaxf(mx, __shfl_xor_sync(0xffffffffu, mx, off));

    float sum = 0.0f;
    #pragma unroll
    for (int jj = 0; jj < 32; ++jj) { sc[jj] = expf(sc[jj] - mx); sum += sc[jj]; }
    #pragma unroll
    for (int off = 4; off; off >>= 1)
        sum += __shfl_xor_sync(0xffffffffu, sum, off);
    float inv = 1.0f / sum;

    float oacc[32] = {};
    #pragma unroll
    for (int jj = 0; jj < 32; ++jj) {
        int j = jj * 8 + s;
        float w = sc[jj];
        #pragma unroll
        for (int d = 0; d < 32; ++d) oacc[d] += w * vs[j][d];
    }

    float w4[4];
    #pragma unroll
    for (int d = 0; d < 32; ++d) {
        float t = oacc[d];
        t += __shfl_xor_sync(0xffffffffu, t, 1);
        t += __shfl_xor_sync(0xffffffffu, t, 2);
        t += __shfl_xor_sync(0xffffffffu, t, 4);
        if ((d >> 2) == s) w4[d & 3] = t;
    }
    *(float4*)(o + ((size_t)(b * 256 + i)) * 256 + hh * 32 + s * 4) =
        make_float4(w4[0] * inv, w4[1] * inv, w4[2] * inv, w4[3] * inv);
}

// ---------------- launch ---------------------------------------------------
extern "C" void kernel_launch(void* const* d_in, const int* in_sizes, int n_in,
                              void* d_out, int out_size)
{
    (void)in_sizes; (void)n_in; (void)out_size;
    const float* h    = (const float*)d_in[0];
    const float* e    = (const float*)d_in[1];
    const float* We   = (const float*)d_in[2];
    const float* be   = (const float*)d_in[3];
    const float* Ws   = (const float*)d_in[4];
    const float* bs   = (const float*)d_in[5];
    const float* Wd   = (const float*)d_in[6];
    const float* bd   = (const float*)d_in[7];
    const float* Wb   = (const float*)d_in[8];
    const float* bb   = (const float*)d_in[9];
    const float* ln1g = (const float*)d_in[10];
    const float* ln1b = (const float*)d_in[11];
    const float* Wqkv = (const float*)d_in[12];
    const float* bqkv = (const float*)d_in[13];
    const float* Wo   = (const float*)d_in[14];
    const float* bo   = (const float*)d_in[15];
    const float* ln2g = (const float*)d_in[16];
    const float* ln2b = (const float*)d_in[17];
    const float* W1   = (const float*)d_in[18];
    const float* b1   = (const float*)d_in[19];
    const float* W2   = (const float*)d_in[20];
    const float* b2   = (const float*)d_in[21];

    float* out_h2 = (float*)d_out;
    float* out_e  = out_h2 + (size_t)BN * DD;

    float *pHs, *pHd, *px1, *pqkv, *pbias, *po, *ph1, *py, *pf;
    cudaGetSymbolAddress((void**)&pHs,   g_Hs);
    cudaGetSymbolAddress((void**)&pHd,   g_Hd);
    cudaGetSymbolAddress((void**)&px1,   g_x1);
    cudaGetSymbolAddress((void**)&pqkv,  g_qkv);
    cudaGetSymbolAddress((void**)&pbias, g_bias);
    cudaGetSymbolAddress((void**)&po,    g_o);
    cudaGetSymbolAddress((void**)&ph1,   g_h1);
    cudaGetSymbolAddress((void**)&py,    g_y);
    cudaGetSymbolAddress((void**)&pf,    g_ffn);

    // node-side prep
    ln_kernel<<<BN, 256>>>(h, ln1g, ln1b, px1);
    gemm64<0><<<dim3(4, 16), 256>>>(h,   Ws,   bs,   nullptr, pHs,  256, 256);
    gemm64<0><<<dim3(4, 16), 256>>>(h,   Wd,   bd,   nullptr, pHd,  256, 256);
    gemm64<0><<<dim3(12, 16), 256>>>(px1, Wqkv, bqkv, nullptr, pqkv, 256, 768);

    // edge update + attention bias (writes e_new directly to output)
    edge_kernel<<<4096, 256>>>(e, We, be, pHs, pHd, Wb, bb, out_e, pbias);

    // attention
    cudaFuncSetAttribute(attn_kernel,
                         cudaFuncAttributeMaxDynamicSharedMemorySize, 73728);
    attn_kernel<<<256, 256, 71808>>>(pqkv, pbias, po);

    // output proj + residual
    gemm64<0><<<dim3(4, 16), 256>>>(po, Wo, bo, h, ph1, 256, 256);

    // FFN
    ln_kernel<<<BN, 256>>>(ph1, ln2g, ln2b, py);
    gemm64<1><<<dim3(16, 16), 256>>>(py, W1, b1, nullptr, pf, 256, 1024);
    gemm64<0><<<dim3(4, 16), 256>>>(pf, W2, b2, ph1, out_h2, 1024, 256);
}

// round 3
// speedup vs baseline: 2.0208x; 2.0208x over previous
#include <cuda_runtime.h>
#include <math.h>
#include <stdint.h>

// Shapes (fixed): B=4, N=256, D=256, H=8, HD=32, DFF=1024
#define BN 1024
#define DD 256

// ---------------- scratch ----------------
__device__ __align__(16) float g_Hs[BN * DD];
__device__ __align__(16) float g_Hd[BN * DD];
__device__ __align__(16) float g_x1[BN * DD];
__device__ __align__(16) float g_qkv[BN * 768];
__device__ __align__(16) float g_bias[4 * 8 * 256 * 256];
__device__ __align__(16) float g_o[BN * DD];
__device__ __align__(16) float g_h1[BN * DD];
__device__ __align__(16) float g_y[BN * DD];
__device__ __align__(16) float g_ffn[BN * 1024];
__device__ __align__(16) float g_WeT[DD * DD];   // We^T, tf32-rounded

// ---------------- helpers ----------------
__device__ __forceinline__ float tf32_rna(float x) {
    uint32_t r;
    asm("cvt.rna.tf32.f32 %0, %1;" : "=r"(r) : "f"(x));
    return __uint_as_float(r);
}
__device__ __forceinline__ void mma_tf32(float* c, const uint32_t* a,
                                         uint32_t b0, uint32_t b1) {
    asm volatile(
        "mma.sync.aligned.m16n8k8.row.col.f32.tf32.tf32.f32 "
        "{%0,%1,%2,%3}, {%4,%5,%6,%7}, {%8,%9}, {%0,%1,%2,%3};"
        : "+f"(c[0]), "+f"(c[1]), "+f"(c[2]), "+f"(c[3])
        : "r"(a[0]), "r"(a[1]), "r"(a[2]), "r"(a[3]), "r"(b0), "r"(b1));
}

// ---------------- WeT prep: transpose + tf32 round ----------------
__global__ __launch_bounds__(256) void prep_wet(const float* __restrict__ We,
                                                float* __restrict__ WeT) {
    int n = blockIdx.x, k = threadIdx.x;
    WeT[n * 256 + k] = tf32_rna(We[k * 256 + n]);
}

// ---------------- zero bias ----------------
__global__ __launch_bounds__(256) void zero_bias(float4* __restrict__ p) {
    p[blockIdx.x * 256 + threadIdx.x] = make_float4(0.f, 0.f, 0.f, 0.f);
}

// ---------------- edge kernel: mma.sync tf32 ----------------
// CTA: 128 edge-rows (same b,i; 128 consecutive j) x 128 d-cols.
// 8 warps: 4 row-groups x 2 col-groups; warp tile 32x64.
#define ESTRIDE 36
__global__ __launch_bounds__(256, 2) void edge_mma_kernel(
    const float* __restrict__ e, const float* __restrict__ WeT,
    const float* __restrict__ be, const float* __restrict__ Hs,
    const float* __restrict__ Hd, const float* __restrict__ Wb,
    float* __restrict__ e_new, float* __restrict__ bias)
{
    extern __shared__ float sm[];
    float* sA    = sm;                          // 2 * 128*36
    float* sB    = sm + 2 * 128 * ESTRIDE;      // 2 * 128*36
    float* sHs   = sm + 4 * 128 * ESTRIDE;      // 128
    float* sWb   = sHs + 128;                   // 128*8
    float* sbias = sWb + 1024;                  // 128*8

    const int tid = threadIdx.x;
    const int w = tid >> 5, lane = tid & 31;
    const int g = lane >> 2, tig = lane & 3;
    const int wr = w >> 1, wc = w & 1;

    const int m0 = (blockIdx.x >> 1) * 128;
    const int c0 = (blockIdx.x & 1) * 128;
    const int b = m0 >> 16, i = (m0 >> 8) & 255, j0 = m0 & 255;

    if (tid < 128)
        sHs[tid] = Hs[(((size_t)(b << 8) + i) << 8) + c0 + tid] + be[c0 + tid];
    #pragma unroll
    for (int q = 0; q < 4; ++q) {
        int t = tid + q * 256;
        sWb[t] = Wb[(c0 + (t >> 3)) * 8 + (t & 7)];
        sbias[t] = 0.0f;
    }

    const float* Ab = e + (size_t)m0 * 256;
    const float* Bb = WeT + (size_t)c0 * 256;

    const int lrow = tid >> 3;          // 0..127 (for global<->smem staging)
    const int lf   = (tid & 7) * 4;     // 0..28

    float4 pre[8];
    // prefetch chunk 0
    #pragma unroll
    for (int q = 0; q < 4; ++q) {
        int row = lrow + q * 32;
        pre[q]     = *(const float4*)(Ab + (size_t)row * 256 + lf);
        pre[q + 4] = *(const float4*)(Bb + (size_t)row * 256 + lf);
    }
    #pragma unroll
    for (int q = 0; q < 4; ++q) {
        int row = lrow + q * 32;
        float4 v = pre[q];
        v.x = tf32_rna(v.x); v.y = tf32_rna(v.y);
        v.z = tf32_rna(v.z); v.w = tf32_rna(v.w);
        *(float4*)(sA + row * ESTRIDE + lf) = v;
        *(float4*)(sB + row * ESTRIDE + lf) = pre[q + 4];
    }
    __syncthreads();

    float acc[2][8][4] = {};

    for (int c = 0; c < 8; ++c) {
        const float* cA = sA + (c & 1) * 128 * ESTRIDE;
        const float* cB = sB + (c & 1) * 128 * ESTRIDE;
        if (c < 7) {
            int k0 = (c + 1) * 32;
            #pragma unroll
            for (int q = 0; q < 4; ++q) {
                int row = lrow + q * 32;
                pre[q]     = *(const float4*)(Ab + (size_t)row * 256 + k0 + lf);
                pre[q + 4] = *(const float4*)(Bb + (size_t)row * 256 + k0 + lf);
            }
        }
        #pragma unroll
        for (int kk = 0; kk < 32; kk += 8) {
            uint32_t a[2][4];
            #pragma unroll
            for (int mt = 0; mt < 2; ++mt) {
                int r = wr * 32 + mt * 16 + g;
                a[mt][0] = __float_as_uint(cA[r * ESTRIDE + kk + tig]);
                a[mt][1] = __float_as_uint(cA[(r + 8) * ESTRIDE + kk + tig]);
                a[mt][2] = __float_as_uint(cA[r * ESTRIDE + kk + tig + 4]);
                a[mt][3] = __float_as_uint(cA[(r + 8) * ESTRIDE + kk + tig + 4]);
            }
            #pragma unroll
            for (int nt = 0; nt < 8; ++nt) {
                int n = wc * 64 + nt * 8 + g;
                uint32_t b0 = __float_as_uint(cB[n * ESTRIDE + kk + tig]);
                uint32_t b1 = __float_as_uint(cB[n * ESTRIDE + kk + tig + 4]);
                mma_tf32(acc[0][nt], a[0], b0, b1);
                mma_tf32(acc[1][nt], a[1], b0, b1);
            }
        }
        __syncthreads();
        if (c < 7) {
            float* nA = sA + ((c + 1) & 1) * 128 * ESTRIDE;
            float* nB = sB + ((c + 1) & 1) * 128 * ESTRIDE;
            #pragma unroll
            for (int q = 0; q < 4; ++q) {
                int row = lrow + q * 32;
                float4 v = pre[q];
                v.x = tf32_rna(v.x); v.y = tf32_rna(v.y);
                v.z = tf32_rna(v.z); v.w = tf32_rna(v.w);
                *(float4*)(nA + row * ESTRIDE + lf) = v;
                *(float4*)(nB + row * ESTRIDE + lf) = pre[q + 4];
            }
            __syncthreads();
        }
    }

    // ---- epilogue: +Hs +Hd, ReLU, store e_new, bias head-reduce ----
    float pb[4][8] = {};
    #pragma unroll
    for (int mt = 0; mt < 2; ++mt) {
        #pragma unroll
        for (int rh = 0; rh < 2; ++rh) {
            const int rl = wr * 32 + mt * 16 + rh * 8 + g;   // local row
            const float* hdrow =
                Hd + ((((size_t)b << 8) + j0 + rl) << 8) + c0;
            float* erow = e_new + ((size_t)(m0 + rl)) * 256 + c0;
            const int p = mt * 2 + rh;
            #pragma unroll
            for (int nt = 0; nt < 8; ++nt) {
                const int cl = wc * 64 + nt * 8 + 2 * tig;
                float x0 = acc[mt][nt][rh * 2 + 0] + sHs[cl] + hdrow[cl];
                float x1 = acc[mt][nt][rh * 2 + 1] + sHs[cl + 1] + hdrow[cl + 1];
                x0 = fmaxf(x0, 0.0f);
                x1 = fmaxf(x1, 0.0f);
                *(float2*)(erow + cl) = make_float2(x0, x1);
                const float* w0 = sWb + cl * 8;
                #pragma unroll
                for (int hh = 0; hh < 8; ++hh)
                    pb[p][hh] += x0 * w0[hh] + x1 * w0[8 + hh];
            }
        }
    }
    // reduce over the 4 lanes of each quad (same g, tig 0..3)
    #pragma unroll
    for (int p = 0; p < 4; ++p)
        #pragma unroll
        for (int hh = 0; hh < 8; ++hh) {
            float s = pb[p][hh];
            s += __shfl_xor_sync(0xffffffffu, s, 1);
            s += __shfl_xor_sync(0xffffffffu, s, 2);
            pb[p][hh] = s;
        }
    if (tig == 0) {
        #pragma unroll
        for (int p = 0; p < 4; ++p) {
            int rl = wr * 32 + (p >> 1) * 16 + (p & 1) * 8 + g;
            #pragma unroll
            for (int hh = 0; hh < 8; ++hh)
                atomicAdd(&sbias[rl * 8 + hh], pb[p][hh]);
        }
    }
    __syncthreads();
    #pragma unroll
    for (int q = 0; q < 4; ++q) {
        int t = tid + q * 256;
        int r = t & 127, hh = t >> 7;
        atomicAdd(&bias[((((size_t)b * 8 + hh) * 256 + i) << 8) + j0 + r],
                  sbias[r * 8 + hh]);
    }
}

// ---------------- LayerNorm ----------------
__global__ __launch_bounds__(256) void ln_kernel(
    const float* __restrict__ in, const float* __restrict__ g,
    const float* __restrict__ b, float* __restrict__ out)
{
    int row = blockIdx.x;
    int t = threadIdx.x;
    float v = in[(size_t)row * 256 + t];
    __shared__ float red[8];

    float s = v;
    #pragma unroll
    for (int o = 16; o; o >>= 1) s += __shfl_xor_sync(0xffffffffu, s, o);
    if ((t & 31) == 0) red[t >> 5] = s;
    __syncthreads();
    float mean = (red[0] + red[1] + red[2] + red[3] +
                  red[4] + red[5] + red[6] + red[7]) * (1.0f / 256.0f);
    float d = v - mean;
    __syncthreads();
    s = d * d;
    #pragma unroll
    for (int o = 16; o; o >>= 1) s += __shfl_xor_sync(0xffffffffu, s, o);
    if ((t & 31) == 0) red[t >> 5] = s;
    __syncthreads();
    float var = (red[0] + red[1] + red[2] + red[3] +
                 red[4] + red[5] + red[6] + red[7]) * (1.0f / 256.0f);
    out[(size_t)row * 256 + t] = d * rsqrtf(var + 1e-5f) * g[t] + b[t];
}

// ---------------- generic fp32 GEMM ----------------
__device__ __forceinline__ float gelu_exact(float x) {
    return 0.5f * x * (1.0f + erff(x * 0.70710678118654752f));
}

template <int OP>
__global__ __launch_bounds__(256) void gemm64(
    const float* __restrict__ A, const float* __restrict__ W,
    const float* __restrict__ bias, const float* __restrict__ res,
    float* __restrict__ out, int K, int Ncols)
{
    __shared__ float As[64][16];
    __shared__ float Bs[16][64];
    const int tid = threadIdx.x;
    const int m0 = blockIdx.y * 64;
    const int c0 = blockIdx.x * 64;
    const int ty = tid >> 4;
    const int tx = tid & 15;

    float acc[4][4] = {};

    for (int k0 = 0; k0 < K; k0 += 16) {
        {
            int r = tid >> 2, q = tid & 3;
            *(float4*)&As[r][q * 4] =
                *(const float4*)(A + (size_t)(m0 + r) * K + k0 + q * 4);
        }
        {
            int kk = tid >> 4, q = tid & 15;
            *(float4*)&Bs[kk][q * 4] =
                *(const float4*)(W + (size_t)(k0 + kk) * Ncols + c0 + q * 4);
        }
        __syncthreads();
        #pragma unroll
        for (int k = 0; k < 16; ++k) {
            float a[4];
            #pragma unroll
            for (int r = 0; r < 4; ++r) a[r] = As[ty * 4 + r][k];
            float4 bv = *(float4*)&Bs[k][tx * 4];
            #pragma unroll
            for (int r = 0; r < 4; ++r) {
                acc[r][0] += a[r] * bv.x;
                acc[r][1] += a[r] * bv.y;
                acc[r][2] += a[r] * bv.z;
                acc[r][3] += a[r] * bv.w;
            }
        }
        __syncthreads();
    }

    float4 bs4 = *(const float4*)(bias + c0 + tx * 4);
    #pragma unroll
    for (int r = 0; r < 4; ++r) {
        int m = m0 + ty * 4 + r;
        float v0 = acc[r][0] + bs4.x;
        float v1 = acc[r][1] + bs4.y;
        float v2 = acc[r][2] + bs4.z;
        float v3 = acc[r][3] + bs4.w;
        if (OP == 1) {
            v0 = gelu_exact(v0); v1 = gelu_exact(v1);
            v2 = gelu_exact(v2); v3 = gelu_exact(v3);
        }
        if (res) {
            float4 rr = *(const float4*)(res + (size_t)m * Ncols + c0 + tx * 4);
            v0 += rr.x; v1 += rr.y; v2 += rr.z; v3 += rr.w;
        }
        *(float4*)(out + (size_t)m * Ncols + c0 + tx * 4) =
            make_float4(v0, v1, v2, v3);
    }
}

// ---------------- attention kernel ----------------
__global__ __launch_bounds__(256) void attn_kernel(
    const float* __restrict__ qkv, const float* __restrict__ bias,
    const float* __restrict__ bb, float* __restrict__ o)
{
    extern __shared__ float sm[];
    float (*ks)[33] = (float(*)[33])sm;
    float (*vs)[33] = (float(*)[33])(sm + 256 * 33);
    float (*qs)[33] = (float(*)[33])(sm + 2 * 256 * 33);

    const int tid = threadIdx.x;
    const int tile = blockIdx.x & 7;
    const int bh = blockIdx.x >> 3;
    const int b = bh >> 3, hh = bh & 7;
    const int i0 = tile * 32;
    const float bbv = bb[hh];

    for (int idx = tid; idx < 2048; idx += 256) {
        int j = idx >> 3, q4 = idx & 7;
        const float* base = qkv + (size_t)(b * 256 + j) * 768 + hh * 32 + q4 * 4;
        float4 kk = *(const float4*)(base + 256);
        float4 vv = *(const float4*)(base + 512);
        ks[j][q4 * 4 + 0] = kk.x; ks[j][q4 * 4 + 1] = kk.y;
        ks[j][q4 * 4 + 2] = kk.z; ks[j][q4 * 4 + 3] = kk.w;
        vs[j][q4 * 4 + 0] = vv.x; vs[j][q4 * 4 + 1] = vv.y;
        vs[j][q4 * 4 + 2] = vv.z; vs[j][q4 * 4 + 3] = vv.w;
    }
    for (int idx = tid; idx < 1024; idx += 256) {
        int r = idx >> 5, d = idx & 31;
        qs[r][d] = qkv[(size_t)(b * 256 + i0 + r) * 768 + hh * 32 + d];
    }
    __syncthreads();

    const int r = tid >> 3, s = tid & 7;
    const int i = i0 + r;
    const float* brow = bias + ((((size_t)b * 8 + hh) * 256 + i) << 8);

    float sc[32];
    float mx = -1e30f;
    #pragma unroll
    for (int jj = 0; jj < 32; ++jj) {
        int j = jj * 8 + s;
        float a = 0.0f;
        #pragma unroll
        for (int d = 0; d < 32; ++d) a += qs[r][d] * ks[j][d];
        a = a * 0.17677669529663687f + brow[j] + bbv;
        sc[jj] = a;
        mx = fmaxf(mx, a);
    }
    #pragma unroll
    for (int off = 4; off; off >>= 1)
        mx = fmaxf(mx, __shfl_xor_sync(0xffffffffu, mx, off));

    float sum = 0.0f;
    #pragma unroll
    for (int jj = 0; jj < 32; ++jj) { sc[jj] = expf(sc[jj] - mx); sum += sc[jj]; }
    #pragma unroll
    for (int off = 4; off; off >>= 1)
        sum += __shfl_xor_sync(0xffffffffu, sum, off);
    float inv = 1.0f / sum;

    float oacc[32] = {};
    #pragma unroll
    for (int jj = 0; jj < 32; ++jj) {
        int j = jj * 8 + s;
        float w = sc[jj];
        #pragma unroll
        for (int d = 0; d < 32; ++d) oacc[d] += w * vs[j][d];
    }

    float w4[4];
    #pragma unroll
    for (int d = 0; d < 32; ++d) {
        float t = oacc[d];
        t += __shfl_xor_sync(0xffffffffu, t, 1);
        t += __shfl_xor_sync(0xffffffffu, t, 2);
        t += __shfl_xor_sync(0xffffffffu, t, 4);
        if ((d >> 2) == s) w4[d & 3] = t;
    }
    *(float4*)(o + ((size_t)(b * 256 + i)) * 256 + hh * 32 + s * 4) =
        make_float4(w4[0] * inv, w4[1] * inv, w4[2] * inv, w4[3] * inv);
}

// ---------------- launch ----------------
extern "C" void kernel_launch(void* const* d_in, const int* in_sizes, int n_in,
                              void* d_out, int out_size)
{
    (void)in_sizes; (void)n_in; (void)out_size;
    const float* h    = (const float*)d_in[0];
    const float* e    = (const float*)d_in[1];
    const float* We   = (const float*)d_in[2];
    const float* be   = (const float*)d_in[3];
    const float* Ws   = (const float*)d_in[4];
    const float* bs   = (const float*)d_in[5];
    const float* Wd   = (const float*)d_in[6];
    const float* bd   = (const float*)d_in[7];
    const float* Wb   = (const float*)d_in[8];
    const float* bb   = (const float*)d_in[9];
    const float* ln1g = (const float*)d_in[10];
    const float* ln1b = (const float*)d_in[11];
    const float* Wqkv = (const float*)d_in[12];
    const float* bqkv = (const float*)d_in[13];
    const float* Wo   = (const float*)d_in[14];
    const float* bo   = (const float*)d_in[15];
    const float* ln2g = (const float*)d_in[16];
    const float* ln2b = (const float*)d_in[17];
    const float* W1   = (const float*)d_in[18];
    const float* b1   = (const float*)d_in[19];
    const float* W2   = (const float*)d_in[20];
    const float* b2   = (const float*)d_in[21];

    float* out_h2 = (float*)d_out;
    float* out_e  = out_h2 + (size_t)BN * DD;

    float *pHs, *pHd, *px1, *pqkv, *pbias, *po, *ph1, *py, *pf, *pWeT;
    cudaGetSymbolAddress((void**)&pHs,   g_Hs);
    cudaGetSymbolAddress((void**)&pHd,   g_Hd);
    cudaGetSymbolAddress((void**)&px1,   g_x1);
    cudaGetSymbolAddress((void**)&pqkv,  g_qkv);
    cudaGetSymbolAddress((void**)&pbias, g_bias);
    cudaGetSymbolAddress((void**)&po,    g_o);
    cudaGetSymbolAddress((void**)&ph1,   g_h1);
    cudaGetSymbolAddress((void**)&py,    g_y);
    cudaGetSymbolAddress((void**)&pf,    g_ffn);
    cudaGetSymbolAddress((void**)&pWeT,  g_WeT);

    // node-side prep
    ln_kernel<<<BN, 256>>>(h, ln1g, ln1b, px1);
    gemm64<0><<<dim3(4, 16), 256>>>(h,   Ws,   bs,   nullptr, pHs,  256, 256);
    gemm64<0><<<dim3(4, 16), 256>>>(h,   Wd,   bd,   nullptr, pHd,  256, 256);
    gemm64<0><<<dim3(12, 16), 256>>>(px1, Wqkv, bqkv, nullptr, pqkv, 256, 768);
    prep_wet<<<256, 256>>>(We, pWeT);
    zero_bias<<<2048, 256>>>((float4*)pbias);

    // edge update + attention bias via mma.sync tf32
    const int edge_smem = (4 * 128 * ESTRIDE + 128 + 1024 + 1024) * 4;
    cudaFuncSetAttribute(edge_mma_kernel,
                         cudaFuncAttributeMaxDynamicSharedMemorySize, edge_smem);
    edge_mma_kernel<<<4096, 256, edge_smem>>>(
        e, pWeT, be, pHs, pHd, Wb, out_e, pbias);

    // attention
    cudaFuncSetAttribute(attn_kernel,
                         cudaFuncAttributeMaxDynamicSharedMemorySize, 73728);
    attn_kernel<<<256, 256, 71808>>>(pqkv, pbias, bb, po);

    // output proj + residual
    gemm64<0><<<dim3(4, 16), 256>>>(po, Wo, bo, h, ph1, 256, 256);

    // FFN
    ln_kernel<<<BN, 256>>>(ph1, ln2g, ln2b, py);
    gemm64<1><<<dim3(16, 16), 256>>>(py, W1, b1, nullptr, pf, 256, 1024);
    gemm64<0><<<dim3(4, 16), 256>>>(pf, W2, b2, ph1, out_h2, 1024, 256);
}

// round 4
// speedup vs baseline: 2.1908x; 1.0841x over previous
#include <cuda_runtime.h>
#include <cuda_fp16.h>
#include <math.h>
#include <stdint.h>

// Shapes (fixed): B=4, N=256, D=256, H=8, HD=32, DFF=1024
#define BN 1024
#define DD 256

// ---------------- scratch ----------------
__device__ __align__(16) float g_Hs[BN * DD];
__device__ __align__(16) float g_Hd[BN * DD];
__device__ __align__(16) float g_x1[BN * DD];
__device__ __align__(16) float g_qkv[BN * 768];
__device__ __align__(16) float g_bias[4 * 8 * 256 * 256];
__device__ __align__(16) float g_o[BN * DD];
__device__ __align__(16) float g_h1[BN * DD];
__device__ __align__(16) float g_y[BN * DD];
__device__ __align__(16) float g_ffn[BN * 1024];
__device__ __align__(16) __half g_WeTh[DD * DD];   // We^T in fp16

// ---------------- helpers ----------------
__device__ __forceinline__ uint32_t smem_u32(const void* p) {
    uint32_t a;
    asm("{ .reg .u64 t; cvta.to.shared.u64 t, %1; cvt.u32.u64 %0, t; }"
        : "=r"(a) : "l"(p));
    return a;
}
__device__ __forceinline__ void ldmx4(uint32_t* r, uint32_t addr) {
    asm volatile(
        "ldmatrix.sync.aligned.m8n8.x4.shared.b16 {%0,%1,%2,%3}, [%4];"
        : "=r"(r[0]), "=r"(r[1]), "=r"(r[2]), "=r"(r[3]) : "r"(addr));
}
__device__ __forceinline__ void mma_f16(float* c, const uint32_t* a,
                                        uint32_t b0, uint32_t b1) {
    asm volatile(
        "mma.sync.aligned.m16n8k16.row.col.f32.f16.f16.f32 "
        "{%0,%1,%2,%3}, {%4,%5,%6,%7}, {%8,%9}, {%0,%1,%2,%3};"
        : "+f"(c[0]), "+f"(c[1]), "+f"(c[2]), "+f"(c[3])
        : "r"(a[0]), "r"(a[1]), "r"(a[2]), "r"(a[3]), "r"(b0), "r"(b1));
}
__device__ __forceinline__ uint32_t pack_h2(float x, float y) {
    __half2 h = __float22half2_rn(make_float2(x, y));
    return *reinterpret_cast<uint32_t*>(&h);
}

// ---------------- WeT prep: transpose + fp16 ----------------
__global__ __launch_bounds__(256) void prep_wet(const float* __restrict__ We,
                                                __half* __restrict__ WeTh) {
    int n = blockIdx.x, k = threadIdx.x;
    WeTh[n * 256 + k] = __float2half_rn(We[k * 256 + n]);
}

// ---------------- zero bias ----------------
__global__ __launch_bounds__(256) void zero_bias(float4* __restrict__ p) {
    p[blockIdx.x * 256 + threadIdx.x] = make_float4(0.f, 0.f, 0.f, 0.f);
}

// ---------------- edge kernel: fp16 mma.m16n8k16 + ldmatrix ----------------
// CTA: 128 edge-rows (same b,i; 128 consecutive j) x 128 d-cols.
// 8 warps 4x2; warp tile 32x64. B (128n x 256k halves) resident in smem;
// A double-buffered, 64-k chunks. 16B-chunk XOR swizzle for ldmatrix.
#define SB_B     0          // 128 * 512B = 64KB
#define SB_A     65536      // 2 * 16KB
#define SM_SHS   98304      // 128 floats
#define SM_SWB   98816      // 1024 floats
#define SM_SBIAS 102912     // 1024 floats
#define SM_EDGE_TOTAL 107008

__global__ __launch_bounds__(256, 2) void edge_mma_kernel(
    const float* __restrict__ e, const __half* __restrict__ WeTh,
    const float* __restrict__ be, const float* __restrict__ Hs,
    const float* __restrict__ Hd, const float* __restrict__ Wb,
    float* __restrict__ e_new, float* __restrict__ bias)
{
    extern __shared__ char smem[];
    const uint32_t sb = smem_u32(smem);
    float* sHs   = (float*)(smem + SM_SHS);
    float* sWb   = (float*)(smem + SM_SWB);
    float* sbias = (float*)(smem + SM_SBIAS);

    const int tid = threadIdx.x;
    const int w = tid >> 5, lane = tid & 31;
    const int g = lane >> 2, tig = lane & 3;
    const int wr = w >> 1, wc = w & 1;
    const int x7 = lane & 7;

    const int m0 = (blockIdx.x >> 1) * 128;
    const int c0 = (blockIdx.x & 1) * 128;
    const int b = m0 >> 16, i = (m0 >> 8) & 255, j0 = m0 & 255;

    // small tables
    if (tid < 128)
        sHs[tid] = Hs[(((size_t)(b << 8) + i) << 8) + c0 + tid] + be[c0 + tid];
    #pragma unroll
    for (int q = 0; q < 4; ++q) {
        int t = tid + q * 256;
        sWb[t] = Wb[(c0 + (t >> 3)) * 8 + (t & 7)];
        sbias[t] = 0.0f;
    }

    // ---- stage B once: 128 n-rows x 256 k halves, swizzled 16B chunks ----
    {
        const int ch = tid & 31;
        #pragma unroll
        for (int it = 0; it < 16; ++it) {
            int row = (tid >> 5) + it * 8;
            uint4 val = ((const uint4*)(WeTh + (size_t)(c0 + row) * 256))[ch];
            *(uint4*)(smem + SB_B + row * 512 + ((ch ^ (row & 7)) << 4)) = val;
        }
    }

    const float* Ab = e + (size_t)m0 * 256;
    const int arow = tid >> 3;        // staging row base (0..31)
    const int aseg = tid & 7;         // 16B seg within 64-half row

    // ---- stage A chunk 0 ----
    #pragma unroll
    for (int it = 0; it < 4; ++it) {
        int row = arow + it * 32;
        const float4* p = (const float4*)(Ab + (size_t)row * 256 + aseg * 8);
        float4 v0 = p[0], v1 = p[1];
        uint4 u = make_uint4(pack_h2(v0.x, v0.y), pack_h2(v0.z, v0.w),
                             pack_h2(v1.x, v1.y), pack_h2(v1.z, v1.w));
        *(uint4*)(smem + SB_A + row * 128 + ((aseg ^ (row & 7)) << 4)) = u;
    }
    __syncthreads();

    // ldmatrix lane->row/sel mapping
    const int rowoffA = x7 + (((lane >> 3) & 1) << 3);
    const int selA = lane >> 4;
    const int rowoffB = x7 + ((lane >> 4) << 3);
    const int selB = (lane >> 3) & 1;

    float acc[2][8][4] = {};
    float4 pre[2][2];

    for (int c = 0; c < 4; ++c) {
        // prefetch first half of next A chunk
        if (c < 3) {
            #pragma unroll
            for (int it = 0; it < 2; ++it) {
                int row = arow + it * 32;
                const float4* p =
                    (const float4*)(Ab + (size_t)row * 256 + (c + 1) * 64 + aseg * 8);
                pre[it][0] = p[0];
                pre[it][1] = p[1];
            }
        }
        const uint32_t sAc = sb + SB_A + (c & 1) * 16384;
        #pragma unroll
        for (int kk = 0; kk < 4; ++kk) {
            uint32_t a0[4], a1[4];
            {
                int rowA = wr * 32 + rowoffA;
                ldmx4(a0, sAc + rowA * 128 + ((((kk << 1) + selA) ^ x7) << 4));
                rowA += 16;
                ldmx4(a1, sAc + rowA * 128 + ((((kk << 1) + selA) ^ x7) << 4));
            }
            uint32_t bf[4][4];
            #pragma unroll
            for (int nt2 = 0; nt2 < 4; ++nt2) {
                int rowB = wc * 64 + nt2 * 16 + rowoffB;
                ldmx4(bf[nt2], sb + SB_B + rowB * 512 +
                               (((c * 8 + (kk << 1) + selB) ^ x7) << 4));
            }
            #pragma unroll
            for (int nt2 = 0; nt2 < 4; ++nt2) {
                mma_f16(acc[0][nt2 * 2],     a0, bf[nt2][0], bf[nt2][1]);
                mma_f16(acc[0][nt2 * 2 + 1], a0, bf[nt2][2], bf[nt2][3]);
                mma_f16(acc[1][nt2 * 2],     a1, bf[nt2][0], bf[nt2][1]);
                mma_f16(acc[1][nt2 * 2 + 1], a1, bf[nt2][2], bf[nt2][3]);
            }
        }
        __syncthreads();
        if (c < 3) {
            char* dst = smem + SB_A + ((c + 1) & 1) * 16384;
            #pragma unroll
            for (int it = 0; it < 2; ++it) {
                int row = arow + it * 32;
                float4 v0 = pre[it][0], v1 = pre[it][1];
                uint4 u = make_uint4(pack_h2(v0.x, v0.y), pack_h2(v0.z, v0.w),
                                     pack_h2(v1.x, v1.y), pack_h2(v1.z, v1.w));
                *(uint4*)(dst + row * 128 + ((aseg ^ (row & 7)) << 4)) = u;
            }
            #pragma unroll
            for (int it = 2; it < 4; ++it) {
                int row = arow + it * 32;
                const float4* p =
                    (const float4*)(Ab + (size_t)row * 256 + (c + 1) * 64 + aseg * 8);
                float4 v0 = p[0], v1 = p[1];
                uint4 u = make_uint4(pack_h2(v0.x, v0.y), pack_h2(v0.z, v0.w),
                                     pack_h2(v1.x, v1.y), pack_h2(v1.z, v1.w));
                *(uint4*)(dst + row * 128 + ((aseg ^ (row & 7)) << 4)) = u;
            }
            __syncthreads();
        }
    }

    // ---- epilogue: +Hs +Hd, ReLU, store e_new, bias head-reduce ----
    float pb[4][8] = {};
    #pragma unroll
    for (int mt = 0; mt < 2; ++mt) {
        #pragma unroll
        for (int rh = 0; rh < 2; ++rh) {
            const int rl = wr * 32 + mt * 16 + rh * 8 + g;
            const float* hdrow = Hd + ((((size_t)b << 8) + j0 + rl) << 8) + c0;
            float* erow = e_new + ((size_t)(m0 + rl)) * 256 + c0;
            const int p = mt * 2 + rh;
            #pragma unroll
            for (int nt = 0; nt < 8; ++nt) {
                const int cl = wc * 64 + nt * 8 + 2 * tig;
                float x0 = acc[mt][nt][rh * 2 + 0] + sHs[cl] + hdrow[cl];
                float x1 = acc[mt][nt][rh * 2 + 1] + sHs[cl + 1] + hdrow[cl + 1];
                x0 = fmaxf(x0, 0.0f);
                x1 = fmaxf(x1, 0.0f);
                *(float2*)(erow + cl) = make_float2(x0, x1);
                const float* w0 = sWb + cl * 8;
                #pragma unroll
                for (int hh = 0; hh < 8; ++hh)
                    pb[p][hh] += x0 * w0[hh] + x1 * w0[8 + hh];
            }
        }
    }
    #pragma unroll
    for (int p = 0; p < 4; ++p)
        #pragma unroll
        for (int hh = 0; hh < 8; ++hh) {
            float s = pb[p][hh];
            s += __shfl_xor_sync(0xffffffffu, s, 1);
            s += __shfl_xor_sync(0xffffffffu, s, 2);
            pb[p][hh] = s;
        }
    if (tig == 0) {
        #pragma unroll
        for (int p = 0; p < 4; ++p) {
            int rl = wr * 32 + (p >> 1) * 16 + (p & 1) * 8 + g;
            #pragma unroll
            for (int hh = 0; hh < 8; ++hh)
                atomicAdd(&sbias[rl * 8 + hh], pb[p][hh]);
        }
    }
    __syncthreads();
    #pragma unroll
    for (int q = 0; q < 4; ++q) {
        int t = tid + q * 256;
        int r = t & 127, hh = t >> 7;
        atomicAdd(&bias[((((size_t)b * 8 + hh) * 256 + i) << 8) + j0 + r],
                  sbias[r * 8 + hh]);
    }
}

// ---------------- LayerNorm ----------------
__global__ __launch_bounds__(256) void ln_kernel(
    const float* __restrict__ in, const float* __restrict__ g,
    const float* __restrict__ b, float* __restrict__ out)
{
    int row = blockIdx.x;
    int t = threadIdx.x;
    float v = in[(size_t)row * 256 + t];
    __shared__ float red[8];

    float s = v;
    #pragma unroll
    for (int o = 16; o; o >>= 1) s += __shfl_xor_sync(0xffffffffu, s, o);
    if ((t & 31) == 0) red[t >> 5] = s;
    __syncthreads();
    float mean = (red[0] + red[1] + red[2] + red[3] +
                  red[4] + red[5] + red[6] + red[7]) * (1.0f / 256.0f);
    float d = v - mean;
    __syncthreads();
    s = d * d;
    #pragma unroll
    for (int o = 16; o; o >>= 1) s += __shfl_xor_sync(0xffffffffu, s, o);
    if ((t & 31) == 0) red[t >> 5] = s;
    __syncthreads();
    float var = (red[0] + red[1] + red[2] + red[3] +
                 red[4] + red[5] + red[6] + red[7]) * (1.0f / 256.0f);
    out[(size_t)row * 256 + t] = d * rsqrtf(var + 1e-5f) * g[t] + b[t];
}

// ---------------- small fp32 GEMM: tile 64x32 ----------------
__device__ __forceinline__ float gelu_exact(float x) {
    return 0.5f * x * (1.0f + erff(x * 0.70710678118654752f));
}

template <int OP>
__global__ __launch_bounds__(256) void gemm_t(
    const float* __restrict__ A, const float* __restrict__ W,
    const float* __restrict__ bias, const float* __restrict__ res,
    float* __restrict__ out, int K, int Ncols)
{
    __shared__ float As[64][16];
    __shared__ float Bs[16][32];
    const int tid = threadIdx.x;
    const int m0 = blockIdx.y * 64;
    const int c0 = blockIdx.x * 32;
    const int ty = tid >> 3;   // 0..31 -> 2 rows
    const int tx = tid & 7;    // 0..7  -> 4 cols

    float acc[2][4] = {};

    for (int k0 = 0; k0 < K; k0 += 16) {
        {
            int r = tid >> 2, q = tid & 3;
            *(float4*)&As[r][q * 4] =
                *(const float4*)(A + (size_t)(m0 + r) * K + k0 + q * 4);
        }
        if (tid < 128) {
            int kk = tid >> 3, q = tid & 7;
            *(float4*)&Bs[kk][q * 4] =
                *(const float4*)(W + (size_t)(k0 + kk) * Ncols + c0 + q * 4);
        }
        __syncthreads();
        #pragma unroll
        for (int k = 0; k < 16; ++k) {
            float a0 = As[ty * 2][k];
            float a1 = As[ty * 2 + 1][k];
            float4 bv = *(float4*)&Bs[k][tx * 4];
            acc[0][0] += a0 * bv.x; acc[0][1] += a0 * bv.y;
            acc[0][2] += a0 * bv.z; acc[0][3] += a0 * bv.w;
            acc[1][0] += a1 * bv.x; acc[1][1] += a1 * bv.y;
            acc[1][2] += a1 * bv.z; acc[1][3] += a1 * bv.w;
        }
        __syncthreads();
    }

    float4 bs4 = *(const float4*)(bias + c0 + tx * 4);
    #pragma unroll
    for (int r = 0; r < 2; ++r) {
        int m = m0 + ty * 2 + r;
        float v0 = acc[r][0] + bs4.x;
        float v1 = acc[r][1] + bs4.y;
        float v2 = acc[r][2] + bs4.z;
        float v3 = acc[r][3] + bs4.w;
        if (OP == 1) {
            v0 = gelu_exact(v0); v1 = gelu_exact(v1);
            v2 = gelu_exact(v2); v3 = gelu_exact(v3);
        }
        if (res) {
            float4 rr = *(const float4*)(res + (size_t)m * Ncols + c0 + tx * 4);
            v0 += rr.x; v1 += rr.y; v2 += rr.z; v3 += rr.w;
        }
        *(float4*)(out + (size_t)m * Ncols + c0 + tx * 4) =
            make_float4(v0, v1, v2, v3);
    }
}

// ---------------- attention kernel ----------------
__global__ __launch_bounds__(256) void attn_kernel(
    const float* __restrict__ qkv, const float* __restrict__ bias,
    const float* __restrict__ bb, float* __restrict__ o)
{
    extern __shared__ float sm[];
    float (*ks)[33] = (float(*)[33])sm;
    float (*vs)[33] = (float(*)[33])(sm + 256 * 33);
    float (*qs)[33] = (float(*)[33])(sm + 2 * 256 * 33);

    const int tid = threadIdx.x;
    const int tile = blockIdx.x & 7;
    const int bh = blockIdx.x >> 3;
    const int b = bh >> 3, hh = bh & 7;
    const int i0 = tile * 32;
    const float bbv = bb[hh];

    for (int idx = tid; idx < 2048; idx += 256) {
        int j = idx >> 3, q4 = idx & 7;
        const float* base = qkv + (size_t)(b * 256 + j) * 768 + hh * 32 + q4 * 4;
        float4 kk = *(const float4*)(base + 256);
        float4 vv = *(const float4*)(base + 512);
        ks[j][q4 * 4 + 0] = kk.x; ks[j][q4 * 4 + 1] = kk.y;
        ks[j][q4 * 4 + 2] = kk.z; ks[j][q4 * 4 + 3] = kk.w;
        vs[j][q4 * 4 + 0] = vv.x; vs[j][q4 * 4 + 1] = vv.y;
        vs[j][q4 * 4 + 2] = vv.z; vs[j][q4 * 4 + 3] = vv.w;
    }
    for (int idx = tid; idx < 1024; idx += 256) {
        int r = idx >> 5, d = idx & 31;
        qs[r][d] = qkv[(size_t)(b * 256 + i0 + r) * 768 + hh * 32 + d];
    }
    __syncthreads();

    const int r = tid >> 3, s = tid & 7;
    const int i = i0 + r;
    const float* brow = bias + ((((size_t)b * 8 + hh) * 256 + i) << 8);

    float sc[32];
    float mx = -1e30f;
    #pragma unroll
    for (int jj = 0; jj < 32; ++jj) {
        int j = jj * 8 + s;
        float a = 0.0f;
        #pragma unroll
        for (int d = 0; d < 32; ++d) a += qs[r][d] * ks[j][d];
        a = a * 0.17677669529663687f + brow[j] + bbv;
        sc[jj] = a;
        mx = fmaxf(mx, a);
    }
    #pragma unroll
    for (int off = 4; off; off >>= 1)
        mx = fmaxf(mx, __shfl_xor_sync(0xffffffffu, mx, off));

    float sum = 0.0f;
    #pragma unroll
    for (int jj = 0; jj < 32; ++jj) { sc[jj] = expf(sc[jj] - mx); sum += sc[jj]; }
    #pragma unroll
    for (int off = 4; off; off >>= 1)
        sum += __shfl_xor_sync(0xffffffffu, sum, off);
    float inv = 1.0f / sum;

    float oacc[32] = {};
    #pragma unroll
    for (int jj = 0; jj < 32; ++jj) {
        int j = jj * 8 + s;
        float w = sc[jj];
        #pragma unroll
        for (int d = 0; d < 32; ++d) oacc[d] += w * vs[j][d];
    }

    float w4[4];
    #pragma unroll
    for (int d = 0; d < 32; ++d) {
        float t = oacc[d];
        t += __shfl_xor_sync(0xffffffffu, t, 1);
        t += __shfl_xor_sync(0xffffffffu, t, 2);
        t += __shfl_xor_sync(0xffffffffu, t, 4);
        if ((d >> 2) == s) w4[d & 3] = t;
    }
    *(float4*)(o + ((size_t)(b * 256 + i)) * 256 + hh * 32 + s * 4) =
        make_float4(w4[0] * inv, w4[1] * inv, w4[2] * inv, w4[3] * inv);
}

// ---------------- launch ----------------
extern "C" void kernel_launch(void* const* d_in, const int* in_sizes, int n_in,
                              void* d_out, int out_size)
{
    (void)in_sizes; (void)n_in; (void)out_size;
    const float* h    = (const float*)d_in[0];
    const float* e    = (const float*)d_in[1];
    const float* We   = (const float*)d_in[2];
    const float* be   = (const float*)d_in[3];
    const float* Ws   = (const float*)d_in[4];
    const float* bs   = (const float*)d_in[5];
    const float* Wd   = (const float*)d_in[6];
    const float* bd   = (const float*)d_in[7];
    const float* Wb   = (const float*)d_in[8];
    const float* bb   = (const float*)d_in[9];
    const float* ln1g = (const float*)d_in[10];
    const float* ln1b = (const float*)d_in[11];
    const float* Wqkv = (const float*)d_in[12];
    const float* bqkv = (const float*)d_in[13];
    const float* Wo   = (const float*)d_in[14];
    const float* bo   = (const float*)d_in[15];
    const float* ln2g = (const float*)d_in[16];
    const float* ln2b = (const float*)d_in[17];
    const float* W1   = (const float*)d_in[18];
    const float* b1   = (const float*)d_in[19];
    const float* W2   = (const float*)d_in[20];
    const float* b2   = (const float*)d_in[21];

    float* out_h2 = (float*)d_out;
    float* out_e  = out_h2 + (size_t)BN * DD;

    float *pHs, *pHd, *px1, *pqkv, *pbias, *po, *ph1, *py, *pf;
    __half* pWeTh;
    cudaGetSymbolAddress((void**)&pHs,   g_Hs);
    cudaGetSymbolAddress((void**)&pHd,   g_Hd);
    cudaGetSymbolAddress((void**)&px1,   g_x1);
    cudaGetSymbolAddress((void**)&pqkv,  g_qkv);
    cudaGetSymbolAddress((void**)&pbias, g_bias);
    cudaGetSymbolAddress((void**)&po,    g_o);
    cudaGetSymbolAddress((void**)&ph1,   g_h1);
    cudaGetSymbolAddress((void**)&py,    g_y);
    cudaGetSymbolAddress((void**)&pf,    g_ffn);
    cudaGetSymbolAddress((void**)&pWeTh, g_WeTh);

    // 1-5: node prep + edge prep (edge kernel is launch #6 for ncu -s 5)
    ln_kernel<<<BN, 256>>>(h, ln1g, ln1b, px1);
    gemm_t<0><<<dim3(8, 16), 256>>>(h, Ws, bs, nullptr, pHs, 256, 256);
    gemm_t<0><<<dim3(8, 16), 256>>>(h, Wd, bd, nullptr, pHd, 256, 256);
    prep_wet<<<256, 256>>>(We, pWeTh);
    zero_bias<<<2048, 256>>>((float4*)pbias);

    // 6: edge update + attention bias via fp16 mma
    cudaFuncSetAttribute(edge_mma_kernel,
                         cudaFuncAttributeMaxDynamicSharedMemorySize,
                         SM_EDGE_TOTAL);
    edge_mma_kernel<<<4096, 256, SM_EDGE_TOTAL>>>(
        e, pWeTh, be, pHs, pHd, Wb, out_e, pbias);

    // attention path
    gemm_t<0><<<dim3(24, 16), 256>>>(px1, Wqkv, bqkv, nullptr, pqkv, 256, 768);
    cudaFuncSetAttribute(attn_kernel,
                         cudaFuncAttributeMaxDynamicSharedMemorySize, 73728);
    attn_kernel<<<256, 256, 71808>>>(pqkv, pbias, bb, po);

    // output proj + residual
    gemm_t<0><<<dim3(8, 16), 256>>>(po, Wo, bo, h, ph1, 256, 256);

    // FFN
    ln_kernel<<<BN, 256>>>(ph1, ln2g, ln2b, py);
    gemm_t<1><<<dim3(32, 16), 256>>>(py, W1, b1, nullptr, pf, 256, 1024);
    gemm_t<0><<<dim3(8, 16), 256>>>(pf, W2, b2, ph1, out_h2, 1024, 256);
}

// round 5
// speedup vs baseline: 2.5531x; 1.1654x over previous
#include <cuda_runtime.h>
#include <cuda_fp16.h>
#include <math.h>
#include <stdint.h>

// Shapes (fixed): B=4, N=256, D=256, H=8, HD=32, DFF=1024
#define BN 1024
#define DD 256

// ---------------- scratch ----------------
__device__ __align__(16) float g_Hs[BN * DD];
__device__ __align__(16) float g_Hd[BN * DD];
__device__ __align__(16) float g_x1[BN * DD];
__device__ __align__(16) float g_qkv[BN * 768];
__device__ __align__(16) float g_bias[4 * 8 * 256 * 256];
__device__ __align__(16) float g_o[BN * DD];
__device__ __align__(16) float g_h1[BN * DD];
__device__ __align__(16) float g_y[BN * DD];
__device__ __align__(16) float g_ffn[BN * 1024];
__device__ __align__(16) __half g_WeTh[DD * DD];   // We^T in fp16

// ---------------- helpers ----------------
__device__ __forceinline__ uint32_t smem_u32(const void* p) {
    uint32_t a;
    asm("{ .reg .u64 t; cvta.to.shared.u64 t, %1; cvt.u32.u64 %0, t; }"
        : "=r"(a) : "l"(p));
    return a;
}
__device__ __forceinline__ void cp16(uint32_t dst, const void* src) {
    asm volatile("cp.async.cg.shared.global [%0], [%1], 16;"
                 :: "r"(dst), "l"(src));
}
__device__ __forceinline__ void ldmx4(uint32_t* r, uint32_t addr) {
    asm volatile(
        "ldmatrix.sync.aligned.m8n8.x4.shared.b16 {%0,%1,%2,%3}, [%4];"
        : "=r"(r[0]), "=r"(r[1]), "=r"(r[2]), "=r"(r[3]) : "r"(addr));
}
__device__ __forceinline__ void mma_f16(float* c, const uint32_t* a,
                                        uint32_t b0, uint32_t b1) {
    asm volatile(
        "mma.sync.aligned.m16n8k16.row.col.f32.f16.f16.f32 "
        "{%0,%1,%2,%3}, {%4,%5,%6,%7}, {%8,%9}, {%0,%1,%2,%3};"
        : "+f"(c[0]), "+f"(c[1]), "+f"(c[2]), "+f"(c[3])
        : "r"(a[0]), "r"(a[1]), "r"(a[2]), "r"(a[3]), "r"(b0), "r"(b1));
}
__device__ __forceinline__ uint32_t pack_h2(float x, float y) {
    __half2 h = __float22half2_rn(make_float2(x, y));
    return *reinterpret_cast<uint32_t*>(&h);
}

// ---------------- WeT prep: transpose + fp16 ----------------
__global__ __launch_bounds__(256) void prep_wet(const float* __restrict__ We,
                                                __half* __restrict__ WeTh) {
    int n = blockIdx.x, k = threadIdx.x;
    WeTh[n * 256 + k] = __float2half_rn(We[k * 256 + n]);
}

// ---------------- edge kernel: fp16 mma, 128x256 tile, 512 thr ----------
// smem layout (bytes):
#define SB_B     0          // 256 rows * 512B = 128KB (full WeT)
#define SB_A     131072     // 2 stages * 16KB
#define SM_SHS   163840     // 256 floats
#define SM_SWB   164864     // 2048 floats (Wb [d][h])
#define SM_SBIAS 173056     // 4 * 128 * 8 floats = 16KB
#define SM_EDGE_TOTAL 189440

__global__ __launch_bounds__(512, 1) void edge_mma_kernel(
    const float* __restrict__ e, const __half* __restrict__ WeTh,
    const float* __restrict__ be, const float* __restrict__ Hs,
    const float* __restrict__ Hd, const float* __restrict__ Wb,
    float* __restrict__ e_new, float* __restrict__ bias)
{
    extern __shared__ char smem[];
    const uint32_t sb = smem_u32(smem);
    float* sHs   = (float*)(smem + SM_SHS);
    float* sWb   = (float*)(smem + SM_SWB);
    float* sbias = (float*)(smem + SM_SBIAS);

    const int tid = threadIdx.x;
    const int w = tid >> 5, lane = tid & 31;
    const int g = lane >> 2, tig = lane & 3, x7 = lane & 7;
    const int wr = w >> 2, wc = w & 3;

    const int m0 = blockIdx.x * 128;
    const int b = m0 >> 16, i = (m0 >> 8) & 255, j0 = m0 & 255;

    // ---- B (full WeT, 256x256 halves) via cp.async, swizzled ----
    {
        const int ch = tid & 31;
        const int rbase = tid >> 5;
        #pragma unroll
        for (int it = 0; it < 16; ++it) {
            int row = rbase + it * 16;
            cp16(sb + SB_B + row * 512 + ((ch ^ (row & 7)) << 4),
                 WeTh + (size_t)row * 256 + ch * 8);
        }
    }
    asm volatile("cp.async.commit_group;");

    // ---- A chunk 0: LDG fp32 -> fp16 STS ----
    const float* Ab = e + (size_t)m0 * 256;
    const int seg = tid & 7;
    #pragma unroll
    for (int it = 0; it < 2; ++it) {
        int row = (tid >> 3) + it * 64;
        const float* p = Ab + (size_t)row * 256 + seg * 8;
        float4 v0 = *(const float4*)p;
        float4 v1 = *(const float4*)(p + 4);
        uint4 u = make_uint4(pack_h2(v0.x, v0.y), pack_h2(v0.z, v0.w),
                             pack_h2(v1.x, v1.y), pack_h2(v1.z, v1.w));
        *(uint4*)(smem + SB_A + row * 128 + ((seg ^ (row & 7)) << 4)) = u;
    }

    // ---- tables ----
    if (tid < 256)
        sHs[tid] = Hs[(((size_t)(b << 8) + i) << 8) + tid] + be[tid];
    #pragma unroll
    for (int q = 0; q < 4; ++q)
        sWb[tid + q * 512] = Wb[tid + q * 512];

    asm volatile("cp.async.wait_group 0;" ::: "memory");
    __syncthreads();

    // ldmatrix lane->row/sel mapping
    const int rowoffA = x7 + (((lane >> 3) & 1) << 3);
    const int selA = lane >> 4;
    const int rowoffB = x7 + ((lane >> 4) << 3);
    const int selB = (lane >> 3) & 1;

    float acc[2][8][4] = {};
    float4 pre[4];

    for (int c = 0; c < 4; ++c) {
        if (c < 3) {   // prefetch next A chunk into regs
            #pragma unroll
            for (int it = 0; it < 2; ++it) {
                int row = (tid >> 3) + it * 64;
                const float* p =
                    Ab + (size_t)row * 256 + (c + 1) * 64 + seg * 8;
                pre[it * 2]     = *(const float4*)p;
                pre[it * 2 + 1] = *(const float4*)(p + 4);
            }
        }
        const uint32_t sAc = sb + SB_A + (c & 1) * 16384;
        #pragma unroll
        for (int kk = 0; kk < 4; ++kk) {
            uint32_t a0[4], a1[4];
            {
                int rowA = wr * 32 + rowoffA;
                ldmx4(a0, sAc + rowA * 128 + ((((kk << 1) + selA) ^ x7) << 4));
                ldmx4(a1, sAc + (rowA + 16) * 128 +
                              ((((kk << 1) + selA) ^ x7) << 4));
            }
            uint32_t bf[4][4];
            #pragma unroll
            for (int nt2 = 0; nt2 < 4; ++nt2) {
                int rowB = wc * 64 + nt2 * 16 + rowoffB;
                ldmx4(bf[nt2], sb + SB_B + rowB * 512 +
                               (((c * 8 + (kk << 1) + selB) ^ x7) << 4));
            }
            #pragma unroll
            for (int nt2 = 0; nt2 < 4; ++nt2) {
                mma_f16(acc[0][nt2 * 2],     a0, bf[nt2][0], bf[nt2][1]);
                mma_f16(acc[0][nt2 * 2 + 1], a0, bf[nt2][2], bf[nt2][3]);
                mma_f16(acc[1][nt2 * 2],     a1, bf[nt2][0], bf[nt2][1]);
                mma_f16(acc[1][nt2 * 2 + 1], a1, bf[nt2][2], bf[nt2][3]);
            }
        }
        __syncthreads();
        if (c < 3) {
            char* dst = smem + SB_A + ((c + 1) & 1) * 16384;
            #pragma unroll
            for (int it = 0; it < 2; ++it) {
                int row = (tid >> 3) + it * 64;
                float4 v0 = pre[it * 2], v1 = pre[it * 2 + 1];
                uint4 u = make_uint4(pack_h2(v0.x, v0.y), pack_h2(v0.z, v0.w),
                                     pack_h2(v1.x, v1.y), pack_h2(v1.z, v1.w));
                *(uint4*)(dst + row * 128 + ((seg ^ (row & 7)) << 4)) = u;
            }
            __syncthreads();
        }
    }

    // ---- epilogue: +Hs +Hd, ReLU, store e_new, bias head-reduce ----
    float pb[4][8] = {};
    #pragma unroll
    for (int mt = 0; mt < 2; ++mt) {
        #pragma unroll
        for (int rh = 0; rh < 2; ++rh) {
            const int rl = wr * 32 + mt * 16 + rh * 8 + g;
            const float* hdrow = Hd + ((((size_t)b << 8) + j0 + rl) << 8);
            float* erow = e_new + ((size_t)(m0 + rl)) * 256;
            const int p = mt * 2 + rh;
            #pragma unroll
            for (int nt = 0; nt < 8; ++nt) {
                const int cl = wc * 64 + nt * 8 + 2 * tig;
                float x0 = acc[mt][nt][rh * 2 + 0] + sHs[cl] + hdrow[cl];
                float x1 = acc[mt][nt][rh * 2 + 1] + sHs[cl + 1] + hdrow[cl + 1];
                x0 = fmaxf(x0, 0.0f);
                x1 = fmaxf(x1, 0.0f);
                *(float2*)(erow + cl) = make_float2(x0, x1);
                const float* w0 = sWb + cl * 8;
                #pragma unroll
                for (int hh = 0; hh < 8; ++hh)
                    pb[p][hh] += x0 * w0[hh] + x1 * w0[8 + hh];
            }
        }
    }
    #pragma unroll
    for (int p = 0; p < 4; ++p)
        #pragma unroll
        for (int hh = 0; hh < 8; ++hh) {
            float s = pb[p][hh];
            s += __shfl_xor_sync(0xffffffffu, s, 1);
            s += __shfl_xor_sync(0xffffffffu, s, 2);
            pb[p][hh] = s;
        }
    if (tig == 0) {
        #pragma unroll
        for (int p = 0; p < 4; ++p) {
            int rl = wr * 32 + (p >> 1) * 16 + (p & 1) * 8 + g;
            #pragma unroll
            for (int hh = 0; hh < 8; ++hh)
                sbias[wc * 1024 + rl * 8 + hh] = pb[p][hh];
        }
    }
    __syncthreads();
    #pragma unroll
    for (int q = 0; q < 2; ++q) {
        int t = tid + q * 512;
        int r = t & 127, hh = t >> 7;
        float v = sbias[r * 8 + hh] + sbias[1024 + r * 8 + hh] +
                  sbias[2048 + r * 8 + hh] + sbias[3072 + r * 8 + hh];
        bias[((((size_t)b * 8 + hh) * 256 + i) << 8) + j0 + r] = v;
    }
}

// ---------------- LayerNorm ----------------
__global__ __launch_bounds__(256) void ln_kernel(
    const float* __restrict__ in, const float* __restrict__ g,
    const float* __restrict__ b, float* __restrict__ out)
{
    int row = blockIdx.x;
    int t = threadIdx.x;
    float v = in[(size_t)row * 256 + t];
    __shared__ float red[8];

    float s = v;
    #pragma unroll
    for (int o = 16; o; o >>= 1) s += __shfl_xor_sync(0xffffffffu, s, o);
    if ((t & 31) == 0) red[t >> 5] = s;
    __syncthreads();
    float mean = (red[0] + red[1] + red[2] + red[3] +
                  red[4] + red[5] + red[6] + red[7]) * (1.0f / 256.0f);
    float d = v - mean;
    __syncthreads();
    s = d * d;
    #pragma unroll
    for (int o = 16; o; o >>= 1) s += __shfl_xor_sync(0xffffffffu, s, o);
    if ((t & 31) == 0) red[t >> 5] = s;
    __syncthreads();
    float var = (red[0] + red[1] + red[2] + red[3] +
                 red[4] + red[5] + red[6] + red[7]) * (1.0f / 256.0f);
    out[(size_t)row * 256 + t] = d * rsqrtf(var + 1e-5f) * g[t] + b[t];
}

// ---------------- small fp32 GEMM: tile 64x32 ----------------
__device__ __forceinline__ float gelu_exact(float x) {
    return 0.5f * x * (1.0f + erff(x * 0.70710678118654752f));
}

template <int OP>
__global__ __launch_bounds__(256) void gemm_t(
    const float* __restrict__ A, const float* __restrict__ W,
    const float* __restrict__ bias, const float* __restrict__ res,
    float* __restrict__ out, int K, int Ncols)
{
    __shared__ float As[64][16];
    __shared__ float Bs[16][32];
    const int tid = threadIdx.x;
    const int m0 = blockIdx.y * 64;
    const int c0 = blockIdx.x * 32;
    const int ty = tid >> 3;
    const int tx = tid & 7;

    float acc[2][4] = {};

    for (int k0 = 0; k0 < K; k0 += 16) {
        {
            int r = tid >> 2, q = tid & 3;
            *(float4*)&As[r][q * 4] =
                *(const float4*)(A + (size_t)(m0 + r) * K + k0 + q * 4);
        }
        if (tid < 128) {
            int kk = tid >> 3, q = tid & 7;
            *(float4*)&Bs[kk][q * 4] =
                *(const float4*)(W + (size_t)(k0 + kk) * Ncols + c0 + q * 4);
        }
        __syncthreads();
        #pragma unroll
        for (int k = 0; k < 16; ++k) {
            float a0 = As[ty * 2][k];
            float a1 = As[ty * 2 + 1][k];
            float4 bv = *(float4*)&Bs[k][tx * 4];
            acc[0][0] += a0 * bv.x; acc[0][1] += a0 * bv.y;
            acc[0][2] += a0 * bv.z; acc[0][3] += a0 * bv.w;
            acc[1][0] += a1 * bv.x; acc[1][1] += a1 * bv.y;
            acc[1][2] += a1 * bv.z; acc[1][3] += a1 * bv.w;
        }
        __syncthreads();
    }

    float4 bs4 = *(const float4*)(bias + c0 + tx * 4);
    #pragma unroll
    for (int r = 0; r < 2; ++r) {
        int m = m0 + ty * 2 + r;
        float v0 = acc[r][0] + bs4.x;
        float v1 = acc[r][1] + bs4.y;
        float v2 = acc[r][2] + bs4.z;
        float v3 = acc[r][3] + bs4.w;
        if (OP == 1) {
            v0 = gelu_exact(v0); v1 = gelu_exact(v1);
            v2 = gelu_exact(v2); v3 = gelu_exact(v3);
        }
        if (res) {
            float4 rr = *(const float4*)(res + (size_t)m * Ncols + c0 + tx * 4);
            v0 += rr.x; v1 += rr.y; v2 += rr.z; v3 += rr.w;
        }
        *(float4*)(out + (size_t)m * Ncols + c0 + tx * 4) =
            make_float4(v0, v1, v2, v3);
    }
}

// ---------------- dual GEMM for Hs/Hd (one launch) ----------------
__global__ __launch_bounds__(256) void gemm_hsd(
    const float* __restrict__ A,
    const float* __restrict__ Ws, const float* __restrict__ bs,
    const float* __restrict__ Wd, const float* __restrict__ bd,
    float* __restrict__ oHs, float* __restrict__ oHd)
{
    const float* W    = blockIdx.z ? Wd : Ws;
    const float* bias = blockIdx.z ? bd : bs;
    float* out        = blockIdx.z ? oHd : oHs;

    __shared__ float As[64][16];
    __shared__ float Bs[16][32];
    const int tid = threadIdx.x;
    const int m0 = blockIdx.y * 64;
    const int c0 = blockIdx.x * 32;
    const int ty = tid >> 3;
    const int tx = tid & 7;

    float acc[2][4] = {};

    for (int k0 = 0; k0 < 256; k0 += 16) {
        {
            int r = tid >> 2, q = tid & 3;
            *(float4*)&As[r][q * 4] =
                *(const float4*)(A + (size_t)(m0 + r) * 256 + k0 + q * 4);
        }
        if (tid < 128) {
            int kk = tid >> 3, q = tid & 7;
            *(float4*)&Bs[kk][q * 4] =
                *(const float4*)(W + (size_t)(k0 + kk) * 256 + c0 + q * 4);
        }
        __syncthreads();
        #pragma unroll
        for (int k = 0; k < 16; ++k) {
            float a0 = As[ty * 2][k];
            float a1 = As[ty * 2 + 1][k];
            float4 bv = *(float4*)&Bs[k][tx * 4];
            acc[0][0] += a0 * bv.x; acc[0][1] += a0 * bv.y;
            acc[0][2] += a0 * bv.z; acc[0][3] += a0 * bv.w;
            acc[1][0] += a1 * bv.x; acc[1][1] += a1 * bv.y;
            acc[1][2] += a1 * bv.z; acc[1][3] += a1 * bv.w;
        }
        __syncthreads();
    }

    float4 bs4 = *(const float4*)(bias + c0 + tx * 4);
    #pragma unroll
    for (int r = 0; r < 2; ++r) {
        int m = m0 + ty * 2 + r;
        *(float4*)(out + (size_t)m * 256 + c0 + tx * 4) =
            make_float4(acc[r][0] + bs4.x, acc[r][1] + bs4.y,
                        acc[r][2] + bs4.z, acc[r][3] + bs4.w);
    }
}

// ---------------- attention kernel ----------------
__global__ __launch_bounds__(256) void attn_kernel(
    const float* __restrict__ qkv, const float* __restrict__ bias,
    const float* __restrict__ bb, float* __restrict__ o)
{
    extern __shared__ float sm[];
    float (*ks)[33] = (float(*)[33])sm;
    float (*vs)[33] = (float(*)[33])(sm + 256 * 33);
    float (*qs)[33] = (float(*)[33])(sm + 2 * 256 * 33);

    const int tid = threadIdx.x;
    const int tile = blockIdx.x & 7;
    const int bh = blockIdx.x >> 3;
    const int b = bh >> 3, hh = bh & 7;
    const int i0 = tile * 32;
    const float bbv = bb[hh];

    for (int idx = tid; idx < 2048; idx += 256) {
        int j = idx >> 3, q4 = idx & 7;
        const float* base = qkv + (size_t)(b * 256 + j) * 768 + hh * 32 + q4 * 4;
        float4 kk = *(const float4*)(base + 256);
        float4 vv = *(const float4*)(base + 512);
        ks[j][q4 * 4 + 0] = kk.x; ks[j][q4 * 4 + 1] = kk.y;
        ks[j][q4 * 4 + 2] = kk.z; ks[j][q4 * 4 + 3] = kk.w;
        vs[j][q4 * 4 + 0] = vv.x; vs[j][q4 * 4 + 1] = vv.y;
        vs[j][q4 * 4 + 2] = vv.z; vs[j][q4 * 4 + 3] = vv.w;
    }
    for (int idx = tid; idx < 1024; idx += 256) {
        int r = idx >> 5, d = idx & 31;
        qs[r][d] = qkv[(size_t)(b * 256 + i0 + r) * 768 + hh * 32 + d];
    }
    __syncthreads();

    const int r = tid >> 3, s = tid & 7;
    const int i = i0 + r;
    const float* brow = bias + ((((size_t)b * 8 + hh) * 256 + i) << 8);

    float sc[32];
    float mx = -1e30f;
    #pragma unroll
    for (int jj = 0; jj < 32; ++jj) {
        int j = jj * 8 + s;
        float a = 0.0f;
        #pragma unroll
        for (int d = 0; d < 32; ++d) a += qs[r][d] * ks[j][d];
        a = a * 0.17677669529663687f + brow[j] + bbv;
        sc[jj] = a;
        mx = fmaxf(mx, a);
    }
    #pragma unroll
    for (int off = 4; off; off >>= 1)
        mx = fmaxf(mx, __shfl_xor_sync(0xffffffffu, mx, off));

    float sum = 0.0f;
    #pragma unroll
    for (int jj = 0; jj < 32; ++jj) { sc[jj] = expf(sc[jj] - mx); sum += sc[jj]; }
    #pragma unroll
    for (int off = 4; off; off >>= 1)
        sum += __shfl_xor_sync(0xffffffffu, sum, off);
    float inv = 1.0f / sum;

    float oacc[32] = {};
    #pragma unroll
    for (int jj = 0; jj < 32; ++jj) {
        int j = jj * 8 + s;
        float w = sc[jj];
        #pragma unroll
        for (int d = 0; d < 32; ++d) oacc[d] += w * vs[j][d];
    }

    float w4[4];
    #pragma unroll
    for (int d = 0; d < 32; ++d) {
        float t = oacc[d];
        t += __shfl_xor_sync(0xffffffffu, t, 1);
        t += __shfl_xor_sync(0xffffffffu, t, 2);
        t += __shfl_xor_sync(0xffffffffu, t, 4);
        if ((d >> 2) == s) w4[d & 3] = t;
    }
    *(float4*)(o + ((size_t)(b * 256 + i)) * 256 + hh * 32 + s * 4) =
        make_float4(w4[0] * inv, w4[1] * inv, w4[2] * inv, w4[3] * inv);
}

// ---------------- launch ----------------
extern "C" void kernel_launch(void* const* d_in, const int* in_sizes, int n_in,
                              void* d_out, int out_size)
{
    (void)in_sizes; (void)n_in; (void)out_size;
    const float* h    = (const float*)d_in[0];
    const float* e    = (const float*)d_in[1];
    const float* We   = (const float*)d_in[2];
    const float* be   = (const float*)d_in[3];
    const float* Ws   = (const float*)d_in[4];
    const float* bs   = (const float*)d_in[5];
    const float* Wd   = (const float*)d_in[6];
    const float* bd   = (const float*)d_in[7];
    const float* Wb   = (const float*)d_in[8];
    const float* bb   = (const float*)d_in[9];
    const float* ln1g = (const float*)d_in[10];
    const float* ln1b = (const float*)d_in[11];
    const float* Wqkv = (const float*)d_in[12];
    const float* bqkv = (const float*)d_in[13];
    const float* Wo   = (const float*)d_in[14];
    const float* bo   = (const float*)d_in[15];
    const float* ln2g = (const float*)d_in[16];
    const float* ln2b = (const float*)d_in[17];
    const float* W1   = (const float*)d_in[18];
    const float* b1   = (const float*)d_in[19];
    const float* W2   = (const float*)d_in[20];
    const float* b2   = (const float*)d_in[21];

    float* out_h2 = (float*)d_out;
    float* out_e  = out_h2 + (size_t)BN * DD;

    float *pHs, *pHd, *px1, *pqkv, *pbias, *po, *ph1, *py, *pf;
    __half* pWeTh;
    cudaGetSymbolAddress((void**)&pHs,   g_Hs);
    cudaGetSymbolAddress((void**)&pHd,   g_Hd);
    cudaGetSymbolAddress((void**)&px1,   g_x1);
    cudaGetSymbolAddress((void**)&pqkv,  g_qkv);
    cudaGetSymbolAddress((void**)&pbias, g_bias);
    cudaGetSymbolAddress((void**)&po,    g_o);
    cudaGetSymbolAddress((void**)&ph1,   g_h1);
    cudaGetSymbolAddress((void**)&py,    g_y);
    cudaGetSymbolAddress((void**)&pf,    g_ffn);
    cudaGetSymbolAddress((void**)&pWeTh, g_WeTh);

    // #1-3: prep (edge kernel is launch #4 so ncu -s captures it)
    prep_wet<<<256, 256>>>(We, pWeTh);
    gemm_hsd<<<dim3(8, 16, 2), 256>>>(h, Ws, bs, Wd, bd, pHs, pHd);
    ln_kernel<<<BN, 256>>>(h, ln1g, ln1b, px1);

    // #4: edge update + attention bias
    cudaFuncSetAttribute(edge_mma_kernel,
                         cudaFuncAttributeMaxDynamicSharedMemorySize,
                         SM_EDGE_TOTAL);
    edge_mma_kernel<<<2048, 512, SM_EDGE_TOTAL>>>(
        e, pWeTh, be, pHs, pHd, Wb, out_e, pbias);

    // attention path
    gemm_t<0><<<dim3(24, 16), 256>>>(px1, Wqkv, bqkv, nullptr, pqkv, 256, 768);
    cudaFuncSetAttribute(attn_kernel,
                         cudaFuncAttributeMaxDynamicSharedMemorySize, 73728);
    attn_kernel<<<256, 256, 71808>>>(pqkv, pbias, bb, po);

    // output proj + residual
    gemm_t<0><<<dim3(8, 16), 256>>>(po, Wo, bo, h, ph1, 256, 256);

    // FFN
    ln_kernel<<<BN, 256>>>(ph1, ln2g, ln2b, py);
    gemm_t<1><<<dim3(32, 16), 256>>>(py, W1, b1, nullptr, pf, 256, 1024);
    gemm_t<0><<<dim3(8, 16), 256>>>(pf, W2, b2, ph1, out_h2, 1024, 256);
}

// round 6
// speedup vs baseline: 2.8377x; 1.1115x over previous
#include <cuda_runtime.h>
#include <cuda_fp16.h>
#include <math.h>
#include <stdint.h>

// Shapes (fixed): B=4, N=256, D=256, H=8, HD=32, DFF=1024
#define BN 1024
#define DD 256

// ---------------- scratch ----------------
__device__ __align__(16) float g_Hs[BN * DD];
__device__ __align__(16) float g_Hd[BN * DD];
__device__ __align__(16) float g_x1[BN * DD];
__device__ __align__(16) float g_qkv[BN * 768];
__device__ __align__(16) float g_bias[4 * 8 * 256 * 256];
__device__ __align__(16) float g_o[BN * DD];
__device__ __align__(16) float g_h1[BN * DD];
__device__ __align__(16) float g_y[BN * DD];
__device__ __align__(16) float g_ffn[BN * 1024];
__device__ __align__(16) __half g_WeTh[DD * DD];   // We^T in fp16

// ---------------- helpers ----------------
__device__ __forceinline__ uint32_t smem_u32(const void* p) {
    uint32_t a;
    asm("{ .reg .u64 t; cvta.to.shared.u64 t, %1; cvt.u32.u64 %0, t; }"
        : "=r"(a) : "l"(p));
    return a;
}
__device__ __forceinline__ void cp16(uint32_t dst, const void* src) {
    asm volatile("cp.async.cg.shared.global [%0], [%1], 16;"
                 :: "r"(dst), "l"(src));
}
__device__ __forceinline__ void ldmx4(uint32_t* r, uint32_t addr) {
    asm volatile(
        "ldmatrix.sync.aligned.m8n8.x4.shared.b16 {%0,%1,%2,%3}, [%4];"
        : "=r"(r[0]), "=r"(r[1]), "=r"(r[2]), "=r"(r[3]) : "r"(addr));
}
__device__ __forceinline__ void mma_f16(float* c, const uint32_t* a,
                                        uint32_t b0, uint32_t b1) {
    asm volatile(
        "mma.sync.aligned.m16n8k16.row.col.f32.f16.f16.f32 "
        "{%0,%1,%2,%3}, {%4,%5,%6,%7}, {%8,%9}, {%0,%1,%2,%3};"
        : "+f"(c[0]), "+f"(c[1]), "+f"(c[2]), "+f"(c[3])
        : "r"(a[0]), "r"(a[1]), "r"(a[2]), "r"(a[3]), "r"(b0), "r"(b1));
}
__device__ __forceinline__ uint32_t pack_h2(float x, float y) {
    __half2 h = __float22half2_rn(make_float2(x, y));
    return *reinterpret_cast<uint32_t*>(&h);
}

// ---------------- WeT prep: transpose + fp16 ----------------
__global__ __launch_bounds__(256) void prep_wet(const float* __restrict__ We,
                                                __half* __restrict__ WeTh) {
    int n = blockIdx.x, k = threadIdx.x;
    WeTh[n * 256 + k] = __float2half_rn(We[k * 256 + n]);
}

// ---------------- edge kernel: fp16 mma, 128x256 tile, 512 thr ----------
// smem layout (bytes):
#define SB_B     0          // 256 rows * 512B = 128KB (full WeT)
#define SB_A     131072     // 2 stages * 16KB
#define SM_SHS   163840     // 256 floats
#define SM_SBIAS 164864     // 4 * 128 * 8 floats = 16KB
#define SM_EDGE_TOTAL 181248

__global__ __launch_bounds__(512, 1) void edge_mma_kernel(
    const float* __restrict__ e, const __half* __restrict__ WeTh,
    const float* __restrict__ be, const float* __restrict__ Hs,
    const float* __restrict__ Hd, const float* __restrict__ Wb,
    float* __restrict__ e_new, float* __restrict__ bias)
{
    extern __shared__ char smem[];
    const uint32_t sb = smem_u32(smem);
    float* sHs   = (float*)(smem + SM_SHS);
    float* sbias = (float*)(smem + SM_SBIAS);

    const int tid = threadIdx.x;
    const int w = tid >> 5, lane = tid & 31;
    const int g = lane >> 2, tig = lane & 3, x7 = lane & 7;
    const int wr = w >> 2, wc = w & 3;

    const int m0 = blockIdx.x * 128;
    const int b = m0 >> 16, i = (m0 >> 8) & 255, j0 = m0 & 255;

    // ---- B (full WeT, 256x256 halves) via cp.async, swizzled ----
    {
        const int ch = tid & 31;
        const int rbase = tid >> 5;
        #pragma unroll
        for (int it = 0; it < 16; ++it) {
            int row = rbase + it * 16;
            cp16(sb + SB_B + row * 512 + ((ch ^ (row & 7)) << 4),
                 WeTh + (size_t)row * 256 + ch * 8);
        }
    }
    asm volatile("cp.async.commit_group;");

    // ---- A chunk 0: LDG fp32 -> fp16 STS ----
    const float* Ab = e + (size_t)m0 * 256;
    const int seg = tid & 7;
    #pragma unroll
    for (int it = 0; it < 2; ++it) {
        int row = (tid >> 3) + it * 64;
        const float* p = Ab + (size_t)row * 256 + seg * 8;
        float4 v0 = *(const float4*)p;
        float4 v1 = *(const float4*)(p + 4);
        uint4 u = make_uint4(pack_h2(v0.x, v0.y), pack_h2(v0.z, v0.w),
                             pack_h2(v1.x, v1.y), pack_h2(v1.z, v1.w));
        *(uint4*)(smem + SB_A + row * 128 + ((seg ^ (row & 7)) << 4)) = u;
    }

    // ---- tables + per-warp Wb B-fragments (registers) ----
    if (tid < 256)
        sHs[tid] = Hs[(((size_t)(b << 8) + i) << 8) + tid] + be[tid];

    uint32_t bw0[4], bw1[4];
    #pragma unroll
    for (int kc = 0; kc < 4; ++kc) {
        int k0 = wc * 64 + kc * 16 + 2 * tig;
        bw0[kc] = pack_h2(Wb[(k0    ) * 8 + g], Wb[(k0 + 1) * 8 + g]);
        bw1[kc] = pack_h2(Wb[(k0 + 8) * 8 + g], Wb[(k0 + 9) * 8 + g]);
    }

    asm volatile("cp.async.wait_group 0;" ::: "memory");
    __syncthreads();

    // ldmatrix lane->row/sel mapping
    const int rowoffA = x7 + (((lane >> 3) & 1) << 3);
    const int selA = lane >> 4;
    const int rowoffB = x7 + ((lane >> 4) << 3);
    const int selB = (lane >> 3) & 1;

    float acc[2][8][4] = {};
    float4 pre[4];

    for (int c = 0; c < 4; ++c) {
        if (c < 3) {   // prefetch next A chunk into regs
            #pragma unroll
            for (int it = 0; it < 2; ++it) {
                int row = (tid >> 3) + it * 64;
                const float* p =
                    Ab + (size_t)row * 256 + (c + 1) * 64 + seg * 8;
                pre[it * 2]     = *(const float4*)p;
                pre[it * 2 + 1] = *(const float4*)(p + 4);
            }
        }
        const uint32_t sAc = sb + SB_A + (c & 1) * 16384;
        #pragma unroll
        for (int kk = 0; kk < 4; ++kk) {
            uint32_t a0[4], a1[4];
            {
                int rowA = wr * 32 + rowoffA;
                ldmx4(a0, sAc + rowA * 128 + ((((kk << 1) + selA) ^ x7) << 4));
                ldmx4(a1, sAc + (rowA + 16) * 128 +
                              ((((kk << 1) + selA) ^ x7) << 4));
            }
            uint32_t bf[4][4];
            #pragma unroll
            for (int nt2 = 0; nt2 < 4; ++nt2) {
                int rowB = wc * 64 + nt2 * 16 + rowoffB;
                ldmx4(bf[nt2], sb + SB_B + rowB * 512 +
                               (((c * 8 + (kk << 1) + selB) ^ x7) << 4));
            }
            #pragma unroll
            for (int nt2 = 0; nt2 < 4; ++nt2) {
                mma_f16(acc[0][nt2 * 2],     a0, bf[nt2][0], bf[nt2][1]);
                mma_f16(acc[0][nt2 * 2 + 1], a0, bf[nt2][2], bf[nt2][3]);
                mma_f16(acc[1][nt2 * 2],     a1, bf[nt2][0], bf[nt2][1]);
                mma_f16(acc[1][nt2 * 2 + 1], a1, bf[nt2][2], bf[nt2][3]);
            }
        }
        __syncthreads();
        if (c < 3) {
            char* dst = smem + SB_A + ((c + 1) & 1) * 16384;
            #pragma unroll
            for (int it = 0; it < 2; ++it) {
                int row = (tid >> 3) + it * 64;
                float4 v0 = pre[it * 2], v1 = pre[it * 2 + 1];
                uint4 u = make_uint4(pack_h2(v0.x, v0.y), pack_h2(v0.z, v0.w),
                                     pack_h2(v1.x, v1.y), pack_h2(v1.z, v1.w));
                *(uint4*)(dst + row * 128 + ((seg ^ (row & 7)) << 4)) = u;
            }
            __syncthreads();
        }
    }

    // ---- epilogue: +Hs +Hd, ReLU, store e_new, bias via mma ----
    float bc[2][4] = {};
    #pragma unroll
    for (int mt = 0; mt < 2; ++mt) {
        const int rl = wr * 32 + mt * 16 + g;
        const float* hd0 = Hd + ((((size_t)b << 8) + j0 + rl) << 8);
        const float* hd1 = hd0 + (8 << 8);
        float* er0 = e_new + ((size_t)(m0 + rl)) * 256;
        float* er1 = er0 + 8 * 256;
        uint32_t afr[4];
        #pragma unroll
        for (int nt = 0; nt < 8; ++nt) {
            const int cl = wc * 64 + nt * 8 + 2 * tig;
            float2 hs = *(const float2*)(sHs + cl);
            float2 h0 = *(const float2*)(hd0 + cl);
            float2 h1 = *(const float2*)(hd1 + cl);
            float x0 = fmaxf(acc[mt][nt][0] + hs.x + h0.x, 0.0f);
            float x1 = fmaxf(acc[mt][nt][1] + hs.y + h0.y, 0.0f);
            float x2 = fmaxf(acc[mt][nt][2] + hs.x + h1.x, 0.0f);
            float x3 = fmaxf(acc[mt][nt][3] + hs.y + h1.y, 0.0f);
            *(float2*)(er0 + cl) = make_float2(x0, x1);
            *(float2*)(er1 + cl) = make_float2(x2, x3);
            if ((nt & 1) == 0) {
                afr[0] = pack_h2(x0, x1);
                afr[1] = pack_h2(x2, x3);
            } else {
                afr[2] = pack_h2(x0, x1);
                afr[3] = pack_h2(x2, x3);
                mma_f16(bc[mt], afr, bw0[nt >> 1], bw1[nt >> 1]);
            }
        }
    }
    // store per-warp bias partials (rows g/g+8, heads 2tig/2tig+1)
    {
        float* sbw = sbias + wc * 1024;
        #pragma unroll
        for (int mt = 0; mt < 2; ++mt) {
            int rl = wr * 32 + mt * 16 + g;
            sbw[rl * 8 + 2 * tig]           = bc[mt][0];
            sbw[rl * 8 + 2 * tig + 1]       = bc[mt][1];
            sbw[(rl + 8) * 8 + 2 * tig]     = bc[mt][2];
            sbw[(rl + 8) * 8 + 2 * tig + 1] = bc[mt][3];
        }
    }
    __syncthreads();
    #pragma unroll
    for (int q = 0; q < 2; ++q) {
        int t = tid + q * 512;
        int r = t & 127, hh = t >> 7;
        float v = sbias[r * 8 + hh] + sbias[1024 + r * 8 + hh] +
                  sbias[2048 + r * 8 + hh] + sbias[3072 + r * 8 + hh];
        bias[((((size_t)b * 8 + hh) * 256 + i) << 8) + j0 + r] = v;
    }
}

// ---------------- LayerNorm ----------------
__global__ __launch_bounds__(256) void ln_kernel(
    const float* __restrict__ in, const float* __restrict__ g,
    const float* __restrict__ b, float* __restrict__ out)
{
    int row = blockIdx.x;
    int t = threadIdx.x;
    float v = in[(size_t)row * 256 + t];
    __shared__ float red[8];

    float s = v;
    #pragma unroll
    for (int o = 16; o; o >>= 1) s += __shfl_xor_sync(0xffffffffu, s, o);
    if ((t & 31) == 0) red[t >> 5] = s;
    __syncthreads();
    float mean = (red[0] + red[1] + red[2] + red[3] +
                  red[4] + red[5] + red[6] + red[7]) * (1.0f / 256.0f);
    float d = v - mean;
    __syncthreads();
    s = d * d;
    #pragma unroll
    for (int o = 16; o; o >>= 1) s += __shfl_xor_sync(0xffffffffu, s, o);
    if ((t & 31) == 0) red[t >> 5] = s;
    __syncthreads();
    float var = (red[0] + red[1] + red[2] + red[3] +
                 red[4] + red[5] + red[6] + red[7]) * (1.0f / 256.0f);
    out[(size_t)row * 256 + t] = d * rsqrtf(var + 1e-5f) * g[t] + b[t];
}

// ---------------- small fp32 GEMM: tile 64x32 ----------------
__device__ __forceinline__ float gelu_exact(float x) {
    return 0.5f * x * (1.0f + erff(x * 0.70710678118654752f));
}

template <int OP>
__global__ __launch_bounds__(256) void gemm_t(
    const float* __restrict__ A, const float* __restrict__ W,
    const float* __restrict__ bias, const float* __restrict__ res,
    float* __restrict__ out, int K, int Ncols)
{
    __shared__ float As[64][16];
    __shared__ float Bs[16][32];
    const int tid = threadIdx.x;
    const int m0 = blockIdx.y * 64;
    const int c0 = blockIdx.x * 32;
    const int ty = tid >> 3;
    const int tx = tid & 7;

    float acc[2][4] = {};

    for (int k0 = 0; k0 < K; k0 += 16) {
        {
            int r = tid >> 2, q = tid & 3;
            *(float4*)&As[r][q * 4] =
                *(const float4*)(A + (size_t)(m0 + r) * K + k0 + q * 4);
        }
        if (tid < 128) {
            int kk = tid >> 3, q = tid & 7;
            *(float4*)&Bs[kk][q * 4] =
                *(const float4*)(W + (size_t)(k0 + kk) * Ncols + c0 + q * 4);
        }
        __syncthreads();
        #pragma unroll
        for (int k = 0; k < 16; ++k) {
            float a0 = As[ty * 2][k];
            float a1 = As[ty * 2 + 1][k];
            float4 bv = *(float4*)&Bs[k][tx * 4];
            acc[0][0] += a0 * bv.x; acc[0][1] += a0 * bv.y;
            acc[0][2] += a0 * bv.z; acc[0][3] += a0 * bv.w;
            acc[1][0] += a1 * bv.x; acc[1][1] += a1 * bv.y;
            acc[1][2] += a1 * bv.z; acc[1][3] += a1 * bv.w;
        }
        __syncthreads();
    }

    float4 bs4 = *(const float4*)(bias + c0 + tx * 4);
    #pragma unroll
    for (int r = 0; r < 2; ++r) {
        int m = m0 + ty * 2 + r;
        float v0 = acc[r][0] + bs4.x;
        float v1 = acc[r][1] + bs4.y;
        float v2 = acc[r][2] + bs4.z;
        float v3 = acc[r][3] + bs4.w;
        if (OP == 1) {
            v0 = gelu_exact(v0); v1 = gelu_exact(v1);
            v2 = gelu_exact(v2); v3 = gelu_exact(v3);
        }
        if (res) {
            float4 rr = *(const float4*)(res + (size_t)m * Ncols + c0 + tx * 4);
            v0 += rr.x; v1 += rr.y; v2 += rr.z; v3 += rr.w;
        }
        *(float4*)(out + (size_t)m * Ncols + c0 + tx * 4) =
            make_float4(v0, v1, v2, v3);
    }
}

// ---------------- dual GEMM for Hs/Hd (one launch) ----------------
__global__ __launch_bounds__(256) void gemm_hsd(
    const float* __restrict__ A,
    const float* __restrict__ Ws, const float* __restrict__ bs,
    const float* __restrict__ Wd, const float* __restrict__ bd,
    float* __restrict__ oHs, float* __restrict__ oHd)
{
    const float* W    = blockIdx.z ? Wd : Ws;
    const float* bias = blockIdx.z ? bd : bs;
    float* out        = blockIdx.z ? oHd : oHs;

    __shared__ float As[64][16];
    __shared__ float Bs[16][32];
    const int tid = threadIdx.x;
    const int m0 = blockIdx.y * 64;
    const int c0 = blockIdx.x * 32;
    const int ty = tid >> 3;
    const int tx = tid & 7;

    float acc[2][4] = {};

    for (int k0 = 0; k0 < 256; k0 += 16) {
        {
            int r = tid >> 2, q = tid & 3;
            *(float4*)&As[r][q * 4] =
                *(const float4*)(A + (size_t)(m0 + r) * 256 + k0 + q * 4);
        }
        if (tid < 128) {
            int kk = tid >> 3, q = tid & 7;
            *(float4*)&Bs[kk][q * 4] =
                *(const float4*)(W + (size_t)(k0 + kk) * 256 + c0 + q * 4);
        }
        __syncthreads();
        #pragma unroll
        for (int k = 0; k < 16; ++k) {
            float a0 = As[ty * 2][k];
            float a1 = As[ty * 2 + 1][k];
            float4 bv = *(float4*)&Bs[k][tx * 4];
            acc[0][0] += a0 * bv.x; acc[0][1] += a0 * bv.y;
            acc[0][2] += a0 * bv.z; acc[0][3] += a0 * bv.w;
            acc[1][0] += a1 * bv.x; acc[1][1] += a1 * bv.y;
            acc[1][2] += a1 * bv.z; acc[1][3] += a1 * bv.w;
        }
        __syncthreads();
    }

    float4 bs4 = *(const float4*)(bias + c0 + tx * 4);
    #pragma unroll
    for (int r = 0; r < 2; ++r) {
        int m = m0 + ty * 2 + r;
        *(float4*)(out + (size_t)m * 256 + c0 + tx * 4) =
            make_float4(acc[r][0] + bs4.x, acc[r][1] + bs4.y,
                        acc[r][2] + bs4.z, acc[r][3] + bs4.w);
    }
}

// ---------------- attention kernel ----------------
__global__ __launch_bounds__(256) void attn_kernel(
    const float* __restrict__ qkv, const float* __restrict__ bias,
    const float* __restrict__ bb, float* __restrict__ o)
{
    extern __shared__ float sm[];
    float (*ks)[33] = (float(*)[33])sm;
    float (*vs)[33] = (float(*)[33])(sm + 256 * 33);
    float (*qs)[33] = (float(*)[33])(sm + 2 * 256 * 33);

    const int tid = threadIdx.x;
    const int tile = blockIdx.x & 7;
    const int bh = blockIdx.x >> 3;
    const int b = bh >> 3, hh = bh & 7;
    const int i0 = tile * 32;
    const float bbv = bb[hh];

    for (int idx = tid; idx < 2048; idx += 256) {
        int j = idx >> 3, q4 = idx & 7;
        const float* base = qkv + (size_t)(b * 256 + j) * 768 + hh * 32 + q4 * 4;
        float4 kk = *(const float4*)(base + 256);
        float4 vv = *(const float4*)(base + 512);
        ks[j][q4 * 4 + 0] = kk.x; ks[j][q4 * 4 + 1] = kk.y;
        ks[j][q4 * 4 + 2] = kk.z; ks[j][q4 * 4 + 3] = kk.w;
        vs[j][q4 * 4 + 0] = vv.x; vs[j][q4 * 4 + 1] = vv.y;
        vs[j][q4 * 4 + 2] = vv.z; vs[j][q4 * 4 + 3] = vv.w;
    }
    for (int idx = tid; idx < 1024; idx += 256) {
        int r = idx >> 5, d = idx & 31;
        qs[r][d] = qkv[(size_t)(b * 256 + i0 + r) * 768 + hh * 32 + d];
    }
    __syncthreads();

    const int r = tid >> 3, s = tid & 7;
    const int i = i0 + r;
    const float* brow = bias + ((((size_t)b * 8 + hh) * 256 + i) << 8);

    float sc[32];
    float mx = -1e30f;
    #pragma unroll
    for (int jj = 0; jj < 32; ++jj) {
        int j = jj * 8 + s;
        float a = 0.0f;
        #pragma unroll
        for (int d = 0; d < 32; ++d) a += qs[r][d] * ks[j][d];
        a = a * 0.17677669529663687f + brow[j] + bbv;
        sc[jj] = a;
        mx = fmaxf(mx, a);
    }
    #pragma unroll
    for (int off = 4; off; off >>= 1)
        mx = fmaxf(mx, __shfl_xor_sync(0xffffffffu, mx, off));

    float sum = 0.0f;
    #pragma unroll
    for (int jj = 0; jj < 32; ++jj) { sc[jj] = expf(sc[jj] - mx); sum += sc[jj]; }
    #pragma unroll
    for (int off = 4; off; off >>= 1)
        sum += __shfl_xor_sync(0xffffffffu, sum, off);
    float inv = 1.0f / sum;

    float oacc[32] = {};
    #pragma unroll
    for (int jj = 0; jj < 32; ++jj) {
        int j = jj * 8 + s;
        float w = sc[jj];
        #pragma unroll
        for (int d = 0; d < 32; ++d) oacc[d] += w * vs[j][d];
    }

    float w4[4];
    #pragma unroll
    for (int d = 0; d < 32; ++d) {
        float t = oacc[d];
        t += __shfl_xor_sync(0xffffffffu, t, 1);
        t += __shfl_xor_sync(0xffffffffu, t, 2);
        t += __shfl_xor_sync(0xffffffffu, t, 4);
        if ((d >> 2) == s) w4[d & 3] = t;
    }
    *(float4*)(o + ((size_t)(b * 256 + i)) * 256 + hh * 32 + s * 4) =
        make_float4(w4[0] * inv, w4[1] * inv, w4[2] * inv, w4[3] * inv);
}

// ---------------- launch ----------------
extern "C" void kernel_launch(void* const* d_in, const int* in_sizes, int n_in,
                              void* d_out, int out_size)
{
    (void)in_sizes; (void)n_in; (void)out_size;
    const float* h    = (const float*)d_in[0];
    const float* e    = (const float*)d_in[1];
    const float* We   = (const float*)d_in[2];
    const float* be   = (const float*)d_in[3];
    const float* Ws   = (const float*)d_in[4];
    const float* bs   = (const float*)d_in[5];
    const float* Wd   = (const float*)d_in[6];
    const float* bd   = (const float*)d_in[7];
    const float* Wb   = (const float*)d_in[8];
    const float* bb   = (const float*)d_in[9];
    const float* ln1g = (const float*)d_in[10];
    const float* ln1b = (const float*)d_in[11];
    const float* Wqkv = (const float*)d_in[12];
    const float* bqkv = (const float*)d_in[13];
    const float* Wo   = (const float*)d_in[14];
    const float* bo   = (const float*)d_in[15];
    const float* ln2g = (const float*)d_in[16];
    const float* ln2b = (const float*)d_in[17];
    const float* W1   = (const float*)d_in[18];
    const float* b1   = (const float*)d_in[19];
    const float* W2   = (const float*)d_in[20];
    const float* b2   = (const float*)d_in[21];

    float* out_h2 = (float*)d_out;
    float* out_e  = out_h2 + (size_t)BN * DD;

    float *pHs, *pHd, *px1, *pqkv, *pbias, *po, *ph1, *py, *pf;
    __half* pWeTh;
    cudaGetSymbolAddress((void**)&pHs,   g_Hs);
    cudaGetSymbolAddress((void**)&pHd,   g_Hd);
    cudaGetSymbolAddress((void**)&px1,   g_x1);
    cudaGetSymbolAddress((void**)&pqkv,  g_qkv);
    cudaGetSymbolAddress((void**)&pbias, g_bias);
    cudaGetSymbolAddress((void**)&po,    g_o);
    cudaGetSymbolAddress((void**)&ph1,   g_h1);
    cudaGetSymbolAddress((void**)&py,    g_y);
    cudaGetSymbolAddress((void**)&pf,    g_ffn);
    cudaGetSymbolAddress((void**)&pWeTh, g_WeTh);

    // #1-3: prep (edge kernel is launch #4 so ncu -s captures it)
    prep_wet<<<256, 256>>>(We, pWeTh);
    gemm_hsd<<<dim3(8, 16, 2), 256>>>(h, Ws, bs, Wd, bd, pHs, pHd);
    ln_kernel<<<BN, 256>>>(h, ln1g, ln1b, px1);

    // #4: edge update + attention bias
    cudaFuncSetAttribute(edge_mma_kernel,
                         cudaFuncAttributeMaxDynamicSharedMemorySize,
                         SM_EDGE_TOTAL);
    edge_mma_kernel<<<2048, 512, SM_EDGE_TOTAL>>>(
        e, pWeTh, be, pHs, pHd, Wb, out_e, pbias);

    // attention path
    gemm_t<0><<<dim3(24, 16), 256>>>(px1, Wqkv, bqkv, nullptr, pqkv, 256, 768);
    cudaFuncSetAttribute(attn_kernel,
                         cudaFuncAttributeMaxDynamicSharedMemorySize, 73728);
    attn_kernel<<<256, 256, 71808>>>(pqkv, pbias, bb, po);

    // output proj + residual
    gemm_t<0><<<dim3(8, 16), 256>>>(po, Wo, bo, h, ph1, 256, 256);

    // FFN
    ln_kernel<<<BN, 256>>>(ph1, ln2g, ln2b, py);
    gemm_t<1><<<dim3(32, 16), 256>>>(py, W1, b1, nullptr, pf, 256, 1024);
    gemm_t<0><<<dim3(8, 16), 256>>>(pf, W2, b2, ph1, out_h2, 1024, 256);
}

// round 7
// speedup vs baseline: 3.1858x; 1.1227x over previous
#include <cuda_runtime.h>
#include <cuda_fp16.h>
#include <math.h>
#include <stdint.h>

// Shapes (fixed): B=4, N=256, D=256, H=8, HD=32, DFF=1024
#define BN 1024
#define DD 256

// ---------------- scratch ----------------
__device__ __align__(16) float  g_Hs[BN * DD];
__device__ __align__(16) __half g_Hdh[BN * DD];
__device__ __align__(16) float  g_x1[BN * DD];
__device__ __align__(16) float  g_qkv[BN * 768];
__device__ __align__(16) float  g_bias[4 * 8 * 256 * 256];
__device__ __align__(16) float  g_o[BN * DD];
__device__ __align__(16) float  g_h1[BN * DD];
__device__ __align__(16) float  g_y[BN * DD];
__device__ __align__(16) float  g_ffn[BN * 1024];
__device__ __align__(16) __half g_WeTh[DD * DD];
__device__ __align__(16) __half g_WqkvTh[768 * DD];
__device__ __align__(16) __half g_WoTh[DD * DD];
__device__ __align__(16) __half g_W1Th[1024 * DD];
__device__ __align__(16) __half g_W2Th[DD * 1024];

// ---------------- helpers ----------------
__device__ __forceinline__ uint32_t smem_u32(const void* p) {
    uint32_t a;
    asm("{ .reg .u64 t; cvta.to.shared.u64 t, %1; cvt.u32.u64 %0, t; }"
        : "=r"(a) : "l"(p));
    return a;
}
__device__ __forceinline__ void cp16(uint32_t dst, const void* src) {
    asm volatile("cp.async.cg.shared.global [%0], [%1], 16;"
                 :: "r"(dst), "l"(src));
}
__device__ __forceinline__ void ldmx4(uint32_t* r, uint32_t addr) {
    asm volatile(
        "ldmatrix.sync.aligned.m8n8.x4.shared.b16 {%0,%1,%2,%3}, [%4];"
        : "=r"(r[0]), "=r"(r[1]), "=r"(r[2]), "=r"(r[3]) : "r"(addr));
}
__device__ __forceinline__ void mma_f16(float* c, const uint32_t* a,
                                        uint32_t b0, uint32_t b1) {
    asm volatile(
        "mma.sync.aligned.m16n8k16.row.col.f32.f16.f16.f32 "
        "{%0,%1,%2,%3}, {%4,%5,%6,%7}, {%8,%9}, {%0,%1,%2,%3};"
        : "+f"(c[0]), "+f"(c[1]), "+f"(c[2]), "+f"(c[3])
        : "r"(a[0]), "r"(a[1]), "r"(a[2]), "r"(a[3]), "r"(b0), "r"(b1));
}
__device__ __forceinline__ uint32_t pack_h2(float x, float y) {
    __half2 h = __float22half2_rn(make_float2(x, y));
    return *reinterpret_cast<uint32_t*>(&h);
}
__device__ __forceinline__ float gelu_exact(float x) {
    return 0.5f * x * (1.0f + erff(x * 0.70710678118654752f));
}

// ---------------- weight transpose+fp16: out[n][k] = in[k][n] ------------
__global__ __launch_bounds__(256) void transpose_h(
    const float* __restrict__ in, __half* __restrict__ out, int K, int N) {
    int n = blockIdx.x;
    for (int k = threadIdx.x; k < K; k += 256)
        out[(size_t)n * K + k] = __float2half_rn(in[(size_t)k * N + n]);
}

// ---------------- dual GEMM for Hs/Hd (Hs fp32 with +be, Hd fp16) -------
__global__ __launch_bounds__(256) void gemm_hsd(
    const float* __restrict__ A,
    const float* __restrict__ Ws, const float* __restrict__ bs,
    const float* __restrict__ Wd, const float* __restrict__ bd,
    const float* __restrict__ be,
    float* __restrict__ oHs, __half* __restrict__ oHdh)
{
    const float* W    = blockIdx.z ? Wd : Ws;
    const float* bias = blockIdx.z ? bd : bs;

    __shared__ float As[64][16];
    __shared__ float Bs[16][32];
    const int tid = threadIdx.x;
    const int m0 = blockIdx.y * 64;
    const int c0 = blockIdx.x * 32;
    const int ty = tid >> 3;
    const int tx = tid & 7;

    float acc[2][4] = {};

    for (int k0 = 0; k0 < 256; k0 += 16) {
        {
            int r = tid >> 2, q = tid & 3;
            *(float4*)&As[r][q * 4] =
                *(const float4*)(A + (size_t)(m0 + r) * 256 + k0 + q * 4);
        }
        if (tid < 128) {
            int kk = tid >> 3, q = tid & 7;
            *(float4*)&Bs[kk][q * 4] =
                *(const float4*)(W + (size_t)(k0 + kk) * 256 + c0 + q * 4);
        }
        __syncthreads();
        #pragma unroll
        for (int k = 0; k < 16; ++k) {
            float a0 = As[ty * 2][k];
            float a1 = As[ty * 2 + 1][k];
            float4 bv = *(float4*)&Bs[k][tx * 4];
            acc[0][0] += a0 * bv.x; acc[0][1] += a0 * bv.y;
            acc[0][2] += a0 * bv.z; acc[0][3] += a0 * bv.w;
            acc[1][0] += a1 * bv.x; acc[1][1] += a1 * bv.y;
            acc[1][2] += a1 * bv.z; acc[1][3] += a1 * bv.w;
        }
        __syncthreads();
    }

    float4 bs4 = *(const float4*)(bias + c0 + tx * 4);
    if (blockIdx.z == 0) {
        float4 be4 = *(const float4*)(be + c0 + tx * 4);
        bs4.x += be4.x; bs4.y += be4.y; bs4.z += be4.z; bs4.w += be4.w;
    }
    #pragma unroll
    for (int r = 0; r < 2; ++r) {
        int m = m0 + ty * 2 + r;
        float v0 = acc[r][0] + bs4.x, v1 = acc[r][1] + bs4.y;
        float v2 = acc[r][2] + bs4.z, v3 = acc[r][3] + bs4.w;
        if (blockIdx.z == 0) {
            *(float4*)(oHs + (size_t)m * 256 + c0 + tx * 4) =
                make_float4(v0, v1, v2, v3);
        } else {
            __half2* o2 = (__half2*)(oHdh + (size_t)m * 256 + c0 + tx * 4);
            o2[0] = __float22half2_rn(make_float2(v0, v1));
            o2[1] = __float22half2_rn(make_float2(v2, v3));
        }
    }
}

// ---------------- edge kernel: fp16 mma, 128x256 tile, 512 thr ----------
#define SB_B     0          // 256 rows * 512B = 128KB (full WeT)
#define SB_A     131072     // 2 stages * 16KB
#define SB_HD    163840     // 128 rows * 528B = 67584 (fp16 Hd tile)
#define SM_EDGE_TOTAL 231424

__global__ __launch_bounds__(512, 1) void edge_mma_kernel(
    const float* __restrict__ e, const __half* __restrict__ WeTh,
    const float* __restrict__ Hs, const __half* __restrict__ Hdh,
    const float* __restrict__ Wb,
    float* __restrict__ e_new, float* __restrict__ bias)
{
    extern __shared__ char smem[];
    const uint32_t sb = smem_u32(smem);
    float* sbias = (float*)(smem + SB_A);   // overlays A stage0 (free in epilogue)

    const int tid = threadIdx.x;
    const int w = tid >> 5, lane = tid & 31;
    const int g = lane >> 2, tig = lane & 3, x7 = lane & 7;
    const int wr = w >> 2, wc = w & 3;

    const int m0 = blockIdx.x * 128;
    const int b = m0 >> 16, i = (m0 >> 8) & 255, j0 = m0 & 255;

    // ---- B (full WeT) + Hd tile via cp.async ----
    {
        const int ch = tid & 31;
        const int rbase = tid >> 5;
        #pragma unroll
        for (int it = 0; it < 16; ++it) {
            int row = rbase + it * 16;
            cp16(sb + SB_B + row * 512 + ((ch ^ (row & 7)) << 4),
                 WeTh + (size_t)row * 256 + ch * 8);
        }
        #pragma unroll
        for (int p = 0; p < 8; ++p) {
            int idx = tid + p * 512;
            int r = idx >> 5, c2 = idx & 31;
            cp16(sb + SB_HD + r * 528 + c2 * 16,
                 Hdh + (((size_t)(b * 256 + j0 + r)) << 8) + c2 * 8);
        }
    }
    asm volatile("cp.async.commit_group;");

    // ---- A chunk 0: LDG fp32 -> fp16 STS ----
    const float* Ab = e + (size_t)m0 * 256;
    const int seg = tid & 7;
    #pragma unroll
    for (int it = 0; it < 2; ++it) {
        int row = (tid >> 3) + it * 64;
        const float* p = Ab + (size_t)row * 256 + seg * 8;
        float4 v0 = *(const float4*)p;
        float4 v1 = *(const float4*)(p + 4);
        uint4 u = make_uint4(pack_h2(v0.x, v0.y), pack_h2(v0.z, v0.w),
                             pack_h2(v1.x, v1.y), pack_h2(v1.z, v1.w));
        *(uint4*)(smem + SB_A + row * 128 + ((seg ^ (row & 7)) << 4)) = u;
    }

    // ---- per-warp Wb B-fragments (registers) ----
    uint32_t bw0[4], bw1[4];
    #pragma unroll
    for (int kc = 0; kc < 4; ++kc) {
        int k0 = wc * 64 + kc * 16 + 2 * tig;
        bw0[kc] = pack_h2(Wb[(k0    ) * 8 + g], Wb[(k0 + 1) * 8 + g]);
        bw1[kc] = pack_h2(Wb[(k0 + 8) * 8 + g], Wb[(k0 + 9) * 8 + g]);
    }

    asm volatile("cp.async.wait_group 0;" ::: "memory");
    __syncthreads();

    const int rowoffA = x7 + (((lane >> 3) & 1) << 3);
    const int selA = lane >> 4;
    const int rowoffB = x7 + ((lane >> 4) << 3);
    const int selB = (lane >> 3) & 1;

    float acc[2][8][4] = {};
    float4 pre[4];

    for (int c = 0; c < 4; ++c) {
        if (c < 3) {
            #pragma unroll
            for (int it = 0; it < 2; ++it) {
                int row = (tid >> 3) + it * 64;
                const float* p =
                    Ab + (size_t)row * 256 + (c + 1) * 64 + seg * 8;
                pre[it * 2]     = *(const float4*)p;
                pre[it * 2 + 1] = *(const float4*)(p + 4);
            }
        }
        const uint32_t sAc = sb + SB_A + (c & 1) * 16384;
        #pragma unroll
        for (int kk = 0; kk < 4; ++kk) {
            uint32_t a0[4], a1[4];
            {
                int rowA = wr * 32 + rowoffA;
                ldmx4(a0, sAc + rowA * 128 + ((((kk << 1) + selA) ^ x7) << 4));
                ldmx4(a1, sAc + (rowA + 16) * 128 +
                              ((((kk << 1) + selA) ^ x7) << 4));
            }
            uint32_t bf[4][4];
            #pragma unroll
            for (int nt2 = 0; nt2 < 4; ++nt2) {
                int rowB = wc * 64 + nt2 * 16 + rowoffB;
                ldmx4(bf[nt2], sb + SB_B + rowB * 512 +
                               (((c * 8 + (kk << 1) + selB) ^ x7) << 4));
            }
            #pragma unroll
            for (int nt2 = 0; nt2 < 4; ++nt2) {
                mma_f16(acc[0][nt2 * 2],     a0, bf[nt2][0], bf[nt2][1]);
                mma_f16(acc[0][nt2 * 2 + 1], a0, bf[nt2][2], bf[nt2][3]);
                mma_f16(acc[1][nt2 * 2],     a1, bf[nt2][0], bf[nt2][1]);
                mma_f16(acc[1][nt2 * 2 + 1], a1, bf[nt2][2], bf[nt2][3]);
            }
        }
        __syncthreads();
        if (c < 3) {
            char* dst = smem + SB_A + ((c + 1) & 1) * 16384;
            #pragma unroll
            for (int it = 0; it < 2; ++it) {
                int row = (tid >> 3) + it * 64;
                float4 v0 = pre[it * 2], v1 = pre[it * 2 + 1];
                uint4 u = make_uint4(pack_h2(v0.x, v0.y), pack_h2(v0.z, v0.w),
                                     pack_h2(v1.x, v1.y), pack_h2(v1.z, v1.w));
                *(uint4*)(dst + row * 128 + ((seg ^ (row & 7)) << 4)) = u;
            }
            __syncthreads();
        }
    }

    // ---- epilogue: +Hs +Hd(smem fp16), ReLU, store e_new, bias via mma --
    const float* hsrow = Hs + (((size_t)(b << 8) + i) << 8);
    const char* hdb = smem + SB_HD;
    float bc[2][4] = {};
    #pragma unroll
    for (int mt = 0; mt < 2; ++mt) {
        const int rl = wr * 32 + mt * 16 + g;
        float* er0 = e_new + ((size_t)(m0 + rl)) * 256;
        float* er1 = er0 + 8 * 256;
        uint32_t afr[4];
        #pragma unroll
        for (int nt = 0; nt < 8; ++nt) {
            const int cl = wc * 64 + nt * 8 + 2 * tig;
            float2 hs = *(const float2*)(hsrow + cl);
            float2 h0 = __half22float2(*(const __half2*)(hdb + rl * 528 + cl * 2));
            float2 h1 = __half22float2(*(const __half2*)(hdb + (rl + 8) * 528 + cl * 2));
            float x0 = fmaxf(acc[mt][nt][0] + hs.x + h0.x, 0.0f);
            float x1 = fmaxf(acc[mt][nt][1] + hs.y + h0.y, 0.0f);
            float x2 = fmaxf(acc[mt][nt][2] + hs.x + h1.x, 0.0f);
            float x3 = fmaxf(acc[mt][nt][3] + hs.y + h1.y, 0.0f);
            *(float2*)(er0 + cl) = make_float2(x0, x1);
            *(float2*)(er1 + cl) = make_float2(x2, x3);
            if ((nt & 1) == 0) {
                afr[0] = pack_h2(x0, x1);
                afr[1] = pack_h2(x2, x3);
            } else {
                afr[2] = pack_h2(x0, x1);
                afr[3] = pack_h2(x2, x3);
                mma_f16(bc[mt], afr, bw0[nt >> 1], bw1[nt >> 1]);
            }
        }
    }
    {
        float* sbw = sbias + wc * 1024;
        #pragma unroll
        for (int mt = 0; mt < 2; ++mt) {
            int rl = wr * 32 + mt * 16 + g;
            sbw[rl * 8 + 2 * tig]           = bc[mt][0];
            sbw[rl * 8 + 2 * tig + 1]       = bc[mt][1];
            sbw[(rl + 8) * 8 + 2 * tig]     = bc[mt][2];
            sbw[(rl + 8) * 8 + 2 * tig + 1] = bc[mt][3];
        }
    }
    __syncthreads();
    #pragma unroll
    for (int q = 0; q < 2; ++q) {
        int t = tid + q * 512;
        int r = t & 127, hh = t >> 7;
        float v = sbias[r * 8 + hh] + sbias[1024 + r * 8 + hh] +
                  sbias[2048 + r * 8 + hh] + sbias[3072 + r * 8 + hh];
        bias[((((size_t)b * 8 + hh) * 256 + i) << 8) + j0 + r] = v;
    }
}

// ---------------- generic fp16 MMA GEMM: 128x64 tile, 256 thr ----------
// A fp32 [M,K], Wh fp16 [N,K] (n-major), out = op(A@Wh^T + bias) [+res]
template <int OP, bool RES>
__global__ __launch_bounds__(256) void gemm_mma(
    const float* __restrict__ A, const __half* __restrict__ Wh,
    const float* __restrict__ bias, const float* __restrict__ res,
    float* __restrict__ out, int K, int N)
{
    extern __shared__ char sm2[];
    const uint32_t sb = smem_u32(sm2);
    const int tid = threadIdx.x;
    const int w = tid >> 5, lane = tid & 31;
    const int g = lane >> 2, tig = lane & 3, x7 = lane & 7;
    const int wr = w >> 1, wc = w & 1;
    const int m0 = blockIdx.y * 128, n0 = blockIdx.x * 64;
    const int NC = K >> 6;

    const float*  Ab = A + (size_t)m0 * K;
    const __half* Bb = Wh + (size_t)n0 * K;
    const int seg = tid & 7;

    // B chunk 0
    #pragma unroll
    for (int p = 0; p < 2; ++p) {
        int idx = tid + p * 256;
        int r = idx >> 3, ch = idx & 7;
        cp16(sb + 32768 + r * 128 + ((ch ^ (r & 7)) << 4),
             Bb + (size_t)r * K + ch * 8);
    }
    asm volatile("cp.async.commit_group;");
    // A chunk 0
    #pragma unroll
    for (int it = 0; it < 4; ++it) {
        int row = (tid >> 3) + it * 32;
        const float* p = Ab + (size_t)row * K + seg * 8;
        float4 v0 = *(const float4*)p;
        float4 v1 = *(const float4*)(p + 4);
        uint4 u = make_uint4(pack_h2(v0.x, v0.y), pack_h2(v0.z, v0.w),
                             pack_h2(v1.x, v1.y), pack_h2(v1.z, v1.w));
        *(uint4*)(sm2 + row * 128 + ((seg ^ (row & 7)) << 4)) = u;
    }
    asm volatile("cp.async.wait_group 0;" ::: "memory");
    __syncthreads();

    const int rowoffA = x7 + (((lane >> 3) & 1) << 3);
    const int selA = lane >> 4;
    const int rowoffB = x7 + ((lane >> 4) << 3);
    const int selB = (lane >> 3) & 1;

    float acc[2][4][4] = {};
    float4 pre[8];

    for (int c = 0; c < NC; ++c) {
        if (c + 1 < NC) {
            #pragma unroll
            for (int p = 0; p < 2; ++p) {
                int idx = tid + p * 256;
                int r = idx >> 3, ch = idx & 7;
                cp16(sb + 32768 + (((c + 1) & 1) << 13) + r * 128 +
                         ((ch ^ (r & 7)) << 4),
                     Bb + (size_t)r * K + (c + 1) * 64 + ch * 8);
            }
            asm volatile("cp.async.commit_group;");
            #pragma unroll
            for (int it = 0; it < 4; ++it) {
                int row = (tid >> 3) + it * 32;
                const float* p = Ab + (size_t)row * K + (c + 1) * 64 + seg * 8;
                pre[it * 2]     = *(const float4*)p;
                pre[it * 2 + 1] = *(const float4*)(p + 4);
            }
        }
        const uint32_t sA = sb + ((c & 1) << 14);
        const uint32_t sB = sb + 32768 + ((c & 1) << 13);
        #pragma unroll
        for (int kk = 0; kk < 4; ++kk) {
            uint32_t a0[4], a1[4];
            int rA = wr * 32 + rowoffA;
            ldmx4(a0, sA + rA * 128 + ((((kk << 1) + selA) ^ x7) << 4));
            ldmx4(a1, sA + (rA + 16) * 128 + ((((kk << 1) + selA) ^ x7) << 4));
            uint32_t bf[2][4];
            #pragma unroll
            for (int nt2 = 0; nt2 < 2; ++nt2) {
                int rB = wc * 32 + nt2 * 16 + rowoffB;
                ldmx4(bf[nt2], sB + rB * 128 + ((((kk << 1) + selB) ^ x7) << 4));
            }
            #pragma unroll
            for (int nt2 = 0; nt2 < 2; ++nt2) {
                mma_f16(acc[0][nt2 * 2],     a0, bf[nt2][0], bf[nt2][1]);
                mma_f16(acc[0][nt2 * 2 + 1], a0, bf[nt2][2], bf[nt2][3]);
                mma_f16(acc[1][nt2 * 2],     a1, bf[nt2][0], bf[nt2][1]);
                mma_f16(acc[1][nt2 * 2 + 1], a1, bf[nt2][2], bf[nt2][3]);
            }
        }
        __syncthreads();
        if (c + 1 < NC) {
            char* dst = sm2 + (((c + 1) & 1) << 14);
            #pragma unroll
            for (int it = 0; it < 4; ++it) {
                int row = (tid >> 3) + it * 32;
                float4 v0 = pre[it * 2], v1 = pre[it * 2 + 1];
                uint4 u = make_uint4(pack_h2(v0.x, v0.y), pack_h2(v0.z, v0.w),
                                     pack_h2(v1.x, v1.y), pack_h2(v1.z, v1.w));
                *(uint4*)(dst + row * 128 + ((seg ^ (row & 7)) << 4)) = u;
            }
            asm volatile("cp.async.wait_group 0;" ::: "memory");
            __syncthreads();
        }
    }

    // epilogue
    #pragma unroll
    for (int mt = 0; mt < 2; ++mt) {
        #pragma unroll
        for (int rh = 0; rh < 2; ++rh) {
            int rl = wr * 32 + mt * 16 + rh * 8 + g;
            float* orow = out + (size_t)(m0 + rl) * N + n0;
            const float* rrow = RES ? res + (size_t)(m0 + rl) * N + n0 : nullptr;
            #pragma unroll
            for (int nt = 0; nt < 4; ++nt) {
                int cl = wc * 32 + nt * 8 + 2 * tig;
                float x0 = acc[mt][nt][rh * 2 + 0] + __ldg(bias + n0 + cl);
                float x1 = acc[mt][nt][rh * 2 + 1] + __ldg(bias + n0 + cl + 1);
                if (OP == 1) { x0 = gelu_exact(x0); x1 = gelu_exact(x1); }
                if (RES) {
                    float2 rv = *(const float2*)(rrow + cl);
                    x0 += rv.x; x1 += rv.y;
                }
                *(float2*)(orow + cl) = make_float2(x0, x1);
            }
        }
    }
}

// ---------------- LayerNorm ----------------
__global__ __launch_bounds__(256) void ln_kernel(
    const float* __restrict__ in, const float* __restrict__ g,
    const float* __restrict__ b, float* __restrict__ out)
{
    int row = blockIdx.x;
    int t = threadIdx.x;
    float v = in[(size_t)row * 256 + t];
    __shared__ float red[8];

    float s = v;
    #pragma unroll
    for (int o = 16; o; o >>= 1) s += __shfl_xor_sync(0xffffffffu, s, o);
    if ((t & 31) == 0) red[t >> 5] = s;
    __syncthreads();
    float mean = (red[0] + red[1] + red[2] + red[3] +
                  red[4] + red[5] + red[6] + red[7]) * (1.0f / 256.0f);
    float d = v - mean;
    __syncthreads();
    s = d * d;
    #pragma unroll
    for (int o = 16; o; o >>= 1) s += __shfl_xor_sync(0xffffffffu, s, o);
    if ((t & 31) == 0) red[t >> 5] = s;
    __syncthreads();
    float var = (red[0] + red[1] + red[2] + red[3] +
                 red[4] + red[5] + red[6] + red[7]) * (1.0f / 256.0f);
    out[(size_t)row * 256 + t] = d * rsqrtf(var + 1e-5f) * g[t] + b[t];
}

// ---------------- attention kernel ----------------
__global__ __launch_bounds__(256) void attn_kernel(
    const float* __restrict__ qkv, const float* __restrict__ bias,
    const float* __restrict__ bb, float* __restrict__ o)
{
    extern __shared__ float sm[];
    float (*ks)[33] = (float(*)[33])sm;
    float (*vs)[33] = (float(*)[33])(sm + 256 * 33);
    float (*qs)[33] = (float(*)[33])(sm + 2 * 256 * 33);

    const int tid = threadIdx.x;
    const int tile = blockIdx.x & 7;
    const int bh = blockIdx.x >> 3;
    const int b = bh >> 3, hh = bh & 7;
    const int i0 = tile * 32;
    const float bbv = bb[hh];

    for (int idx = tid; idx < 2048; idx += 256) {
        int j = idx >> 3, q4 = idx & 7;
        const float* base = qkv + (size_t)(b * 256 + j) * 768 + hh * 32 + q4 * 4;
        float4 kk = *(const float4*)(base + 256);
        float4 vv = *(const float4*)(base + 512);
        ks[j][q4 * 4 + 0] = kk.x; ks[j][q4 * 4 + 1] = kk.y;
        ks[j][q4 * 4 + 2] = kk.z; ks[j][q4 * 4 + 3] = kk.w;
        vs[j][q4 * 4 + 0] = vv.x; vs[j][q4 * 4 + 1] = vv.y;
        vs[j][q4 * 4 + 2] = vv.z; vs[j][q4 * 4 + 3] = vv.w;
    }
    for (int idx = tid; idx < 1024; idx += 256) {
        int r = idx >> 5, d = idx & 31;
        qs[r][d] = qkv[(size_t)(b * 256 + i0 + r) * 768 + hh * 32 + d];
    }
    __syncthreads();

    const int r = tid >> 3, s = tid & 7;
    const int i = i0 + r;
    const float* brow = bias + ((((size_t)b * 8 + hh) * 256 + i) << 8);

    float sc[32];
    float mx = -1e30f;
    #pragma unroll
    for (int jj = 0; jj < 32; ++jj) {
        int j = jj * 8 + s;
        float a = 0.0f;
        #pragma unroll
        for (int d = 0; d < 32; ++d) a += qs[r][d] * ks[j][d];
        a = a * 0.17677669529663687f + brow[j] + bbv;
        sc[jj] = a;
        mx = fmaxf(mx, a);
    }
    #pragma unroll
    for (int off = 4; off; off >>= 1)
        mx = fmaxf(mx, __shfl_xor_sync(0xffffffffu, mx, off));

    float sum = 0.0f;
    #pragma unroll
    for (int jj = 0; jj < 32; ++jj) { sc[jj] = expf(sc[jj] - mx); sum += sc[jj]; }
    #pragma unroll
    for (int off = 4; off; off >>= 1)
        sum += __shfl_xor_sync(0xffffffffu, sum, off);
    float inv = 1.0f / sum;

    float oacc[32] = {};
    #pragma unroll
    for (int jj = 0; jj < 32; ++jj) {
        int j = jj * 8 + s;
        float w = sc[jj];
        #pragma unroll
        for (int d = 0; d < 32; ++d) oacc[d] += w * vs[j][d];
    }

    float w4[4];
    #pragma unroll
    for (int d = 0; d < 32; ++d) {
        float t = oacc[d];
        t += __shfl_xor_sync(0xffffffffu, t, 1);
        t += __shfl_xor_sync(0xffffffffu, t, 2);
        t += __shfl_xor_sync(0xffffffffu, t, 4);
        if ((d >> 2) == s) w4[d & 3] = t;
    }
    *(float4*)(o + ((size_t)(b * 256 + i)) * 256 + hh * 32 + s * 4) =
        make_float4(w4[0] * inv, w4[1] * inv, w4[2] * inv, w4[3] * inv);
}

// ---------------- launch ----------------
extern "C" void kernel_launch(void* const* d_in, const int* in_sizes, int n_in,
                              void* d_out, int out_size)
{
    (void)in_sizes; (void)n_in; (void)out_size;
    const float* h    = (const float*)d_in[0];
    const float* e    = (const float*)d_in[1];
    const float* We   = (const float*)d_in[2];
    const float* be   = (const float*)d_in[3];
    const float* Ws   = (const float*)d_in[4];
    const float* bs   = (const float*)d_in[5];
    const float* Wd   = (const float*)d_in[6];
    const float* bd   = (const float*)d_in[7];
    const float* Wb   = (const float*)d_in[8];
    const float* bb   = (const float*)d_in[9];
    const float* ln1g = (const float*)d_in[10];
    const float* ln1b = (const float*)d_in[11];
    const float* Wqkv = (const float*)d_in[12];
    const float* bqkv = (const float*)d_in[13];
    const float* Wo   = (const float*)d_in[14];
    const float* bo   = (const float*)d_in[15];
    const float* ln2g = (const float*)d_in[16];
    const float* ln2b = (const float*)d_in[17];
    const float* W1   = (const float*)d_in[18];
    const float* b1   = (const float*)d_in[19];
    const float* W2   = (const float*)d_in[20];
    const float* b2   = (const float*)d_in[21];

    float* out_h2 = (float*)d_out;
    float* out_e  = out_h2 + (size_t)BN * DD;

    float *pHs, *px1, *pqkv, *pbias, *po, *ph1, *py, *pf;
    __half *pHdh, *pWeTh, *pWqkvTh, *pWoTh, *pW1Th, *pW2Th;
    cudaGetSymbolAddress((void**)&pHs,     g_Hs);
    cudaGetSymbolAddress((void**)&pHdh,    g_Hdh);
    cudaGetSymbolAddress((void**)&px1,     g_x1);
    cudaGetSymbolAddress((void**)&pqkv,    g_qkv);
    cudaGetSymbolAddress((void**)&pbias,   g_bias);
    cudaGetSymbolAddress((void**)&po,      g_o);
    cudaGetSymbolAddress((void**)&ph1,     g_h1);
    cudaGetSymbolAddress((void**)&py,      g_y);
    cudaGetSymbolAddress((void**)&pf,      g_ffn);
    cudaGetSymbolAddress((void**)&pWeTh,   g_WeTh);
    cudaGetSymbolAddress((void**)&pWqkvTh, g_WqkvTh);
    cudaGetSymbolAddress((void**)&pWoTh,   g_WoTh);
    cudaGetSymbolAddress((void**)&pW1Th,   g_W1Th);
    cudaGetSymbolAddress((void**)&pW2Th,   g_W2Th);

    // #1-3: prep (edge kernel is launch #4 so ncu -s captures it)
    transpose_h<<<256, 256>>>(We, pWeTh, 256, 256);
    gemm_hsd<<<dim3(8, 16, 2), 256>>>(h, Ws, bs, Wd, bd, be, pHs, pHdh);
    ln_kernel<<<BN, 256>>>(h, ln1g, ln1b, px1);

    // #4: edge update + attention bias
    cudaFuncSetAttribute(edge_mma_kernel,
                         cudaFuncAttributeMaxDynamicSharedMemorySize,
                         SM_EDGE_TOTAL);
    edge_mma_kernel<<<2048, 512, SM_EDGE_TOTAL>>>(
        e, pWeTh, pHs, pHdh, Wb, out_e, pbias);

    // weight transposes for mma gemms
    transpose_h<<<768, 256>>>(Wqkv, pWqkvTh, 256, 768);
    transpose_h<<<256, 256>>>(Wo, pWoTh, 256, 256);
    transpose_h<<<1024, 256>>>(W1, pW1Th, 256, 1024);
    transpose_h<<<256, 256>>>(W2, pW2Th, 1024, 256);

    cudaFuncSetAttribute(gemm_mma<0, false>,
                         cudaFuncAttributeMaxDynamicSharedMemorySize, 49152);
    cudaFuncSetAttribute(gemm_mma<0, true>,
                         cudaFuncAttributeMaxDynamicSharedMemorySize, 49152);
    cudaFuncSetAttribute(gemm_mma<1, false>,
                         cudaFuncAttributeMaxDynamicSharedMemorySize, 49152);

    // attention path
    gemm_mma<0, false><<<dim3(12, 8), 256, 49152>>>(
        px1, pWqkvTh, bqkv, nullptr, pqkv, 256, 768);
    cudaFuncSetAttribute(attn_kernel,
                         cudaFuncAttributeMaxDynamicSharedMemorySize, 73728);
    attn_kernel<<<256, 256, 71808>>>(pqkv, pbias, bb, po);

    // output proj + residual
    gemm_mma<0, true><<<dim3(4, 8), 256, 49152>>>(
        po, pWoTh, bo, h, ph1, 256, 256);

    // FFN
    ln_kernel<<<BN, 256>>>(ph1, ln2g, ln2b, py);
    gemm_mma<1, false><<<dim3(16, 8), 256, 49152>>>(
        py, pW1Th, b1, nullptr, pf, 256, 1024);
    gemm_mma<0, true><<<dim3(4, 8), 256, 49152>>>(
        pf, pW2Th, b2, ph1, out_h2, 1024, 256);
}

// round 8
// speedup vs baseline: 3.7572x; 1.1794x over previous
#include <cuda_runtime.h>
#include <cuda_fp16.h>
#include <math.h>
#include <stdint.h>

// Shapes (fixed): B=4, N=256, D=256, H=8, HD=32, DFF=1024
#define BN 1024
#define DD 256

// ---------------- scratch ----------------
__device__ __align__(16) float  g_Hs[BN * DD];    // Hs + be
__device__ __align__(16) float  g_Hd[BN * DD];
__device__ __align__(16) float  g_x1[BN * DD];
__device__ __align__(16) float  g_qkv[BN * 768];
__device__ __align__(16) float  g_bias[4 * 8 * 256 * 256];
__device__ __align__(16) float  g_o[BN * DD];
__device__ __align__(16) float  g_h1[BN * DD];
__device__ __align__(16) float  g_y[BN * DD];
__device__ __align__(16) float  g_ffn[BN * 1024];
__device__ __align__(16) __half g_WeTh[DD * DD];
__device__ __align__(16) __half g_WqkvTh[768 * DD];
__device__ __align__(16) __half g_WoTh[DD * DD];
__device__ __align__(16) __half g_W1Th[1024 * DD];
__device__ __align__(16) __half g_W2Th[DD * 1024];

// ---------------- helpers ----------------
__device__ __forceinline__ uint32_t smem_u32(const void* p) {
    uint32_t a;
    asm("{ .reg .u64 t; cvta.to.shared.u64 t, %1; cvt.u32.u64 %0, t; }"
        : "=r"(a) : "l"(p));
    return a;
}
__device__ __forceinline__ void cp16(uint32_t dst, const void* src) {
    asm volatile("cp.async.cg.shared.global [%0], [%1], 16;"
                 :: "r"(dst), "l"(src));
}
__device__ __forceinline__ void ldmx4(uint32_t* r, uint32_t addr) {
    asm volatile(
        "ldmatrix.sync.aligned.m8n8.x4.shared.b16 {%0,%1,%2,%3}, [%4];"
        : "=r"(r[0]), "=r"(r[1]), "=r"(r[2]), "=r"(r[3]) : "r"(addr));
}
__device__ __forceinline__ void mma_f16(float* c, const uint32_t* a,
                                        uint32_t b0, uint32_t b1) {
    asm volatile(
        "mma.sync.aligned.m16n8k16.row.col.f32.f16.f16.f32 "
        "{%0,%1,%2,%3}, {%4,%5,%6,%7}, {%8,%9}, {%0,%1,%2,%3};"
        : "+f"(c[0]), "+f"(c[1]), "+f"(c[2]), "+f"(c[3])
        : "r"(a[0]), "r"(a[1]), "r"(a[2]), "r"(a[3]), "r"(b0), "r"(b1));
}
__device__ __forceinline__ uint32_t pack_h2(float x, float y) {
    __half2 h = __float22half2_rn(make_float2(x, y));
    return *reinterpret_cast<uint32_t*>(&h);
}
__device__ __forceinline__ float gelu_exact(float x) {
    return 0.5f * x * (1.0f + erff(x * 0.70710678118654752f));
}

// ---------------- merged weight transpose+fp16 ----------------
__global__ __launch_bounds__(256) void transpose_all(
    const float* __restrict__ We,  const float* __restrict__ Wqkv,
    const float* __restrict__ Wo,  const float* __restrict__ W1,
    const float* __restrict__ W2,
    __half* __restrict__ oWe,  __half* __restrict__ oWqkv,
    __half* __restrict__ oWo,  __half* __restrict__ oW1,
    __half* __restrict__ oW2)
{
    int bid = blockIdx.x;
    const float* in; __half* out; int K, N, n;
    if (bid < 256)        { in = We;   out = oWe;   K = 256;  N = 256;  n = bid; }
    else if (bid < 1024)  { in = Wqkv; out = oWqkv; K = 256;  N = 768;  n = bid - 256; }
    else if (bid < 1280)  { in = Wo;   out = oWo;   K = 256;  N = 256;  n = bid - 1024; }
    else if (bid < 2304)  { in = W1;   out = oW1;   K = 256;  N = 1024; n = bid - 1280; }
    else                  { in = W2;   out = oW2;   K = 1024; N = 256;  n = bid - 2304; }
    for (int k = threadIdx.x; k < K; k += 256)
        out[(size_t)n * K + k] = __float2half_rn(in[(size_t)k * N + n]);
}

// ---------------- dual GEMM: Hs(+be) and Hd, both fp32 ----------------
__global__ __launch_bounds__(256) void gemm_hsd(
    const float* __restrict__ A,
    const float* __restrict__ Ws, const float* __restrict__ bs,
    const float* __restrict__ Wd, const float* __restrict__ bd,
    const float* __restrict__ be,
    float* __restrict__ oHs, float* __restrict__ oHd)
{
    const float* W    = blockIdx.z ? Wd : Ws;
    const float* bias = blockIdx.z ? bd : bs;
    float* out        = blockIdx.z ? oHd : oHs;

    __shared__ float As[64][16];
    __shared__ float Bs[16][32];
    const int tid = threadIdx.x;
    const int m0 = blockIdx.y * 64;
    const int c0 = blockIdx.x * 32;
    const int ty = tid >> 3;
    const int tx = tid & 7;

    float acc[2][4] = {};

    for (int k0 = 0; k0 < 256; k0 += 16) {
        {
            int r = tid >> 2, q = tid & 3;
            *(float4*)&As[r][q * 4] =
                *(const float4*)(A + (size_t)(m0 + r) * 256 + k0 + q * 4);
        }
        if (tid < 128) {
            int kk = tid >> 3, q = tid & 7;
            *(float4*)&Bs[kk][q * 4] =
                *(const float4*)(W + (size_t)(k0 + kk) * 256 + c0 + q * 4);
        }
        __syncthreads();
        #pragma unroll
        for (int k = 0; k < 16; ++k) {
            float a0 = As[ty * 2][k];
            float a1 = As[ty * 2 + 1][k];
            float4 bv = *(float4*)&Bs[k][tx * 4];
            acc[0][0] += a0 * bv.x; acc[0][1] += a0 * bv.y;
            acc[0][2] += a0 * bv.z; acc[0][3] += a0 * bv.w;
            acc[1][0] += a1 * bv.x; acc[1][1] += a1 * bv.y;
            acc[1][2] += a1 * bv.z; acc[1][3] += a1 * bv.w;
        }
        __syncthreads();
    }

    float4 bs4 = *(const float4*)(bias + c0 + tx * 4);
    if (blockIdx.z == 0) {
        float4 be4 = *(const float4*)(be + c0 + tx * 4);
        bs4.x += be4.x; bs4.y += be4.y; bs4.z += be4.z; bs4.w += be4.w;
    }
    #pragma unroll
    for (int r = 0; r < 2; ++r) {
        int m = m0 + ty * 2 + r;
        *(float4*)(out + (size_t)m * 256 + c0 + tx * 4) =
            make_float4(acc[r][0] + bs4.x, acc[r][1] + bs4.y,
                        acc[r][2] + bs4.z, acc[r][3] + bs4.w);
    }
}

// ---------------- edge kernel (R6 design): fp16 mma, 128x256, 512 thr ----
#define SB_B     0          // 256 rows * 512B = 128KB (full WeT)
#define SB_A     131072     // 2 stages * 16KB
#define SM_SHS   163840     // 256 floats
#define SM_SBIAS 164864     // 4 * 128 * 8 floats = 16KB
#define SM_EDGE_TOTAL 181248

__global__ __launch_bounds__(512, 1) void edge_mma_kernel(
    const float* __restrict__ e, const __half* __restrict__ WeTh,
    const float* __restrict__ Hs, const float* __restrict__ Hd,
    const float* __restrict__ Wb,
    float* __restrict__ e_new, float* __restrict__ bias)
{
    extern __shared__ char smem[];
    const uint32_t sb = smem_u32(smem);
    float* sHs   = (float*)(smem + SM_SHS);
    float* sbias = (float*)(smem + SM_SBIAS);

    const int tid = threadIdx.x;
    const int w = tid >> 5, lane = tid & 31;
    const int g = lane >> 2, tig = lane & 3, x7 = lane & 7;
    const int wr = w >> 2, wc = w & 3;

    const int m0 = blockIdx.x * 128;
    const int b = m0 >> 16, i = (m0 >> 8) & 255, j0 = m0 & 255;

    // ---- B (full WeT) via cp.async, swizzled ----
    {
        const int ch = tid & 31;
        const int rbase = tid >> 5;
        #pragma unroll
        for (int it = 0; it < 16; ++it) {
            int row = rbase + it * 16;
            cp16(sb + SB_B + row * 512 + ((ch ^ (row & 7)) << 4),
                 WeTh + (size_t)row * 256 + ch * 8);
        }
    }
    asm volatile("cp.async.commit_group;");

    // ---- A chunk 0: LDG fp32 -> fp16 STS ----
    const float* Ab = e + (size_t)m0 * 256;
    const int seg = tid & 7;
    #pragma unroll
    for (int it = 0; it < 2; ++it) {
        int row = (tid >> 3) + it * 64;
        const float* p = Ab + (size_t)row * 256 + seg * 8;
        float4 v0 = *(const float4*)p;
        float4 v1 = *(const float4*)(p + 4);
        uint4 u = make_uint4(pack_h2(v0.x, v0.y), pack_h2(v0.z, v0.w),
                             pack_h2(v1.x, v1.y), pack_h2(v1.z, v1.w));
        *(uint4*)(smem + SB_A + row * 128 + ((seg ^ (row & 7)) << 4)) = u;
    }

    // ---- tables + per-warp Wb B-fragments ----
    if (tid < 256)
        sHs[tid] = Hs[(((size_t)(b << 8) + i) << 8) + tid];   // be pre-folded

    uint32_t bw0[4], bw1[4];
    #pragma unroll
    for (int kc = 0; kc < 4; ++kc) {
        int k0 = wc * 64 + kc * 16 + 2 * tig;
        bw0[kc] = pack_h2(Wb[(k0    ) * 8 + g], Wb[(k0 + 1) * 8 + g]);
        bw1[kc] = pack_h2(Wb[(k0 + 8) * 8 + g], Wb[(k0 + 9) * 8 + g]);
    }

    asm volatile("cp.async.wait_group 0;" ::: "memory");
    __syncthreads();

    const int rowoffA = x7 + (((lane >> 3) & 1) << 3);
    const int selA = lane >> 4;
    const int rowoffB = x7 + ((lane >> 4) << 3);
    const int selB = (lane >> 3) & 1;

    float acc[2][8][4] = {};
    float4 pre[4];

    for (int c = 0; c < 4; ++c) {
        if (c < 3) {
            #pragma unroll
            for (int it = 0; it < 2; ++it) {
                int row = (tid >> 3) + it * 64;
                const float* p =
                    Ab + (size_t)row * 256 + (c + 1) * 64 + seg * 8;
                pre[it * 2]     = *(const float4*)p;
                pre[it * 2 + 1] = *(const float4*)(p + 4);
            }
        }
        const uint32_t sAc = sb + SB_A + (c & 1) * 16384;
        #pragma unroll
        for (int kk = 0; kk < 4; ++kk) {
            uint32_t a0[4], a1[4];
            {
                int rowA = wr * 32 + rowoffA;
                ldmx4(a0, sAc + rowA * 128 + ((((kk << 1) + selA) ^ x7) << 4));
                ldmx4(a1, sAc + (rowA + 16) * 128 +
                              ((((kk << 1) + selA) ^ x7) << 4));
            }
            uint32_t bf[4][4];
            #pragma unroll
            for (int nt2 = 0; nt2 < 4; ++nt2) {
                int rowB = wc * 64 + nt2 * 16 + rowoffB;
                ldmx4(bf[nt2], sb + SB_B + rowB * 512 +
                               (((c * 8 + (kk << 1) + selB) ^ x7) << 4));
            }
            #pragma unroll
            for (int nt2 = 0; nt2 < 4; ++nt2) {
                mma_f16(acc[0][nt2 * 2],     a0, bf[nt2][0], bf[nt2][1]);
                mma_f16(acc[0][nt2 * 2 + 1], a0, bf[nt2][2], bf[nt2][3]);
                mma_f16(acc[1][nt2 * 2],     a1, bf[nt2][0], bf[nt2][1]);
                mma_f16(acc[1][nt2 * 2 + 1], a1, bf[nt2][2], bf[nt2][3]);
            }
        }
        __syncthreads();
        if (c < 3) {
            char* dst = smem + SB_A + ((c + 1) & 1) * 16384;
            #pragma unroll
            for (int it = 0; it < 2; ++it) {
                int row = (tid >> 3) + it * 64;
                float4 v0 = pre[it * 2], v1 = pre[it * 2 + 1];
                uint4 u = make_uint4(pack_h2(v0.x, v0.y), pack_h2(v0.z, v0.w),
                                     pack_h2(v1.x, v1.y), pack_h2(v1.z, v1.w));
                *(uint4*)(dst + row * 128 + ((seg ^ (row & 7)) << 4)) = u;
            }
            __syncthreads();
        }
    }

    // ---- epilogue: +Hs +Hd, ReLU, store e_new, bias via mma ----
    float bc[2][4] = {};
    #pragma unroll
    for (int mt = 0; mt < 2; ++mt) {
        const int rl = wr * 32 + mt * 16 + g;
        const float* hd0 = Hd + ((((size_t)b << 8) + j0 + rl) << 8);
        const float* hd1 = hd0 + (8 << 8);
        float* er0 = e_new + ((size_t)(m0 + rl)) * 256;
        float* er1 = er0 + 8 * 256;
        uint32_t afr[4];
        #pragma unroll
        for (int nt = 0; nt < 8; ++nt) {
            const int cl = wc * 64 + nt * 8 + 2 * tig;
            float2 hs = *(const float2*)(sHs + cl);
            float2 h0 = *(const float2*)(hd0 + cl);
            float2 h1 = *(const float2*)(hd1 + cl);
            float x0 = fmaxf(acc[mt][nt][0] + hs.x + h0.x, 0.0f);
            float x1 = fmaxf(acc[mt][nt][1] + hs.y + h0.y, 0.0f);
            float x2 = fmaxf(acc[mt][nt][2] + hs.x + h1.x, 0.0f);
            float x3 = fmaxf(acc[mt][nt][3] + hs.y + h1.y, 0.0f);
            *(float2*)(er0 + cl) = make_float2(x0, x1);
            *(float2*)(er1 + cl) = make_float2(x2, x3);
            if ((nt & 1) == 0) {
                afr[0] = pack_h2(x0, x1);
                afr[1] = pack_h2(x2, x3);
            } else {
                afr[2] = pack_h2(x0, x1);
                afr[3] = pack_h2(x2, x3);
                mma_f16(bc[mt], afr, bw0[nt >> 1], bw1[nt >> 1]);
            }
        }
    }
    {
        float* sbw = sbias + wc * 1024;
        #pragma unroll
        for (int mt = 0; mt < 2; ++mt) {
            int rl = wr * 32 + mt * 16 + g;
            sbw[rl * 8 + 2 * tig]           = bc[mt][0];
            sbw[rl * 8 + 2 * tig + 1]       = bc[mt][1];
            sbw[(rl + 8) * 8 + 2 * tig]     = bc[mt][2];
            sbw[(rl + 8) * 8 + 2 * tig + 1] = bc[mt][3];
        }
    }
    __syncthreads();
    #pragma unroll
    for (int q = 0; q < 2; ++q) {
        int t = tid + q * 512;
        int r = t & 127, hh = t >> 7;
        float v = sbias[r * 8 + hh] + sbias[1024 + r * 8 + hh] +
                  sbias[2048 + r * 8 + hh] + sbias[3072 + r * 8 + hh];
        bias[((((size_t)b * 8 + hh) * 256 + i) << 8) + j0 + r] = v;
    }
}

// ---------------- fp16 MMA GEMM: 64x64 tile, 256 thr (8 warps 2x4) ------
// A fp32 [M,K], Wh fp16 [N,K], out = op(A@Wh^T + bias) [+res]
// smem: A 2x8KB @0, B 2x8KB @16384 -> 32KB
template <int OP, bool RES>
__global__ __launch_bounds__(256) void gemm_mma64(
    const float* __restrict__ A, const __half* __restrict__ Wh,
    const float* __restrict__ bias, const float* __restrict__ res,
    float* __restrict__ out, int K, int N)
{
    extern __shared__ char sm2[];
    const uint32_t sb = smem_u32(sm2);
    const int tid = threadIdx.x;
    const int w = tid >> 5, lane = tid & 31;
    const int g = lane >> 2, tig = lane & 3, x7 = lane & 7;
    const int wr = w >> 2, wc = w & 3;
    const int m0 = blockIdx.y * 64, n0 = blockIdx.x * 64;
    const int NC = K >> 6;

    const float*  Ab = A + (size_t)m0 * K;
    const __half* Bb = Wh + (size_t)n0 * K;
    const int arow = tid >> 2;        // 0..63
    const int cpair = tid & 3;        // 2 chunks of 8 floats each

    // B chunk 0: 64 rows x 64 halves = 8KB
    #pragma unroll
    for (int p = 0; p < 2; ++p) {
        int idx = tid + p * 256;
        int r = idx >> 3, ch = idx & 7;
        cp16(sb + 16384 + r * 128 + ((ch ^ (r & 7)) << 4),
             Bb + (size_t)r * K + ch * 8);
    }
    asm volatile("cp.async.commit_group;");
    // A chunk 0
    #pragma unroll
    for (int q = 0; q < 2; ++q) {
        int ch = cpair * 2 + q;
        const float* p = Ab + (size_t)arow * K + ch * 8;
        float4 v0 = *(const float4*)p;
        float4 v1 = *(const float4*)(p + 4);
        uint4 u = make_uint4(pack_h2(v0.x, v0.y), pack_h2(v0.z, v0.w),
                             pack_h2(v1.x, v1.y), pack_h2(v1.z, v1.w));
        *(uint4*)(sm2 + arow * 128 + ((ch ^ (arow & 7)) << 4)) = u;
    }
    asm volatile("cp.async.wait_group 0;" ::: "memory");
    __syncthreads();

    const int rowoffA = x7 + (((lane >> 3) & 1) << 3);
    const int selA = lane >> 4;
    const int rowoffB = x7 + ((lane >> 4) << 3);
    const int selB = (lane >> 3) & 1;

    float acc[2][2][4] = {};
    float4 pre[4];

    for (int c = 0; c < NC; ++c) {
        if (c + 1 < NC) {
            #pragma unroll
            for (int p = 0; p < 2; ++p) {
                int idx = tid + p * 256;
                int r = idx >> 3, ch = idx & 7;
                cp16(sb + 16384 + (((c + 1) & 1) << 13) + r * 128 +
                         ((ch ^ (r & 7)) << 4),
                     Bb + (size_t)r * K + (c + 1) * 64 + ch * 8);
            }
            asm volatile("cp.async.commit_group;");
            #pragma unroll
            for (int q = 0; q < 2; ++q) {
                int ch = cpair * 2 + q;
                const float* p = Ab + (size_t)arow * K + (c + 1) * 64 + ch * 8;
                pre[q * 2]     = *(const float4*)p;
                pre[q * 2 + 1] = *(const float4*)(p + 4);
            }
        }
        const uint32_t sA = sb + ((c & 1) << 13);
        const uint32_t sB = sb + 16384 + ((c & 1) << 13);
        #pragma unroll
        for (int kk = 0; kk < 4; ++kk) {
            uint32_t a0[4], a1[4];
            int rA = wr * 32 + rowoffA;
            ldmx4(a0, sA + rA * 128 + ((((kk << 1) + selA) ^ x7) << 4));
            ldmx4(a1, sA + (rA + 16) * 128 + ((((kk << 1) + selA) ^ x7) << 4));
            uint32_t bf[4];
            int rB = wc * 16 + rowoffB;
            ldmx4(bf, sB + rB * 128 + ((((kk << 1) + selB) ^ x7) << 4));
            mma_f16(acc[0][0], a0, bf[0], bf[1]);
            mma_f16(acc[0][1], a0, bf[2], bf[3]);
            mma_f16(acc[1][0], a1, bf[0], bf[1]);
            mma_f16(acc[1][1], a1, bf[2], bf[3]);
        }
        __syncthreads();
        if (c + 1 < NC) {
            char* dst = sm2 + (((c + 1) & 1) << 13);
            #pragma unroll
            for (int q = 0; q < 2; ++q) {
                int ch = cpair * 2 + q;
                float4 v0 = pre[q * 2], v1 = pre[q * 2 + 1];
                uint4 u = make_uint4(pack_h2(v0.x, v0.y), pack_h2(v0.z, v0.w),
                                     pack_h2(v1.x, v1.y), pack_h2(v1.z, v1.w));
                *(uint4*)(dst + arow * 128 + ((ch ^ (arow & 7)) << 4)) = u;
            }
            asm volatile("cp.async.wait_group 0;" ::: "memory");
            __syncthreads();
        }
    }

    // epilogue
    #pragma unroll
    for (int mt = 0; mt < 2; ++mt) {
        #pragma unroll
        for (int rh = 0; rh < 2; ++rh) {
            int rl = wr * 32 + mt * 16 + rh * 8 + g;
            float* orow = out + (size_t)(m0 + rl) * N + n0;
            const float* rrow = RES ? res + (size_t)(m0 + rl) * N + n0 : nullptr;
            #pragma unroll
            for (int nh = 0; nh < 2; ++nh) {
                int cl = wc * 16 + nh * 8 + 2 * tig;
                float x0 = acc[mt][nh][rh * 2 + 0] + __ldg(bias + n0 + cl);
                float x1 = acc[mt][nh][rh * 2 + 1] + __ldg(bias + n0 + cl + 1);
                if (OP == 1) { x0 = gelu_exact(x0); x1 = gelu_exact(x1); }
                if (RES) {
                    float2 rv = *(const float2*)(rrow + cl);
                    x0 += rv.x; x1 += rv.y;
                }
                *(float2*)(orow + cl) = make_float2(x0, x1);
            }
        }
    }
}

// ---------------- LayerNorm ----------------
__global__ __launch_bounds__(256) void ln_kernel(
    const float* __restrict__ in, const float* __restrict__ g,
    const float* __restrict__ b, float* __restrict__ out)
{
    int row = blockIdx.x;
    int t = threadIdx.x;
    float v = in[(size_t)row * 256 + t];
    __shared__ float red[8];

    float s = v;
    #pragma unroll
    for (int o = 16; o; o >>= 1) s += __shfl_xor_sync(0xffffffffu, s, o);
    if ((t & 31) == 0) red[t >> 5] = s;
    __syncthreads();
    float mean = (red[0] + red[1] + red[2] + red[3] +
                  red[4] + red[5] + red[6] + red[7]) * (1.0f / 256.0f);
    float d = v - mean;
    __syncthreads();
    s = d * d;
    #pragma unroll
    for (int o = 16; o; o >>= 1) s += __shfl_xor_sync(0xffffffffu, s, o);
    if ((t & 31) == 0) red[t >> 5] = s;
    __syncthreads();
    float var = (red[0] + red[1] + red[2] + red[3] +
                 red[4] + red[5] + red[6] + red[7]) * (1.0f / 256.0f);
    out[(size_t)row * 256 + t] = d * rsqrtf(var + 1e-5f) * g[t] + b[t];
}

// ---------------- attention kernel ----------------
__global__ __launch_bounds__(256) void attn_kernel(
    const float* __restrict__ qkv, const float* __restrict__ bias,
    const float* __restrict__ bb, float* __restrict__ o)
{
    extern __shared__ float sm[];
    float (*ks)[33] = (float(*)[33])sm;
    float (*vs)[33] = (float(*)[33])(sm + 256 * 33);
    float (*qs)[33] = (float(*)[33])(sm + 2 * 256 * 33);

    const int tid = threadIdx.x;
    const int tile = blockIdx.x & 7;
    const int bh = blockIdx.x >> 3;
    const int b = bh >> 3, hh = bh & 7;
    const int i0 = tile * 32;
    const float bbv = bb[hh];

    for (int idx = tid; idx < 2048; idx += 256) {
        int j = idx >> 3, q4 = idx & 7;
        const float* base = qkv + (size_t)(b * 256 + j) * 768 + hh * 32 + q4 * 4;
        float4 kk = *(const float4*)(base + 256);
        float4 vv = *(const float4*)(base + 512);
        ks[j][q4 * 4 + 0] = kk.x; ks[j][q4 * 4 + 1] = kk.y;
        ks[j][q4 * 4 + 2] = kk.z; ks[j][q4 * 4 + 3] = kk.w;
        vs[j][q4 * 4 + 0] = vv.x; vs[j][q4 * 4 + 1] = vv.y;
        vs[j][q4 * 4 + 2] = vv.z; vs[j][q4 * 4 + 3] = vv.w;
    }
    for (int idx = tid; idx < 1024; idx += 256) {
        int r = idx >> 5, d = idx & 31;
        qs[r][d] = qkv[(size_t)(b * 256 + i0 + r) * 768 + hh * 32 + d];
    }
    __syncthreads();

    const int r = tid >> 3, s = tid & 7;
    const int i = i0 + r;
    const float* brow = bias + ((((size_t)b * 8 + hh) * 256 + i) << 8);

    float sc[32];
    float mx = -1e30f;
    #pragma unroll
    for (int jj = 0; jj < 32; ++jj) {
        int j = jj * 8 + s;
        float a = 0.0f;
        #pragma unroll
        for (int d = 0; d < 32; ++d) a += qs[r][d] * ks[j][d];
        a = a * 0.17677669529663687f + brow[j] + bbv;
        sc[jj] = a;
        mx = fmaxf(mx, a);
    }
    #pragma unroll
    for (int off = 4; off; off >>= 1)
        mx = fmaxf(mx, __shfl_xor_sync(0xffffffffu, mx, off));

    float sum = 0.0f;
    #pragma unroll
    for (int jj = 0; jj < 32; ++jj) { sc[jj] = expf(sc[jj] - mx); sum += sc[jj]; }
    #pragma unroll
    for (int off = 4; off; off >>= 1)
        sum += __shfl_xor_sync(0xffffffffu, sum, off);
    float inv = 1.0f / sum;

    float oacc[32] = {};
    #pragma unroll
    for (int jj = 0; jj < 32; ++jj) {
        int j = jj * 8 + s;
        float w = sc[jj];
        #pragma unroll
        for (int d = 0; d < 32; ++d) oacc[d] += w * vs[j][d];
    }

    float w4[4];
    #pragma unroll
    for (int d = 0; d < 32; ++d) {
        float t = oacc[d];
        t += __shfl_xor_sync(0xffffffffu, t, 1);
        t += __shfl_xor_sync(0xffffffffu, t, 2);
        t += __shfl_xor_sync(0xffffffffu, t, 4);
        if ((d >> 2) == s) w4[d & 3] = t;
    }
    *(float4*)(o + ((size_t)(b * 256 + i)) * 256 + hh * 32 + s * 4) =
        make_float4(w4[0] * inv, w4[1] * inv, w4[2] * inv, w4[3] * inv);
}

// ---------------- launch ----------------
extern "C" void kernel_launch(void* const* d_in, const int* in_sizes, int n_in,
                              void* d_out, int out_size)
{
    (void)in_sizes; (void)n_in; (void)out_size;
    const float* h    = (const float*)d_in[0];
    const float* e    = (const float*)d_in[1];
    const float* We   = (const float*)d_in[2];
    const float* be   = (const float*)d_in[3];
    const float* Ws   = (const float*)d_in[4];
    const float* bs   = (const float*)d_in[5];
    const float* Wd   = (const float*)d_in[6];
    const float* bd   = (const float*)d_in[7];
    const float* Wb   = (const float*)d_in[8];
    const float* bb   = (const float*)d_in[9];
    const float* ln1g = (const float*)d_in[10];
    const float* ln1b = (const float*)d_in[11];
    const float* Wqkv = (const float*)d_in[12];
    const float* bqkv = (const float*)d_in[13];
    const float* Wo   = (const float*)d_in[14];
    const float* bo   = (const float*)d_in[15];
    const float* ln2g = (const float*)d_in[16];
    const float* ln2b = (const float*)d_in[17];
    const float* W1   = (const float*)d_in[18];
    const float* b1   = (const float*)d_in[19];
    const float* W2   = (const float*)d_in[20];
    const float* b2   = (const float*)d_in[21];

    float* out_h2 = (float*)d_out;
    float* out_e  = out_h2 + (size_t)BN * DD;

    float *pHs, *pHd, *px1, *pqkv, *pbias, *po, *ph1, *py, *pf;
    __half *pWeTh, *pWqkvTh, *pWoTh, *pW1Th, *pW2Th;
    cudaGetSymbolAddress((void**)&pHs,     g_Hs);
    cudaGetSymbolAddress((void**)&pHd,     g_Hd);
    cudaGetSymbolAddress((void**)&px1,     g_x1);
    cudaGetSymbolAddress((void**)&pqkv,    g_qkv);
    cudaGetSymbolAddress((void**)&pbias,   g_bias);
    cudaGetSymbolAddress((void**)&po,      g_o);
    cudaGetSymbolAddress((void**)&ph1,     g_h1);
    cudaGetSymbolAddress((void**)&py,      g_y);
    cudaGetSymbolAddress((void**)&pf,      g_ffn);
    cudaGetSymbolAddress((void**)&pWeTh,   g_WeTh);
    cudaGetSymbolAddress((void**)&pWqkvTh, g_WqkvTh);
    cudaGetSymbolAddress((void**)&pWoTh,   g_WoTh);
    cudaGetSymbolAddress((void**)&pW1Th,   g_W1Th);
    cudaGetSymbolAddress((void**)&pW2Th,   g_W2Th);

    // #1-3: prep (edge kernel is launch #4 so ncu -s captures it)
    transpose_all<<<2560, 256>>>(We, Wqkv, Wo, W1, W2,
                                 pWeTh, pWqkvTh, pWoTh, pW1Th, pW2Th);
    gemm_hsd<<<dim3(8, 16, 2), 256>>>(h, Ws, bs, Wd, bd, be, pHs, pHd);
    ln_kernel<<<BN, 256>>>(h, ln1g, ln1b, px1);

    // #4: edge update + attention bias
    cudaFuncSetAttribute(edge_mma_kernel,
                         cudaFuncAttributeMaxDynamicSharedMemorySize,
                         SM_EDGE_TOTAL);
    edge_mma_kernel<<<2048, 512, SM_EDGE_TOTAL>>>(
        e, pWeTh, pHs, pHd, Wb, out_e, pbias);

    // attention path
    gemm_mma64<0, false><<<dim3(12, 16), 256, 32768>>>(
        px1, pWqkvTh, bqkv, nullptr, pqkv, 256, 768);
    cudaFuncSetAttribute(attn_kernel,
                         cudaFuncAttributeMaxDynamicSharedMemorySize, 73728);
    attn_kernel<<<256, 256, 71808>>>(pqkv, pbias, bb, po);

    // output proj + residual
    gemm_mma64<0, true><<<dim3(4, 16), 256, 32768>>>(
        po, pWoTh, bo, h, ph1, 256, 256);

    // FFN
    ln_kernel<<<BN, 256>>>(ph1, ln2g, ln2b, py);
    gemm_mma64<1, false><<<dim3(16, 16), 256, 32768>>>(
        py, pW1Th, b1, nullptr, pf, 256, 1024);
    gemm_mma64<0, true><<<dim3(4, 16), 256, 32768>>>(
        pf, pW2Th, b2, ph1, out_h2, 1024, 256);
}

// round 9
// speedup vs baseline: 4.1625x; 1.1079x over previous
#include <cuda_runtime.h>
#include <cuda_fp16.h>
#include <math.h>
#include <stdint.h>

// Shapes (fixed): B=4, N=256, D=256, H=8, HD=32, DFF=1024
#define BN 1024
#define DD 256

// ---------------- scratch ----------------
__device__ __align__(16) float  g_Hs[BN * DD];    // Hs + be
__device__ __align__(16) float  g_Hd[BN * DD];
__device__ __align__(16) float  g_x1[BN * DD];
__device__ __align__(16) float  g_qkv[BN * 768];
__device__ __align__(16) float  g_bias[4 * 8 * 256 * 256];
__device__ __align__(16) float  g_o[BN * DD];
__device__ __align__(16) float  g_h1[BN * DD];
__device__ __align__(16) float  g_y[BN * DD];
__device__ __align__(16) float  g_ffn[BN * 1024];
__device__ __align__(16) __half g_WeTh[DD * DD];
__device__ __align__(16) __half g_WqkvTh[768 * DD];
__device__ __align__(16) __half g_WoTh[DD * DD];
__device__ __align__(16) __half g_W1Th[1024 * DD];
__device__ __align__(16) __half g_W2Th[DD * 1024];

// ---------------- helpers ----------------
__device__ __forceinline__ uint32_t smem_u32(const void* p) {
    uint32_t a;
    asm("{ .reg .u64 t; cvta.to.shared.u64 t, %1; cvt.u32.u64 %0, t; }"
        : "=r"(a) : "l"(p));
    return a;
}
__device__ __forceinline__ void cp16(uint32_t dst, const void* src) {
    asm volatile("cp.async.cg.shared.global [%0], [%1], 16;"
                 :: "r"(dst), "l"(src));
}
__device__ __forceinline__ void ldmx4(uint32_t* r, uint32_t addr) {
    asm volatile(
        "ldmatrix.sync.aligned.m8n8.x4.shared.b16 {%0,%1,%2,%3}, [%4];"
        : "=r"(r[0]), "=r"(r[1]), "=r"(r[2]), "=r"(r[3]) : "r"(addr));
}
__device__ __forceinline__ void mma_f16(float* c, const uint32_t* a,
                                        uint32_t b0, uint32_t b1) {
    asm volatile(
        "mma.sync.aligned.m16n8k16.row.col.f32.f16.f16.f32 "
        "{%0,%1,%2,%3}, {%4,%5,%6,%7}, {%8,%9}, {%0,%1,%2,%3};"
        : "+f"(c[0]), "+f"(c[1]), "+f"(c[2]), "+f"(c[3])
        : "r"(a[0]), "r"(a[1]), "r"(a[2]), "r"(a[3]), "r"(b0), "r"(b1));
}
__device__ __forceinline__ uint32_t pack_h2(float x, float y) {
    __half2 h = __float22half2_rn(make_float2(x, y));
    return *reinterpret_cast<uint32_t*>(&h);
}
__device__ __forceinline__ float gelu_exact(float x) {
    return 0.5f * x * (1.0f + erff(x * 0.70710678118654752f));
}

// ---------------- tiled weight transpose+fp16 (coalesced) ----------------
__global__ __launch_bounds__(256) void transpose_all(
    const float* __restrict__ We,  const float* __restrict__ Wqkv,
    const float* __restrict__ Wo,  const float* __restrict__ W1,
    const float* __restrict__ W2,
    __half* __restrict__ oWe,  __half* __restrict__ oWqkv,
    __half* __restrict__ oWo,  __half* __restrict__ oW1,
    __half* __restrict__ oW2)
{
    __shared__ float s[32][33];
    int bid = blockIdx.x;
    const float* in; __half* out; int K, N, t;
    if (bid < 64)        { in = We;   out = oWe;   K = 256;  N = 256;  t = bid; }
    else if (bid < 256)  { in = Wqkv; out = oWqkv; K = 256;  N = 768;  t = bid - 64; }
    else if (bid < 320)  { in = Wo;   out = oWo;   K = 256;  N = 256;  t = bid - 256; }
    else if (bid < 576)  { in = W1;   out = oW1;   K = 256;  N = 1024; t = bid - 320; }
    else                 { in = W2;   out = oW2;   K = 1024; N = 256;  t = bid - 576; }
    const int ntn = N >> 5;
    const int k0 = (t / ntn) << 5, n0 = (t % ntn) << 5;
    const int r = threadIdx.x >> 5, c = threadIdx.x & 31;
    #pragma unroll
    for (int q = 0; q < 4; ++q)
        s[r + q * 8][c] = in[(size_t)(k0 + r + q * 8) * N + n0 + c];
    __syncthreads();
    #pragma unroll
    for (int q = 0; q < 4; ++q)
        out[(size_t)(n0 + r + q * 8) * K + k0 + c] =
            __float2half_rn(s[c][r + q * 8]);
}

// ---------------- dual GEMM: Hs(+be) and Hd, both fp32 ----------------
__global__ __launch_bounds__(256) void gemm_hsd(
    const float* __restrict__ A,
    const float* __restrict__ Ws, const float* __restrict__ bs,
    const float* __restrict__ Wd, const float* __restrict__ bd,
    const float* __restrict__ be,
    float* __restrict__ oHs, float* __restrict__ oHd)
{
    const float* W    = blockIdx.z ? Wd : Ws;
    const float* bias = blockIdx.z ? bd : bs;
    float* out        = blockIdx.z ? oHd : oHs;

    __shared__ float As[64][16];
    __shared__ float Bs[16][32];
    const int tid = threadIdx.x;
    const int m0 = blockIdx.y * 64;
    const int c0 = blockIdx.x * 32;
    const int ty = tid >> 3;
    const int tx = tid & 7;

    float acc[2][4] = {};

    for (int k0 = 0; k0 < 256; k0 += 16) {
        {
            int r = tid >> 2, q = tid & 3;
            *(float4*)&As[r][q * 4] =
                *(const float4*)(A + (size_t)(m0 + r) * 256 + k0 + q * 4);
        }
        if (tid < 128) {
            int kk = tid >> 3, q = tid & 7;
            *(float4*)&Bs[kk][q * 4] =
                *(const float4*)(W + (size_t)(k0 + kk) * 256 + c0 + q * 4);
        }
        __syncthreads();
        #pragma unroll
        for (int k = 0; k < 16; ++k) {
            float a0 = As[ty * 2][k];
            float a1 = As[ty * 2 + 1][k];
            float4 bv = *(float4*)&Bs[k][tx * 4];
            acc[0][0] += a0 * bv.x; acc[0][1] += a0 * bv.y;
            acc[0][2] += a0 * bv.z; acc[0][3] += a0 * bv.w;
            acc[1][0] += a1 * bv.x; acc[1][1] += a1 * bv.y;
            acc[1][2] += a1 * bv.z; acc[1][3] += a1 * bv.w;
        }
        __syncthreads();
    }

    float4 bs4 = *(const float4*)(bias + c0 + tx * 4);
    if (blockIdx.z == 0) {
        float4 be4 = *(const float4*)(be + c0 + tx * 4);
        bs4.x += be4.x; bs4.y += be4.y; bs4.z += be4.z; bs4.w += be4.w;
    }
    #pragma unroll
    for (int r = 0; r < 2; ++r) {
        int m = m0 + ty * 2 + r;
        *(float4*)(out + (size_t)m * 256 + c0 + tx * 4) =
            make_float4(acc[r][0] + bs4.x, acc[r][1] + bs4.y,
                        acc[r][2] + bs4.z, acc[r][3] + bs4.w);
    }
}

// ---------------- edge kernel: 64x256 tile, 256 thr, 2 CTAs/SM ----------
// smem: B 2x32KB @0, A 2x8KB @65536, sHs @81920, sbias @82944
#define SB_B     0
#define SB_A     65536
#define SM_SHS   81920
#define SM_SBIAS 82944
#define SM_EDGE_TOTAL 91136

__global__ __launch_bounds__(256, 2) void edge_mma_kernel(
    const float* __restrict__ e, const __half* __restrict__ WeTh,
    const float* __restrict__ Hs, const float* __restrict__ Hd,
    const float* __restrict__ Wb,
    float* __restrict__ e_new, float* __restrict__ bias)
{
    extern __shared__ char smem[];
    const uint32_t sb = smem_u32(smem);
    float* sHs   = (float*)(smem + SM_SHS);
    float* sbias = (float*)(smem + SM_SBIAS);

    const int tid = threadIdx.x;
    const int w = tid >> 5, lane = tid & 31;
    const int g = lane >> 2, tig = lane & 3, x7 = lane & 7;
    const int wr = w >> 2, wc = w & 3;     // 2 row-groups x 4 col-groups

    const int m0 = blockIdx.x * 64;
    const int b = m0 >> 16, i = (m0 >> 8) & 255, j0 = m0 & 255;

    // ---- B chunk 0 (256 n-rows x 64 k) via cp.async ----
    #pragma unroll
    for (int it = 0; it < 8; ++it) {
        int idx = tid + it * 256;
        int r = idx >> 3, ch = idx & 7;
        cp16(sb + SB_B + r * 128 + ((ch ^ (r & 7)) << 4),
             WeTh + (size_t)r * 256 + ch * 8);
    }
    asm volatile("cp.async.commit_group;");

    // ---- A chunk 0: LDG fp32 -> fp16 STS (64 rows x 64 k) ----
    const float* Ab = e + (size_t)m0 * 256;
    #pragma unroll
    for (int p = 0; p < 2; ++p) {
        int idx = tid + p * 256;
        int row = idx >> 3, seg = idx & 7;
        const float* ptr = Ab + (size_t)row * 256 + seg * 8;
        float4 v0 = *(const float4*)ptr;
        float4 v1 = *(const float4*)(ptr + 4);
        uint4 u = make_uint4(pack_h2(v0.x, v0.y), pack_h2(v0.z, v0.w),
                             pack_h2(v1.x, v1.y), pack_h2(v1.z, v1.w));
        *(uint4*)(smem + SB_A + row * 128 + ((seg ^ (row & 7)) << 4)) = u;
    }

    // ---- tables + per-warp Wb B-fragments ----
    sHs[tid] = Hs[(((size_t)(b << 8) + i) << 8) + tid];   // be pre-folded

    uint32_t bw0[4], bw1[4];
    #pragma unroll
    for (int kc = 0; kc < 4; ++kc) {
        int k0 = wc * 64 + kc * 16 + 2 * tig;
        bw0[kc] = pack_h2(Wb[(k0    ) * 8 + g], Wb[(k0 + 1) * 8 + g]);
        bw1[kc] = pack_h2(Wb[(k0 + 8) * 8 + g], Wb[(k0 + 9) * 8 + g]);
    }

    asm volatile("cp.async.wait_group 0;" ::: "memory");
    __syncthreads();

    const int rowoffA = x7 + (((lane >> 3) & 1) << 3);
    const int selA = lane >> 4;
    const int rowoffB = x7 + ((lane >> 4) << 3);
    const int selB = (lane >> 3) & 1;

    float acc[2][8][4] = {};
    float4 pre[4];

    for (int c = 0; c < 4; ++c) {
        if (c < 3) {
            // B prefetch to stage^1
            #pragma unroll
            for (int it = 0; it < 8; ++it) {
                int idx = tid + it * 256;
                int r = idx >> 3, ch = idx & 7;
                cp16(sb + SB_B + (((c + 1) & 1) << 15) + r * 128 +
                         ((ch ^ (r & 7)) << 4),
                     WeTh + (size_t)r * 256 + (c + 1) * 64 + ch * 8);
            }
            asm volatile("cp.async.commit_group;");
            // A prefetch to regs
            #pragma unroll
            for (int p = 0; p < 2; ++p) {
                int idx = tid + p * 256;
                int row = idx >> 3, seg = idx & 7;
                const float* ptr =
                    Ab + (size_t)row * 256 + (c + 1) * 64 + seg * 8;
                pre[p * 2]     = *(const float4*)ptr;
                pre[p * 2 + 1] = *(const float4*)(ptr + 4);
            }
        }
        const uint32_t sAc = sb + SB_A + ((c & 1) << 13);
        const uint32_t sBc = sb + SB_B + ((c & 1) << 15);
        #pragma unroll
        for (int kk = 0; kk < 4; ++kk) {
            uint32_t a0[4], a1[4];
            {
                int rowA = wr * 32 + rowoffA;
                ldmx4(a0, sAc + rowA * 128 + ((((kk << 1) + selA) ^ x7) << 4));
                ldmx4(a1, sAc + (rowA + 16) * 128 +
                              ((((kk << 1) + selA) ^ x7) << 4));
            }
            uint32_t bf[4][4];
            #pragma unroll
            for (int nt2 = 0; nt2 < 4; ++nt2) {
                int rowB = wc * 64 + nt2 * 16 + rowoffB;
                ldmx4(bf[nt2], sBc + rowB * 128 +
                               ((((kk << 1) + selB) ^ x7) << 4));
            }
            #pragma unroll
            for (int nt2 = 0; nt2 < 4; ++nt2) {
                mma_f16(acc[0][nt2 * 2],     a0, bf[nt2][0], bf[nt2][1]);
                mma_f16(acc[0][nt2 * 2 + 1], a0, bf[nt2][2], bf[nt2][3]);
                mma_f16(acc[1][nt2 * 2],     a1, bf[nt2][0], bf[nt2][1]);
                mma_f16(acc[1][nt2 * 2 + 1], a1, bf[nt2][2], bf[nt2][3]);
            }
        }
        __syncthreads();
        if (c < 3) {
            char* dst = smem + SB_A + (((c + 1) & 1) << 13);
            #pragma unroll
            for (int p = 0; p < 2; ++p) {
                int idx = tid + p * 256;
                int row = idx >> 3, seg = idx & 7;
                float4 v0 = pre[p * 2], v1 = pre[p * 2 + 1];
                uint4 u = make_uint4(pack_h2(v0.x, v0.y), pack_h2(v0.z, v0.w),
                                     pack_h2(v1.x, v1.y), pack_h2(v1.z, v1.w));
                *(uint4*)(dst + row * 128 + ((seg ^ (row & 7)) << 4)) = u;
            }
            asm volatile("cp.async.wait_group 0;" ::: "memory");
            __syncthreads();
        }
    }

    // ---- epilogue: +Hs +Hd, ReLU, store e_new, bias via mma ----
    float bc[2][4] = {};
    #pragma unroll
    for (int mt = 0; mt < 2; ++mt) {
        const int rl = wr * 32 + mt * 16 + g;
        const float* hd0 = Hd + ((((size_t)b << 8) + j0 + rl) << 8);
        const float* hd1 = hd0 + (8 << 8);
        float* er0 = e_new + ((size_t)(m0 + rl)) * 256;
        float* er1 = er0 + 8 * 256;
        uint32_t afr[4];
        #pragma unroll
        for (int nt = 0; nt < 8; ++nt) {
            const int cl = wc * 64 + nt * 8 + 2 * tig;
            float2 hs = *(const float2*)(sHs + cl);
            float2 h0 = *(const float2*)(hd0 + cl);
            float2 h1 = *(const float2*)(hd1 + cl);
            float x0 = fmaxf(acc[mt][nt][0] + hs.x + h0.x, 0.0f);
            float x1 = fmaxf(acc[mt][nt][1] + hs.y + h0.y, 0.0f);
            float x2 = fmaxf(acc[mt][nt][2] + hs.x + h1.x, 0.0f);
            float x3 = fmaxf(acc[mt][nt][3] + hs.y + h1.y, 0.0f);
            *(float2*)(er0 + cl) = make_float2(x0, x1);
            *(float2*)(er1 + cl) = make_float2(x2, x3);
            if ((nt & 1) == 0) {
                afr[0] = pack_h2(x0, x1);
                afr[1] = pack_h2(x2, x3);
            } else {
                afr[2] = pack_h2(x0, x1);
                afr[3] = pack_h2(x2, x3);
                mma_f16(bc[mt], afr, bw0[nt >> 1], bw1[nt >> 1]);
            }
        }
    }
    {
        float* sbw = sbias + wc * 512;
        #pragma unroll
        for (int mt = 0; mt < 2; ++mt) {
            int rl = wr * 32 + mt * 16 + g;
            sbw[rl * 8 + 2 * tig]           = bc[mt][0];
            sbw[rl * 8 + 2 * tig + 1]       = bc[mt][1];
            sbw[(rl + 8) * 8 + 2 * tig]     = bc[mt][2];
            sbw[(rl + 8) * 8 + 2 * tig + 1] = bc[mt][3];
        }
    }
    __syncthreads();
    #pragma unroll
    for (int q = 0; q < 2; ++q) {
        int t = tid + q * 256;
        int r = t & 63, hh = t >> 6;
        float v = sbias[r * 8 + hh] + sbias[512 + r * 8 + hh] +
                  sbias[1024 + r * 8 + hh] + sbias[1536 + r * 8 + hh];
        bias[((((size_t)b * 8 + hh) * 256 + i) << 8) + j0 + r] = v;
    }
}

// ---------------- fp16 MMA GEMM: 64x64 tile, 256 thr (8 warps 2x4) ------
template <int OP, bool RES>
__global__ __launch_bounds__(256) void gemm_mma64(
    const float* __restrict__ A, const __half* __restrict__ Wh,
    const float* __restrict__ bias, const float* __restrict__ res,
    float* __restrict__ out, int K, int N)
{
    extern __shared__ char sm2[];
    const uint32_t sb = smem_u32(sm2);
    const int tid = threadIdx.x;
    const int w = tid >> 5, lane = tid & 31;
    const int g = lane >> 2, tig = lane & 3, x7 = lane & 7;
    const int wr = w >> 2, wc = w & 3;
    const int m0 = blockIdx.y * 64, n0 = blockIdx.x * 64;
    const int NC = K >> 6;

    const float*  Ab = A + (size_t)m0 * K;
    const __half* Bb = Wh + (size_t)n0 * K;
    const int arow = tid >> 2;
    const int cpair = tid & 3;

    #pragma unroll
    for (int p = 0; p < 2; ++p) {
        int idx = tid + p * 256;
        int r = idx >> 3, ch = idx & 7;
        cp16(sb + 16384 + r * 128 + ((ch ^ (r & 7)) << 4),
             Bb + (size_t)r * K + ch * 8);
    }
    asm volatile("cp.async.commit_group;");
    #pragma unroll
    for (int q = 0; q < 2; ++q) {
        int ch = cpair * 2 + q;
        const float* p = Ab + (size_t)arow * K + ch * 8;
        float4 v0 = *(const float4*)p;
        float4 v1 = *(const float4*)(p + 4);
        uint4 u = make_uint4(pack_h2(v0.x, v0.y), pack_h2(v0.z, v0.w),
                             pack_h2(v1.x, v1.y), pack_h2(v1.z, v1.w));
        *(uint4*)(sm2 + arow * 128 + ((ch ^ (arow & 7)) << 4)) = u;
    }
    asm volatile("cp.async.wait_group 0;" ::: "memory");
    __syncthreads();

    const int rowoffA = x7 + (((lane >> 3) & 1) << 3);
    const int selA = lane >> 4;
    const int rowoffB = x7 + ((lane >> 4) << 3);
    const int selB = (lane >> 3) & 1;

    float acc[2][2][4] = {};
    float4 pre[4];

    for (int c = 0; c < NC; ++c) {
        if (c + 1 < NC) {
            #pragma unroll
            for (int p = 0; p < 2; ++p) {
                int idx = tid + p * 256;
                int r = idx >> 3, ch = idx & 7;
                cp16(sb + 16384 + (((c + 1) & 1) << 13) + r * 128 +
                         ((ch ^ (r & 7)) << 4),
                     Bb + (size_t)r * K + (c + 1) * 64 + ch * 8);
            }
            asm volatile("cp.async.commit_group;");
            #pragma unroll
            for (int q = 0; q < 2; ++q) {
                int ch = cpair * 2 + q;
                const float* p = Ab + (size_t)arow * K + (c + 1) * 64 + ch * 8;
                pre[q * 2]     = *(const float4*)p;
                pre[q * 2 + 1] = *(const float4*)(p + 4);
            }
        }
        const uint32_t sA = sb + ((c & 1) << 13);
        const uint32_t sB = sb + 16384 + ((c & 1) << 13);
        #pragma unroll
        for (int kk = 0; kk < 4; ++kk) {
            uint32_t a0[4], a1[4];
            int rA = wr * 32 + rowoffA;
            ldmx4(a0, sA + rA * 128 + ((((kk << 1) + selA) ^ x7) << 4));
            ldmx4(a1, sA + (rA + 16) * 128 + ((((kk << 1) + selA) ^ x7) << 4));
            uint32_t bf[4];
            int rB = wc * 16 + rowoffB;
            ldmx4(bf, sB + rB * 128 + ((((kk << 1) + selB) ^ x7) << 4));
            mma_f16(acc[0][0], a0, bf[0], bf[1]);
            mma_f16(acc[0][1], a0, bf[2], bf[3]);
            mma_f16(acc[1][0], a1, bf[0], bf[1]);
            mma_f16(acc[1][1], a1, bf[2], bf[3]);
        }
        __syncthreads();
        if (c + 1 < NC) {
            char* dst = sm2 + (((c + 1) & 1) << 13);
            #pragma unroll
            for (int q = 0; q < 2; ++q) {
                int ch = cpair * 2 + q;
                float4 v0 = pre[q * 2], v1 = pre[q * 2 + 1];
                uint4 u = make_uint4(pack_h2(v0.x, v0.y), pack_h2(v0.z, v0.w),
                                     pack_h2(v1.x, v1.y), pack_h2(v1.z, v1.w));
                *(uint4*)(dst + arow * 128 + ((ch ^ (arow & 7)) << 4)) = u;
            }
            asm volatile("cp.async.wait_group 0;" ::: "memory");
            __syncthreads();
        }
    }

    #pragma unroll
    for (int mt = 0; mt < 2; ++mt) {
        #pragma unroll
        for (int rh = 0; rh < 2; ++rh) {
            int rl = wr * 32 + mt * 16 + rh * 8 + g;
            float* orow = out + (size_t)(m0 + rl) * N + n0;
            const float* rrow = RES ? res + (size_t)(m0 + rl) * N + n0 : nullptr;
            #pragma unroll
            for (int nh = 0; nh < 2; ++nh) {
                int cl = wc * 16 + nh * 8 + 2 * tig;
                float x0 = acc[mt][nh][rh * 2 + 0] + __ldg(bias + n0 + cl);
                float x1 = acc[mt][nh][rh * 2 + 1] + __ldg(bias + n0 + cl + 1);
                if (OP == 1) { x0 = gelu_exact(x0); x1 = gelu_exact(x1); }
                if (RES) {
                    float2 rv = *(const float2*)(rrow + cl);
                    x0 += rv.x; x1 += rv.y;
                }
                *(float2*)(orow + cl) = make_float2(x0, x1);
            }
        }
    }
}

// ---------------- LayerNorm ----------------
__global__ __launch_bounds__(256) void ln_kernel(
    const float* __restrict__ in, const float* __restrict__ g,
    const float* __restrict__ b, float* __restrict__ out)
{
    int row = blockIdx.x;
    int t = threadIdx.x;
    float v = in[(size_t)row * 256 + t];
    __shared__ float red[8];

    float s = v;
    #pragma unroll
    for (int o = 16; o; o >>= 1) s += __shfl_xor_sync(0xffffffffu, s, o);
    if ((t & 31) == 0) red[t >> 5] = s;
    __syncthreads();
    float mean = (red[0] + red[1] + red[2] + red[3] +
                  red[4] + red[5] + red[6] + red[7]) * (1.0f / 256.0f);
    float d = v - mean;
    __syncthreads();
    s = d * d;
    #pragma unroll
    for (int o = 16; o; o >>= 1) s += __shfl_xor_sync(0xffffffffu, s, o);
    if ((t & 31) == 0) red[t >> 5] = s;
    __syncthreads();
    float var = (red[0] + red[1] + red[2] + red[3] +
                 red[4] + red[5] + red[6] + red[7]) * (1.0f / 256.0f);
    out[(size_t)row * 256 + t] = d * rsqrtf(var + 1e-5f) * g[t] + b[t];
}

// ---------------- attention kernel ----------------
__global__ __launch_bounds__(256) void attn_kernel(
    const float* __restrict__ qkv, const float* __restrict__ bias,
    const float* __restrict__ bb, float* __restrict__ o)
{
    extern __shared__ float sm[];
    float (*ks)[33] = (float(*)[33])sm;
    float (*vs)[33] = (float(*)[33])(sm + 256 * 33);
    float (*qs)[33] = (float(*)[33])(sm + 2 * 256 * 33);

    const int tid = threadIdx.x;
    const int tile = blockIdx.x & 7;
    const int bh = blockIdx.x >> 3;
    const int b = bh >> 3, hh = bh & 7;
    const int i0 = tile * 32;
    const float bbv = bb[hh];

    for (int idx = tid; idx < 2048; idx += 256) {
        int j = idx >> 3, q4 = idx & 7;
        const float* base = qkv + (size_t)(b * 256 + j) * 768 + hh * 32 + q4 * 4;
        float4 kk = *(const float4*)(base + 256);
        float4 vv = *(const float4*)(base + 512);
        ks[j][q4 * 4 + 0] = kk.x; ks[j][q4 * 4 + 1] = kk.y;
        ks[j][q4 * 4 + 2] = kk.z; ks[j][q4 * 4 + 3] = kk.w;
        vs[j][q4 * 4 + 0] = vv.x; vs[j][q4 * 4 + 1] = vv.y;
        vs[j][q4 * 4 + 2] = vv.z; vs[j][q4 * 4 + 3] = vv.w;
    }
    for (int idx = tid; idx < 1024; idx += 256) {
        int r = idx >> 5, d = idx & 31;
        qs[r][d] = qkv[(size_t)(b * 256 + i0 + r) * 768 + hh * 32 + d];
    }
    __syncthreads();

    const int r = tid >> 3, s = tid & 7;
    const int i = i0 + r;
    const float* brow = bias + ((((size_t)b * 8 + hh) * 256 + i) << 8);

    float sc[32];
    float mx = -1e30f;
    #pragma unroll
    for (int jj = 0; jj < 32; ++jj) {
        int j = jj * 8 + s;
        float a = 0.0f;
        #pragma unroll
        for (int d = 0; d < 32; ++d) a += qs[r][d] * ks[j][d];
        a = a * 0.17677669529663687f + brow[j] + bbv;
        sc[jj] = a;
        mx = fmaxf(mx, a);
    }
    #pragma unroll
    for (int off = 4; off; off >>= 1)
        mx = fmaxf(mx, __shfl_xor_sync(0xffffffffu, mx, off));

    float sum = 0.0f;
    #pragma unroll
    for (int jj = 0; jj < 32; ++jj) { sc[jj] = expf(sc[jj] - mx); sum += sc[jj]; }
    #pragma unroll
    for (int off = 4; off; off >>= 1)
        sum += __shfl_xor_sync(0xffffffffu, sum, off);
    float inv = 1.0f / sum;

    float oacc[32] = {};
    #pragma unroll
    for (int jj = 0; jj < 32; ++jj) {
        int j = jj * 8 + s;
        float w = sc[jj];
        #pragma unroll
        for (int d = 0; d < 32; ++d) oacc[d] += w * vs[j][d];
    }

    float w4[4];
    #pragma unroll
    for (int d = 0; d < 32; ++d) {
        float t = oacc[d];
        t += __shfl_xor_sync(0xffffffffu, t, 1);
        t += __shfl_xor_sync(0xffffffffu, t, 2);
        t += __shfl_xor_sync(0xffffffffu, t, 4);
        if ((d >> 2) == s) w4[d & 3] = t;
    }
    *(float4*)(o + ((size_t)(b * 256 + i)) * 256 + hh * 32 + s * 4) =
        make_float4(w4[0] * inv, w4[1] * inv, w4[2] * inv, w4[3] * inv);
}

// ---------------- launch ----------------
extern "C" void kernel_launch(void* const* d_in, const int* in_sizes, int n_in,
                              void* d_out, int out_size)
{
    (void)in_sizes; (void)n_in; (void)out_size;
    const float* h    = (const float*)d_in[0];
    const float* e    = (const float*)d_in[1];
    const float* We   = (const float*)d_in[2];
    const float* be   = (const float*)d_in[3];
    const float* Ws   = (const float*)d_in[4];
    const float* bs   = (const float*)d_in[5];
    const float* Wd   = (const float*)d_in[6];
    const float* bd   = (const float*)d_in[7];
    const float* Wb   = (const float*)d_in[8];
    const float* bb   = (const float*)d_in[9];
    const float* ln1g = (const float*)d_in[10];
    const float* ln1b = (const float*)d_in[11];
    const float* Wqkv = (const float*)d_in[12];
    const float* bqkv = (const float*)d_in[13];
    const float* Wo   = (const float*)d_in[14];
    const float* bo   = (const float*)d_in[15];
    const float* ln2g = (const float*)d_in[16];
    const float* ln2b = (const float*)d_in[17];
    const float* W1   = (const float*)d_in[18];
    const float* b1   = (const float*)d_in[19];
    const float* W2   = (const float*)d_in[20];
    const float* b2   = (const float*)d_in[21];

    float* out_h2 = (float*)d_out;
    float* out_e  = out_h2 + (size_t)BN * DD;

    float *pHs, *pHd, *px1, *pqkv, *pbias, *po, *ph1, *py, *pf;
    __half *pWeTh, *pWqkvTh, *pWoTh, *pW1Th, *pW2Th;
    cudaGetSymbolAddress((void**)&pHs,     g_Hs);
    cudaGetSymbolAddress((void**)&pHd,     g_Hd);
    cudaGetSymbolAddress((void**)&px1,     g_x1);
    cudaGetSymbolAddress((void**)&pqkv,    g_qkv);
    cudaGetSymbolAddress((void**)&pbias,   g_bias);
    cudaGetSymbolAddress((void**)&po,      g_o);
    cudaGetSymbolAddress((void**)&ph1,     g_h1);
    cudaGetSymbolAddress((void**)&py,      g_y);
    cudaGetSymbolAddress((void**)&pf,      g_ffn);
    cudaGetSymbolAddress((void**)&pWeTh,   g_WeTh);
    cudaGetSymbolAddress((void**)&pWqkvTh, g_WqkvTh);
    cudaGetSymbolAddress((void**)&pWoTh,   g_WoTh);
    cudaGetSymbolAddress((void**)&pW1Th,   g_W1Th);
    cudaGetSymbolAddress((void**)&pW2Th,   g_W2Th);

    // #1-3: prep (edge kernel is launch #4 so ncu -s captures it)
    transpose_all<<<832, 256>>>(We, Wqkv, Wo, W1, W2,
                                pWeTh, pWqkvTh, pWoTh, pW1Th, pW2Th);
    gemm_hsd<<<dim3(8, 16, 2), 256>>>(h, Ws, bs, Wd, bd, be, pHs, pHd);
    ln_kernel<<<BN, 256>>>(h, ln1g, ln1b, px1);

    // #4: edge update + attention bias (2 CTAs/SM)
    cudaFuncSetAttribute(edge_mma_kernel,
                         cudaFuncAttributeMaxDynamicSharedMemorySize,
                         SM_EDGE_TOTAL);
    edge_mma_kernel<<<4096, 256, SM_EDGE_TOTAL>>>(
        e, pWeTh, pHs, pHd, Wb, out_e, pbias);

    // attention path
    gemm_mma64<0, false><<<dim3(12, 16), 256, 32768>>>(
        px1, pWqkvTh, bqkv, nullptr, pqkv, 256, 768);
    cudaFuncSetAttribute(attn_kernel,
                         cudaFuncAttributeMaxDynamicSharedMemorySize, 73728);
    attn_kernel<<<256, 256, 71808>>>(pqkv, pbias, bb, po);

    // output proj + residual
    gemm_mma64<0, true><<<dim3(4, 16), 256, 32768>>>(
        po, pWoTh, bo, h, ph1, 256, 256);

    // FFN
    ln_kernel<<<BN, 256>>>(ph1, ln2g, ln2b, py);
    gemm_mma64<1, false><<<dim3(16, 16), 256, 32768>>>(
        py, pW1Th, b1, nullptr, pf, 256, 1024);
    gemm_mma64<0, true><<<dim3(4, 16), 256, 32768>>>(
        pf, pW2Th, b2, ph1, out_h2, 1024, 256);
}

// round 12
// speedup vs baseline: 4.5983x; 1.1047x over previous
#include <cuda_runtime.h>
#include <cuda_fp16.h>
#include <math.h>
#include <stdint.h>

// Shapes (fixed): B=4, N=256, D=256, H=8, HD=32, DFF=1024
#define BN 1024
#define DD 256

// ---------------- scratch ----------------
__device__ __align__(16) float  g_Hs[BN * DD];    // Hs + be
__device__ __align__(16) float  g_Hd[BN * DD];
__device__ __align__(16) float  g_x1[BN * DD];
__device__ __align__(16) float  g_qkv[BN * 768];
__device__ __align__(16) float  g_bias[4 * 8 * 256 * 256];
__device__ __align__(16) float  g_o[BN * DD];
__device__ __align__(16) float  g_h1[BN * DD];
__device__ __align__(16) float  g_y[BN * DD];
__device__ __align__(16) float  g_ffn[BN * 1024];
__device__ __align__(16) __half g_WeTh[DD * DD];
__device__ __align__(16) __half g_WqkvTh[768 * DD];
__device__ __align__(16) __half g_WoTh[DD * DD];
__device__ __align__(16) __half g_W1Th[1024 * DD];
__device__ __align__(16) __half g_W2Th[DD * 1024];

// ---------------- helpers ----------------
__device__ __forceinline__ uint32_t smem_u32(const void* p) {
    uint32_t a;
    asm("{ .reg .u64 t; cvta.to.shared.u64 t, %1; cvt.u32.u64 %0, t; }"
        : "=r"(a) : "l"(p));
    return a;
}
__device__ __forceinline__ void cp16(uint32_t dst, const void* src) {
    asm volatile("cp.async.cg.shared.global [%0], [%1], 16;"
                 :: "r"(dst), "l"(src));
}
__device__ __forceinline__ void ldmx4(uint32_t* r, uint32_t addr) {
    asm volatile(
        "ldmatrix.sync.aligned.m8n8.x4.shared.b16 {%0,%1,%2,%3}, [%4];"
        : "=r"(r[0]), "=r"(r[1]), "=r"(r[2]), "=r"(r[3]) : "r"(addr));
}
__device__ __forceinline__ void mma_f16(float* c, const uint32_t* a,
                                        uint32_t b0, uint32_t b1) {
    asm volatile(
        "mma.sync.aligned.m16n8k16.row.col.f32.f16.f16.f32 "
        "{%0,%1,%2,%3}, {%4,%5,%6,%7}, {%8,%9}, {%0,%1,%2,%3};"
        : "+f"(c[0]), "+f"(c[1]), "+f"(c[2]), "+f"(c[3])
        : "r"(a[0]), "r"(a[1]), "r"(a[2]), "r"(a[3]), "r"(b0), "r"(b1));
}
__device__ __forceinline__ uint32_t pack_h2(float x, float y) {
    __half2 h = __float22half2_rn(make_float2(x, y));
    return *reinterpret_cast<uint32_t*>(&h);
}
__device__ __forceinline__ float gelu_exact(float x) {
    return 0.5f * x * (1.0f + erff(x * 0.70710678118654752f));
}

// ---------------- tiled weight transpose+fp16 (coalesced) ----------------
__global__ __launch_bounds__(256) void transpose_all(
    const float* __restrict__ We,  const float* __restrict__ Wqkv,
    const float* __restrict__ Wo,  const float* __restrict__ W1,
    const float* __restrict__ W2,
    __half* __restrict__ oWe,  __half* __restrict__ oWqkv,
    __half* __restrict__ oWo,  __half* __restrict__ oW1,
    __half* __restrict__ oW2)
{
    __shared__ float s[32][33];
    int bid = blockIdx.x;
    const float* in; __half* out; int K, N, t;
    if (bid < 64)        { in = We;   out = oWe;   K = 256;  N = 256;  t = bid; }
    else if (bid < 256)  { in = Wqkv; out = oWqkv; K = 256;  N = 768;  t = bid - 64; }
    else if (bid < 320)  { in = Wo;   out = oWo;   K = 256;  N = 256;  t = bid - 256; }
    else if (bid < 576)  { in = W1;   out = oW1;   K = 256;  N = 1024; t = bid - 320; }
    else                 { in = W2;   out = oW2;   K = 1024; N = 256;  t = bid - 576; }
    const int ntn = N >> 5;
    const int k0 = (t / ntn) << 5, n0 = (t % ntn) << 5;
    const int r = threadIdx.x >> 5, c = threadIdx.x & 31;
    #pragma unroll
    for (int q = 0; q < 4; ++q)
        s[r + q * 8][c] = in[(size_t)(k0 + r + q * 8) * N + n0 + c];
    __syncthreads();
    #pragma unroll
    for (int q = 0; q < 4; ++q)
        out[(size_t)(n0 + r + q * 8) * K + k0 + c] =
            __float2half_rn(s[c][r + q * 8]);
}

// ---------------- dual GEMM: Hs(+be) and Hd, both fp32 ----------------
__global__ __launch_bounds__(256) void gemm_hsd(
    const float* __restrict__ A,
    const float* __restrict__ Ws, const float* __restrict__ bs,
    const float* __restrict__ Wd, const float* __restrict__ bd,
    const float* __restrict__ be,
    float* __restrict__ oHs, float* __restrict__ oHd)
{
    const float* W    = blockIdx.z ? Wd : Ws;
    const float* bias = blockIdx.z ? bd : bs;
    float* out        = blockIdx.z ? oHd : oHs;

    __shared__ float As[64][16];
    __shared__ float Bs[16][32];
    const int tid = threadIdx.x;
    const int m0 = blockIdx.y * 64;
    const int c0 = blockIdx.x * 32;
    const int ty = tid >> 3;
    const int tx = tid & 7;

    float acc[2][4] = {};

    for (int k0 = 0; k0 < 256; k0 += 16) {
        {
            int r = tid >> 2, q = tid & 3;
            *(float4*)&As[r][q * 4] =
                *(const float4*)(A + (size_t)(m0 + r) * 256 + k0 + q * 4);
        }
        if (tid < 128) {
            int kk = tid >> 3, q = tid & 7;
            *(float4*)&Bs[kk][q * 4] =
                *(const float4*)(W + (size_t)(k0 + kk) * 256 + c0 + q * 4);
        }
        __syncthreads();
        #pragma unroll
        for (int k = 0; k < 16; ++k) {
            float a0 = As[ty * 2][k];
            float a1 = As[ty * 2 + 1][k];
            float4 bv = *(float4*)&Bs[k][tx * 4];
            acc[0][0] += a0 * bv.x; acc[0][1] += a0 * bv.y;
            acc[0][2] += a0 * bv.z; acc[0][3] += a0 * bv.w;
            acc[1][0] += a1 * bv.x; acc[1][1] += a1 * bv.y;
            acc[1][2] += a1 * bv.z; acc[1][3] += a1 * bv.w;
        }
        __syncthreads();
    }

    float4 bs4 = *(const float4*)(bias + c0 + tx * 4);
    if (blockIdx.z == 0) {
        float4 be4 = *(const float4*)(be + c0 + tx * 4);
        bs4.x += be4.x; bs4.y += be4.y; bs4.z += be4.z; bs4.w += be4.w;
    }
    #pragma unroll
    for (int r = 0; r < 2; ++r) {
        int m = m0 + ty * 2 + r;
        *(float4*)(out + (size_t)m * 256 + c0 + tx * 4) =
            make_float4(acc[r][0] + bs4.x, acc[r][1] + bs4.y,
                        acc[r][2] + bs4.z, acc[r][3] + bs4.w);
    }
}

// ---------------- edge kernel: 64x256 tile, 256 thr, 2 CTAs/SM ----------
// smem: B 2x32KB @0 (reused as 32KB epilogue staging), A 2x8KB @65536,
//       sHs @81920, sbias @82944
#define SB_B     0
#define SB_A     65536
#define SM_SHS   81920
#define SM_SBIAS 82944
#define SM_EDGE_TOTAL 91136

__global__ __launch_bounds__(256, 2) void edge_mma_kernel(
    const float* __restrict__ e, const __half* __restrict__ WeTh,
    const float* __restrict__ Hs, const float* __restrict__ Hd,
    const float* __restrict__ Wb,
    float* __restrict__ e_new, float* __restrict__ bias)
{
    extern __shared__ char smem[];
    const uint32_t sb = smem_u32(smem);
    float* sHs   = (float*)(smem + SM_SHS);
    float* sbias = (float*)(smem + SM_SBIAS);

    const int tid = threadIdx.x;
    const int w = tid >> 5, lane = tid & 31;
    const int g = lane >> 2, tig = lane & 3, x7 = lane & 7;
    const int wr = w >> 2, wc = w & 3;     // 2 row-groups x 4 col-groups

    const int m0 = blockIdx.x * 64;
    const int b = m0 >> 16, i = (m0 >> 8) & 255, j0 = m0 & 255;

    // ---- B chunk 0 (256 n-rows x 64 k) via cp.async ----
    #pragma unroll
    for (int it = 0; it < 8; ++it) {
        int idx = tid + it * 256;
        int r = idx >> 3, ch = idx & 7;
        cp16(sb + SB_B + r * 128 + ((ch ^ (r & 7)) << 4),
             WeTh + (size_t)r * 256 + ch * 8);
    }
    asm volatile("cp.async.commit_group;");

    // ---- A chunk 0: LDG fp32 -> fp16 STS (64 rows x 64 k) ----
    const float* Ab = e + (size_t)m0 * 256;
    #pragma unroll
    for (int p = 0; p < 2; ++p) {
        int idx = tid + p * 256;
        int row = idx >> 3, seg = idx & 7;
        const float* ptr = Ab + (size_t)row * 256 + seg * 8;
        float4 v0 = *(const float4*)ptr;
        float4 v1 = *(const float4*)(ptr + 4);
        uint4 u = make_uint4(pack_h2(v0.x, v0.y), pack_h2(v0.z, v0.w),
                             pack_h2(v1.x, v1.y), pack_h2(v1.z, v1.w));
        *(uint4*)(smem + SB_A + row * 128 + ((seg ^ (row & 7)) << 4)) = u;
    }

    // ---- tables ----
    sHs[tid] = Hs[(((size_t)(b << 8) + i) << 8) + tid];   // be pre-folded

    asm volatile("cp.async.wait_group 0;" ::: "memory");
    __syncthreads();

    const int rowoffA = x7 + (((lane >> 3) & 1) << 3);
    const int selA = lane >> 4;
    const int rowoffB = x7 + ((lane >> 4) << 3);
    const int selB = (lane >> 3) & 1;

    float acc[2][8][4] = {};
    float4 pre[4];

    for (int c = 0; c < 4; ++c) {
        if (c < 3) {
            // B prefetch to stage^1
            #pragma unroll
            for (int it = 0; it < 8; ++it) {
                int idx = tid + it * 256;
                int r = idx >> 3, ch = idx & 7;
                cp16(sb + SB_B + (((c + 1) & 1) << 15) + r * 128 +
                         ((ch ^ (r & 7)) << 4),
                     WeTh + (size_t)r * 256 + (c + 1) * 64 + ch * 8);
            }
            asm volatile("cp.async.commit_group;");
            // A prefetch to regs
            #pragma unroll
            for (int p = 0; p < 2; ++p) {
                int idx = tid + p * 256;
                int row = idx >> 3, seg = idx & 7;
                const float* ptr =
                    Ab + (size_t)row * 256 + (c + 1) * 64 + seg * 8;
                pre[p * 2]     = *(const float4*)ptr;
                pre[p * 2 + 1] = *(const float4*)(ptr + 4);
            }
        }
        const uint32_t sAc = sb + SB_A + ((c & 1) << 13);
        const uint32_t sBc = sb + SB_B + ((c & 1) << 15);
        #pragma unroll
        for (int kk = 0; kk < 4; ++kk) {
            uint32_t a0[4], a1[4];
            {
                int rowA = wr * 32 + rowoffA;
                ldmx4(a0, sAc + rowA * 128 + ((((kk << 1) + selA) ^ x7) << 4));
                ldmx4(a1, sAc + (rowA + 16) * 128 +
                              ((((kk << 1) + selA) ^ x7) << 4));
            }
            uint32_t bf[4][4];
            #pragma unroll
            for (int nt2 = 0; nt2 < 4; ++nt2) {
                int rowB = wc * 64 + nt2 * 16 + rowoffB;
                ldmx4(bf[nt2], sBc + rowB * 128 +
                               ((((kk << 1) + selB) ^ x7) << 4));
            }
            #pragma unroll
            for (int nt2 = 0; nt2 < 4; ++nt2) {
                mma_f16(acc[0][nt2 * 2],     a0, bf[nt2][0], bf[nt2][1]);
                mma_f16(acc[0][nt2 * 2 + 1], a0, bf[nt2][2], bf[nt2][3]);
                mma_f16(acc[1][nt2 * 2],     a1, bf[nt2][0], bf[nt2][1]);
                mma_f16(acc[1][nt2 * 2 + 1], a1, bf[nt2][2], bf[nt2][3]);
            }
        }
        __syncthreads();
        if (c < 3) {
            char* dst = smem + SB_A + (((c + 1) & 1) << 13);
            #pragma unroll
            for (int p = 0; p < 2; ++p) {
                int idx = tid + p * 256;
                int row = idx >> 3, seg = idx & 7;
                float4 v0 = pre[p * 2], v1 = pre[p * 2 + 1];
                uint4 u = make_uint4(pack_h2(v0.x, v0.y), pack_h2(v0.z, v0.w),
                                     pack_h2(v1.x, v1.y), pack_h2(v1.z, v1.w));
                *(uint4*)(dst + row * 128 + ((seg ^ (row & 7)) << 4)) = u;
            }
            asm volatile("cp.async.wait_group 0;" ::: "memory");
            __syncthreads();
        }
    }
    __syncthreads();   // B stage buffers (64KB @0) now dead -> reuse as staging

    // ---- Wb B-fragments for pass C (per warp: k-half slice) ----
    const int mtile = w >> 1, khalf = w & 1;
    uint32_t bw0[8], bw1[8];
    #pragma unroll
    for (int kc = 0; kc < 8; ++kc) {
        int k0 = khalf * 128 + kc * 16 + 2 * tig;
        bw0[kc] = pack_h2(Wb[(k0    ) * 8 + g], Wb[(k0 + 1) * 8 + g]);
        bw1[kc] = pack_h2(Wb[(k0 + 8) * 8 + g], Wb[(k0 + 9) * 8 + g]);
    }

    // ---- pass A: stage fp16(acc + Hs) into SB_B, swizzled ----
    char* stg = smem + SB_B;     // 64 rows x 512B = 32KB, fits the 64KB region
    #pragma unroll
    for (int mt = 0; mt < 2; ++mt) {
        const int rl = wr * 32 + mt * 16 + g;   // rl & 7 == g
        #pragma unroll
        for (int nt = 0; nt < 8; ++nt) {
            const int cl = wc * 64 + nt * 8 + 2 * tig;
            float2 hs = *(const float2*)(sHs + cl);
            uint32_t u0 = pack_h2(acc[mt][nt][0] + hs.x, acc[mt][nt][1] + hs.y);
            uint32_t u1 = pack_h2(acc[mt][nt][2] + hs.x, acc[mt][nt][3] + hs.y);
            const int chunk = wc * 8 + nt;
            *(uint32_t*)(stg + rl * 512 + ((chunk ^ g) << 4) + 4 * tig) = u0;
            *(uint32_t*)(stg + (rl + 8) * 512 + ((chunk ^ g) << 4) + 4 * tig) = u1;
        }
    }
    __syncthreads();

    // ---- pass B: coalesced +Hd, ReLU, e_new store; relu'd fp16 in place --
    {
        const float* hdb = Hd + (((size_t)(b << 8) + j0) << 8);
        float* eb = e_new + (size_t)m0 * 256;
        #pragma unroll
        for (int p = 0; p < 16; ++p) {
            int idx = p * 256 + tid;
            int r = idx >> 6, c4 = idx & 63;
            uint32_t soff = r * 512 + (((c4 >> 1) ^ (r & 7)) << 4) + (c4 & 1) * 8;
            uint2 hv = *(uint2*)(stg + soff);
            float2 f0 = __half22float2(*(__half2*)&hv.x);
            float2 f1 = __half22float2(*(__half2*)&hv.y);
            float4 hd4 = *(const float4*)(hdb + (size_t)r * 256 + c4 * 4);
            float x0 = fmaxf(f0.x + hd4.x, 0.0f);
            float x1 = fmaxf(f0.y + hd4.y, 0.0f);
            float x2 = fmaxf(f1.x + hd4.z, 0.0f);
            float x3 = fmaxf(f1.y + hd4.w, 0.0f);
            *(float4*)(eb + (size_t)r * 256 + c4 * 4) =
                make_float4(x0, x1, x2, x3);
            uint2 wb;
            wb.x = pack_h2(x0, x1);
            wb.y = pack_h2(x2, x3);
            *(uint2*)(stg + soff) = wb;
        }
    }
    __syncthreads();

    // ---- pass C: bias = relu'd x @ Wb via mma from staging ----
    {
        float bc4[4] = {0.0f, 0.0f, 0.0f, 0.0f};
        #pragma unroll
        for (int kk = 0; kk < 8; ++kk) {
            uint32_t a[4];
            int rowA = mtile * 16 + rowoffA;
            ldmx4(a, sb + SB_B + rowA * 512 +
                     (((khalf * 16 + kk * 2 + selA) ^ x7) << 4));
            mma_f16(bc4, a, bw0[kk], bw1[kk]);
        }
        float* sbw = sbias + khalf * 512;
        int rl = mtile * 16 + g;
        sbw[rl * 8 + 2 * tig]           = bc4[0];
        sbw[rl * 8 + 2 * tig + 1]       = bc4[1];
        sbw[(rl + 8) * 8 + 2 * tig]     = bc4[2];
        sbw[(rl + 8) * 8 + 2 * tig + 1] = bc4[3];
    }
    __syncthreads();
    #pragma unroll
    for (int q = 0; q < 2; ++q) {
        int t = tid + q * 256;
        int r = t & 63, hh = t >> 6;
        float v = sbias[r * 8 + hh] + sbias[512 + r * 8 + hh];
        bias[((((size_t)b * 8 + hh) * 256 + i) << 8) + j0 + r] = v;
    }
}

// ---------------- fp16 MMA GEMM: 64x64 tile, 256 thr (8 warps 2x4) ------
template <int OP, bool RES>
__global__ __launch_bounds__(256) void gemm_mma64(
    const float* __restrict__ A, const __half* __restrict__ Wh,
    const float* __restrict__ bias, const float* __restrict__ res,
    float* __restrict__ out, int K, int N)
{
    extern __shared__ char sm2[];
    const uint32_t sb = smem_u32(sm2);
    const int tid = threadIdx.x;
    const int w = tid >> 5, lane = tid & 31;
    const int g = lane >> 2, tig = lane & 3, x7 = lane & 7;
    const int wr = w >> 2, wc = w & 3;
    const int m0 = blockIdx.y * 64, n0 = blockIdx.x * 64;
    const int NC = K >> 6;

    const float*  Ab = A + (size_t)m0 * K;
    const __half* Bb = Wh + (size_t)n0 * K;
    const int arow = tid >> 2;
    const int cpair = tid & 3;

    #pragma unroll
    for (int p = 0; p < 2; ++p) {
        int idx = tid + p * 256;
        int r = idx >> 3, ch = idx & 7;
        cp16(sb + 16384 + r * 128 + ((ch ^ (r & 7)) << 4),
             Bb + (size_t)r * K + ch * 8);
    }
    asm volatile("cp.async.commit_group;");
    #pragma unroll
    for (int q = 0; q < 2; ++q) {
        int ch = cpair * 2 + q;
        const float* p = Ab + (size_t)arow * K + ch * 8;
        float4 v0 = *(const float4*)p;
        float4 v1 = *(const float4*)(p + 4);
        uint4 u = make_uint4(pack_h2(v0.x, v0.y), pack_h2(v0.z, v0.w),
                             pack_h2(v1.x, v1.y), pack_h2(v1.z, v1.w));
        *(uint4*)(sm2 + arow * 128 + ((ch ^ (arow & 7)) << 4)) = u;
    }
    asm volatile("cp.async.wait_group 0;" ::: "memory");
    __syncthreads();

    const int rowoffA = x7 + (((lane >> 3) & 1) << 3);
    const int selA = lane >> 4;
    const int rowoffB = x7 + ((lane >> 4) << 3);
    const int selB = (lane >> 3) & 1;

    float acc[2][2][4] = {};
    float4 pre[4];

    for (int c = 0; c < NC; ++c) {
        if (c + 1 < NC) {
            #pragma unroll
            for (int p = 0; p < 2; ++p) {
                int idx = tid + p * 256;
                int r = idx >> 3, ch = idx & 7;
                cp16(sb + 16384 + (((c + 1) & 1) << 13) + r * 128 +
                         ((ch ^ (r & 7)) << 4),
                     Bb + (size_t)r * K + (c + 1) * 64 + ch * 8);
            }
            asm volatile("cp.async.commit_group;");
            #pragma unroll
            for (int q = 0; q < 2; ++q) {
                int ch = cpair * 2 + q;
                const float* p = Ab + (size_t)arow * K + (c + 1) * 64 + ch * 8;
                pre[q * 2]     = *(const float4*)p;
                pre[q * 2 + 1] = *(const float4*)(p + 4);
            }
        }
        const uint32_t sA = sb + ((c & 1) << 13);
        const uint32_t sB = sb + 16384 + ((c & 1) << 13);
        #pragma unroll
        for (int kk = 0; kk < 4; ++kk) {
            uint32_t a0[4], a1[4];
            int rA = wr * 32 + rowoffA;
            ldmx4(a0, sA + rA * 128 + ((((kk << 1) + selA) ^ x7) << 4));
            ldmx4(a1, sA + (rA + 16) * 128 + ((((kk << 1) + selA) ^ x7) << 4));
            uint32_t bf[4];
            int rB = wc * 16 + rowoffB;
            ldmx4(bf, sB + rB * 128 + ((((kk << 1) + selB) ^ x7) << 4));
            mma_f16(acc[0][0], a0, bf[0], bf[1]);
            mma_f16(acc[0][1], a0, bf[2], bf[3]);
            mma_f16(acc[1][0], a1, bf[0], bf[1]);
            mma_f16(acc[1][1], a1, bf[2], bf[3]);
        }
        __syncthreads();
        if (c + 1 < NC) {
            char* dst = sm2 + (((c + 1) & 1) << 13);
            #pragma unroll
            for (int q = 0; q < 2; ++q) {
                int ch = cpair * 2 + q;
                float4 v0 = pre[q * 2], v1 = pre[q * 2 + 1];
                uint4 u = make_uint4(pack_h2(v0.x, v0.y), pack_h2(v0.z, v0.w),
                                     pack_h2(v1.x, v1.y), pack_h2(v1.z, v1.w));
                *(uint4*)(dst + arow * 128 + ((ch ^ (arow & 7)) << 4)) = u;
            }
            asm volatile("cp.async.wait_group 0;" ::: "memory");
            __syncthreads();
        }
    }

    #pragma unroll
    for (int mt = 0; mt < 2; ++mt) {
        #pragma unroll
        for (int rh = 0; rh < 2; ++rh) {
            int rl = wr * 32 + mt * 16 + rh * 8 + g;
            float* orow = out + (size_t)(m0 + rl) * N + n0;
            const float* rrow = RES ? res + (size_t)(m0 + rl) * N + n0 : nullptr;
            #pragma unroll
            for (int nh = 0; nh < 2; ++nh) {
                int cl = wc * 16 + nh * 8 + 2 * tig;
                float x0 = acc[mt][nh][rh * 2 + 0] + __ldg(bias + n0 + cl);
                float x1 = acc[mt][nh][rh * 2 + 1] + __ldg(bias + n0 + cl + 1);
                if (OP == 1) { x0 = gelu_exact(x0); x1 = gelu_exact(x1); }
                if (RES) {
                    float2 rv = *(const float2*)(rrow + cl);
                    x0 += rv.x; x1 += rv.y;
                }
                *(float2*)(orow + cl) = make_float2(x0, x1);
            }
        }
    }
}

// ---------------- LayerNorm ----------------
__global__ __launch_bounds__(256) void ln_kernel(
    const float* __restrict__ in, const float* __restrict__ g,
    const float* __restrict__ b, float* __restrict__ out)
{
    int row = blockIdx.x;
    int t = threadIdx.x;
    float v = in[(size_t)row * 256 + t];
    __shared__ float red[8];

    float s = v;
    #pragma unroll
    for (int o = 16; o; o >>= 1) s += __shfl_xor_sync(0xffffffffu, s, o);
    if ((t & 31) == 0) red[t >> 5] = s;
    __syncthreads();
    float mean = (red[0] + red[1] + red[2] + red[3] +
                  red[4] + red[5] + red[6] + red[7]) * (1.0f / 256.0f);
    float d = v - mean;
    __syncthreads();
    s = d * d;
    #pragma unroll
    for (int o = 16; o; o >>= 1) s += __shfl_xor_sync(0xffffffffu, s, o);
    if ((t & 31) == 0) red[t >> 5] = s;
    __syncthreads();
    float var = (red[0] + red[1] + red[2] + red[3] +
                 red[4] + red[5] + red[6] + red[7]) * (1.0f / 256.0f);
    out[(size_t)row * 256 + t] = d * rsqrtf(var + 1e-5f) * g[t] + b[t];
}

// ---------------- attention kernel ----------------
__global__ __launch_bounds__(256) void attn_kernel(
    const float* __restrict__ qkv, const float* __restrict__ bias,
    const float* __restrict__ bb, float* __restrict__ o)
{
    extern __shared__ float sm[];
    float (*ks)[33] = (float(*)[33])sm;
    float (*vs)[33] = (float(*)[33])(sm + 256 * 33);
    float (*qs)[33] = (float(*)[33])(sm + 2 * 256 * 33);

    const int tid = threadIdx.x;
    const int tile = blockIdx.x & 7;
    const int bh = blockIdx.x >> 3;
    const int b = bh >> 3, hh = bh & 7;
    const int i0 = tile * 32;
    const float bbv = bb[hh];

    for (int idx = tid; idx < 2048; idx += 256) {
        int j = idx >> 3, q4 = idx & 7;
        const float* base = qkv + (size_t)(b * 256 + j) * 768 + hh * 32 + q4 * 4;
        float4 kk = *(const float4*)(base + 256);
        float4 vv = *(const float4*)(base + 512);
        ks[j][q4 * 4 + 0] = kk.x; ks[j][q4 * 4 + 1] = kk.y;
        ks[j][q4 * 4 + 2] = kk.z; ks[j][q4 * 4 + 3] = kk.w;
        vs[j][q4 * 4 + 0] = vv.x; vs[j][q4 * 4 + 1] = vv.y;
        vs[j][q4 * 4 + 2] = vv.z; vs[j][q4 * 4 + 3] = vv.w;
    }
    for (int idx = tid; idx < 1024; idx += 256) {
        int r = idx >> 5, d = idx & 31;
        qs[r][d] = qkv[(size_t)(b * 256 + i0 + r) * 768 + hh * 32 + d];
    }
    __syncthreads();

    const int r = tid >> 3, s = tid & 7;
    const int i = i0 + r;
    const float* brow = bias + ((((size_t)b * 8 + hh) * 256 + i) << 8);

    float sc[32];
    float mx = -1e30f;
    #pragma unroll
    for (int jj = 0; jj < 32; ++jj) {
        int j = jj * 8 + s;
        float a = 0.0f;
        #pragma unroll
        for (int d = 0; d < 32; ++d) a += qs[r][d] * ks[j][d];
        a = a * 0.17677669529663687f + brow[j] + bbv;
        sc[jj] = a;
        mx = fmaxf(mx, a);
    }
    #pragma unroll
    for (int off = 4; off; off >>= 1)
        mx = fmaxf(mx, __shfl_xor_sync(0xffffffffu, mx, off));

    float sum = 0.0f;
    #pragma unroll
    for (int jj = 0; jj < 32; ++jj) { sc[jj] = expf(sc[jj] - mx); sum += sc[jj]; }
    #pragma unroll
    for (int off = 4; off; off >>= 1)
        sum += __shfl_xor_sync(0xffffffffu, sum, off);
    float inv = 1.0f / sum;

    float oacc[32] = {};
    #pragma unroll
    for (int jj = 0; jj < 32; ++jj) {
        int j = jj * 8 + s;
        float w = sc[jj];
        #pragma unroll
        for (int d = 0; d < 32; ++d) oacc[d] += w * vs[j][d];
    }

    float w4[4];
    #pragma unroll
    for (int d = 0; d < 32; ++d) {
        float t = oacc[d];
        t += __shfl_xor_sync(0xffffffffu, t, 1);
        t += __shfl_xor_sync(0xffffffffu, t, 2);
        t += __shfl_xor_sync(0xffffffffu, t, 4);
        if ((d >> 2) == s) w4[d & 3] = t;
    }
    *(float4*)(o + ((size_t)(b * 256 + i)) * 256 + hh * 32 + s * 4) =
        make_float4(w4[0] * inv, w4[1] * inv, w4[2] * inv, w4[3] * inv);
}

// ---------------- launch ----------------
extern "C" void kernel_launch(void* const* d_in, const int* in_sizes, int n_in,
                              void* d_out, int out_size)
{
    (void)in_sizes; (void)n_in; (void)out_size;
    const float* h    = (const float*)d_in[0];
    const float* e    = (const float*)d_in[1];
    const float* We   = (const float*)d_in[2];
    const float* be   = (const float*)d_in[3];
    const float* Ws   = (const float*)d_in[4];
    const float* bs   = (const float*)d_in[5];
    const float* Wd   = (const float*)d_in[6];
    const float* bd   = (const float*)d_in[7];
    const float* Wb   = (const float*)d_in[8];
    const float* bb   = (const float*)d_in[9];
    const float* ln1g = (const float*)d_in[10];
    const float* ln1b = (const float*)d_in[11];
    const float* Wqkv = (const float*)d_in[12];
    const float* bqkv = (const float*)d_in[13];
    const float* Wo   = (const float*)d_in[14];
    const float* bo   = (const float*)d_in[15];
    const float* ln2g = (const float*)d_in[16];
    const float* ln2b = (const float*)d_in[17];
    const float* W1   = (const float*)d_in[18];
    const float* b1   = (const float*)d_in[19];
    const float* W2   = (const float*)d_in[20];
    const float* b2   = (const float*)d_in[21];

    float* out_h2 = (float*)d_out;
    float* out_e  = out_h2 + (size_t)BN * DD;

    float *pHs, *pHd, *px1, *pqkv, *pbias, *po, *ph1, *py, *pf;
    __half *pWeTh, *pWqkvTh, *pWoTh, *pW1Th, *pW2Th;
    cudaGetSymbolAddress((void**)&pHs,     g_Hs);
    cudaGetSymbolAddress((void**)&pHd,     g_Hd);
    cudaGetSymbolAddress((void**)&px1,     g_x1);
    cudaGetSymbolAddress((void**)&pqkv,    g_qkv);
    cudaGetSymbolAddress((void**)&pbias,   g_bias);
    cudaGetSymbolAddress((void**)&po,      g_o);
    cudaGetSymbolAddress((void**)&ph1,     g_h1);
    cudaGetSymbolAddress((void**)&py,      g_y);
    cudaGetSymbolAddress((void**)&pf,      g_ffn);
    cudaGetSymbolAddress((void**)&pWeTh,   g_WeTh);
    cudaGetSymbolAddress((void**)&pWqkvTh, g_WqkvTh);
    cudaGetSymbolAddress((void**)&pWoTh,   g_WoTh);
    cudaGetSymbolAddress((void**)&pW1Th,   g_W1Th);
    cudaGetSymbolAddress((void**)&pW2Th,   g_W2Th);

    // #1-3: prep (edge kernel is launch #4 so ncu -s captures it)
    transpose_all<<<832, 256>>>(We, Wqkv, Wo, W1, W2,
                                pWeTh, pWqkvTh, pWoTh, pW1Th, pW2Th);
    gemm_hsd<<<dim3(8, 16, 2), 256>>>(h, Ws, bs, Wd, bd, be, pHs, pHd);
    ln_kernel<<<BN, 256>>>(h, ln1g, ln1b, px1);

    // #4: edge update + attention bias (2 CTAs/SM)
    cudaFuncSetAttribute(edge_mma_kernel,
                         cudaFuncAttributeMaxDynamicSharedMemorySize,
                         SM_EDGE_TOTAL);
    edge_mma_kernel<<<4096, 256, SM_EDGE_TOTAL>>>(
        e, pWeTh, pHs, pHd, Wb, out_e, pbias);

    // attention path
    gemm_mma64<0, false><<<dim3(12, 16), 256, 32768>>>(
        px1, pWqkvTh, bqkv, nullptr, pqkv, 256, 768);
    cudaFuncSetAttribute(attn_kernel,
                         cudaFuncAttributeMaxDynamicSharedMemorySize, 73728);
    attn_kernel<<<256, 256, 71808>>>(pqkv, pbias, bb, po);

    // output proj + residual
    gemm_mma64<0, true><<<dim3(4, 16), 256, 32768>>>(
        po, pWoTh, bo, h, ph1, 256, 256);

    // FFN
    ln_kernel<<<BN, 256>>>(ph1, ln2g, ln2b, py);
    gemm_mma64<1, false><<<dim3(16, 16), 256, 32768>>>(
        py, pW1Th, b1, nullptr, pf, 256, 1024);
    gemm_mma64<0, true><<<dim3(4, 16), 256, 32768>>>(
        pf, pW2Th, b2, ph1, out_h2, 1024, 256);
}

// round 13
// speedup vs baseline: 4.7208x; 1.0266x over previous
#include <cuda_runtime.h>
#include <cuda_fp16.h>
#include <math.h>
#include <stdint.h>

// Shapes (fixed): B=4, N=256, D=256, H=8, HD=32, DFF=1024
#define BN 1024
#define DD 256

// ---------------- scratch ----------------
__device__ __align__(16) float  g_Hs[BN * DD];    // Hs + be
__device__ __align__(16) float  g_Hd[BN * DD];
__device__ __align__(16) float  g_x1[BN * DD];
__device__ __align__(16) float  g_qkv[BN * 768];
__device__ __align__(16) float  g_bias[4 * 8 * 256 * 256];
__device__ __align__(16) float  g_o[BN * DD];
__device__ __align__(16) float  g_h1[BN * DD];
__device__ __align__(16) float  g_y[BN * DD];
__device__ __align__(16) float  g_ffn[BN * 1024];
__device__ __align__(16) __half g_WeTh[DD * DD];
__device__ __align__(16) __half g_WqkvTh[768 * DD];
__device__ __align__(16) __half g_WoTh[DD * DD];
__device__ __align__(16) __half g_W1Th[1024 * DD];
__device__ __align__(16) __half g_W2Th[DD * 1024];

// ---------------- helpers ----------------
__device__ __forceinline__ uint32_t smem_u32(const void* p) {
    uint32_t a;
    asm("{ .reg .u64 t; cvta.to.shared.u64 t, %1; cvt.u32.u64 %0, t; }"
        : "=r"(a) : "l"(p));
    return a;
}
__device__ __forceinline__ void cp16(uint32_t dst, const void* src) {
    asm volatile("cp.async.cg.shared.global [%0], [%1], 16;"
                 :: "r"(dst), "l"(src));
}
__device__ __forceinline__ void ldmx4(uint32_t* r, uint32_t addr) {
    asm volatile(
        "ldmatrix.sync.aligned.m8n8.x4.shared.b16 {%0,%1,%2,%3}, [%4];"
        : "=r"(r[0]), "=r"(r[1]), "=r"(r[2]), "=r"(r[3]) : "r"(addr));
}
__device__ __forceinline__ void mma_f16(float* c, const uint32_t* a,
                                        uint32_t b0, uint32_t b1) {
    asm volatile(
        "mma.sync.aligned.m16n8k16.row.col.f32.f16.f16.f32 "
        "{%0,%1,%2,%3}, {%4,%5,%6,%7}, {%8,%9}, {%0,%1,%2,%3};"
        : "+f"(c[0]), "+f"(c[1]), "+f"(c[2]), "+f"(c[3])
        : "r"(a[0]), "r"(a[1]), "r"(a[2]), "r"(a[3]), "r"(b0), "r"(b1));
}
__device__ __forceinline__ uint32_t pack_h2(float x, float y) {
    __half2 h = __float22half2_rn(make_float2(x, y));
    return *reinterpret_cast<uint32_t*>(&h);
}
__device__ __forceinline__ float gelu_exact(float x) {
    return 0.5f * x * (1.0f + erff(x * 0.70710678118654752f));
}

// ---------------- tiled weight transpose+fp16 (coalesced) ----------------
__global__ __launch_bounds__(256) void transpose_all(
    const float* __restrict__ We,  const float* __restrict__ Wqkv,
    const float* __restrict__ Wo,  const float* __restrict__ W1,
    const float* __restrict__ W2,
    __half* __restrict__ oWe,  __half* __restrict__ oWqkv,
    __half* __restrict__ oWo,  __half* __restrict__ oW1,
    __half* __restrict__ oW2)
{
    __shared__ float s[32][33];
    int bid = blockIdx.x;
    const float* in; __half* out; int K, N, t;
    if (bid < 64)        { in = We;   out = oWe;   K = 256;  N = 256;  t = bid; }
    else if (bid < 256)  { in = Wqkv; out = oWqkv; K = 256;  N = 768;  t = bid - 64; }
    else if (bid < 320)  { in = Wo;   out = oWo;   K = 256;  N = 256;  t = bid - 256; }
    else if (bid < 576)  { in = W1;   out = oW1;   K = 256;  N = 1024; t = bid - 320; }
    else                 { in = W2;   out = oW2;   K = 1024; N = 256;  t = bid - 576; }
    const int ntn = N >> 5;
    const int k0 = (t / ntn) << 5, n0 = (t % ntn) << 5;
    const int r = threadIdx.x >> 5, c = threadIdx.x & 31;
    #pragma unroll
    for (int q = 0; q < 4; ++q)
        s[r + q * 8][c] = in[(size_t)(k0 + r + q * 8) * N + n0 + c];
    __syncthreads();
    #pragma unroll
    for (int q = 0; q < 4; ++q)
        out[(size_t)(n0 + r + q * 8) * K + k0 + c] =
            __float2half_rn(s[c][r + q * 8]);
}

// ---------------- dual GEMM: Hs(+be) and Hd, both fp32 ----------------
__global__ __launch_bounds__(256) void gemm_hsd(
    const float* __restrict__ A,
    const float* __restrict__ Ws, const float* __restrict__ bs,
    const float* __restrict__ Wd, const float* __restrict__ bd,
    const float* __restrict__ be,
    float* __restrict__ oHs, float* __restrict__ oHd)
{
    const float* W    = blockIdx.z ? Wd : Ws;
    const float* bias = blockIdx.z ? bd : bs;
    float* out        = blockIdx.z ? oHd : oHs;

    __shared__ float As[64][16];
    __shared__ float Bs[16][32];
    const int tid = threadIdx.x;
    const int m0 = blockIdx.y * 64;
    const int c0 = blockIdx.x * 32;
    const int ty = tid >> 3;
    const int tx = tid & 7;

    float acc[2][4] = {};

    for (int k0 = 0; k0 < 256; k0 += 16) {
        {
            int r = tid >> 2, q = tid & 3;
            *(float4*)&As[r][q * 4] =
                *(const float4*)(A + (size_t)(m0 + r) * 256 + k0 + q * 4);
        }
        if (tid < 128) {
            int kk = tid >> 3, q = tid & 7;
            *(float4*)&Bs[kk][q * 4] =
                *(const float4*)(W + (size_t)(k0 + kk) * 256 + c0 + q * 4);
        }
        __syncthreads();
        #pragma unroll
        for (int k = 0; k < 16; ++k) {
            float a0 = As[ty * 2][k];
            float a1 = As[ty * 2 + 1][k];
            float4 bv = *(float4*)&Bs[k][tx * 4];
            acc[0][0] += a0 * bv.x; acc[0][1] += a0 * bv.y;
            acc[0][2] += a0 * bv.z; acc[0][3] += a0 * bv.w;
            acc[1][0] += a1 * bv.x; acc[1][1] += a1 * bv.y;
            acc[1][2] += a1 * bv.z; acc[1][3] += a1 * bv.w;
        }
        __syncthreads();
    }

    float4 bs4 = *(const float4*)(bias + c0 + tx * 4);
    if (blockIdx.z == 0) {
        float4 be4 = *(const float4*)(be + c0 + tx * 4);
        bs4.x += be4.x; bs4.y += be4.y; bs4.z += be4.z; bs4.w += be4.w;
    }
    #pragma unroll
    for (int r = 0; r < 2; ++r) {
        int m = m0 + ty * 2 + r;
        *(float4*)(out + (size_t)m * 256 + c0 + tx * 4) =
            make_float4(acc[r][0] + bs4.x, acc[r][1] + bs4.y,
                        acc[r][2] + bs4.z, acc[r][3] + bs4.w);
    }
}

// ---------------- edge kernel: 64x256 tile, 256 thr, 2 CTAs/SM ----------
// smem: B 2x32KB @0 (reused as 32KB epilogue staging), A 2x8KB @65536,
//       sHs @81920, sbias @82944
#define SB_B     0
#define SB_A     65536
#define SM_SHS   81920
#define SM_SBIAS 82944
#define SM_EDGE_TOTAL 91136

__global__ __launch_bounds__(256, 2) void edge_mma_kernel(
    const float* __restrict__ e, const __half* __restrict__ WeTh,
    const float* __restrict__ Hs, const float* __restrict__ Hd,
    const float* __restrict__ Wb,
    float* __restrict__ e_new, float* __restrict__ bias)
{
    extern __shared__ char smem[];
    const uint32_t sb = smem_u32(smem);
    float* sHs   = (float*)(smem + SM_SHS);
    float* sbias = (float*)(smem + SM_SBIAS);

    const int tid = threadIdx.x;
    const int w = tid >> 5, lane = tid & 31;
    const int g = lane >> 2, tig = lane & 3, x7 = lane & 7;
    const int wr = w >> 2, wc = w & 3;     // 2 row-groups x 4 col-groups

    const int m0 = blockIdx.x * 64;
    const int b = m0 >> 16, i = (m0 >> 8) & 255, j0 = m0 & 255;

    // ---- B chunk 0 (256 n-rows x 64 k) via cp.async ----
    #pragma unroll
    for (int it = 0; it < 8; ++it) {
        int idx = tid + it * 256;
        int r = idx >> 3, ch = idx & 7;
        cp16(sb + SB_B + r * 128 + ((ch ^ (r & 7)) << 4),
             WeTh + (size_t)r * 256 + ch * 8);
    }
    asm volatile("cp.async.commit_group;");

    // ---- A chunk 0: LDG fp32 -> fp16 STS (64 rows x 64 k) ----
    const float* Ab = e + (size_t)m0 * 256;
    #pragma unroll
    for (int p = 0; p < 2; ++p) {
        int idx = tid + p * 256;
        int row = idx >> 3, seg = idx & 7;
        const float* ptr = Ab + (size_t)row * 256 + seg * 8;
        float4 v0 = *(const float4*)ptr;
        float4 v1 = *(const float4*)(ptr + 4);
        uint4 u = make_uint4(pack_h2(v0.x, v0.y), pack_h2(v0.z, v0.w),
                             pack_h2(v1.x, v1.y), pack_h2(v1.z, v1.w));
        *(uint4*)(smem + SB_A + row * 128 + ((seg ^ (row & 7)) << 4)) = u;
    }

    // ---- tables ----
    sHs[tid] = Hs[(((size_t)(b << 8) + i) << 8) + tid];   // be pre-folded

    asm volatile("cp.async.wait_group 0;" ::: "memory");
    __syncthreads();

    const int rowoffA = x7 + (((lane >> 3) & 1) << 3);
    const int selA = lane >> 4;
    const int rowoffB = x7 + ((lane >> 4) << 3);
    const int selB = (lane >> 3) & 1;

    float acc[2][8][4] = {};
    float4 pre[4];

    for (int c = 0; c < 4; ++c) {
        if (c < 3) {
            // B prefetch to stage^1
            #pragma unroll
            for (int it = 0; it < 8; ++it) {
                int idx = tid + it * 256;
                int r = idx >> 3, ch = idx & 7;
                cp16(sb + SB_B + (((c + 1) & 1) << 15) + r * 128 +
                         ((ch ^ (r & 7)) << 4),
                     WeTh + (size_t)r * 256 + (c + 1) * 64 + ch * 8);
            }
            asm volatile("cp.async.commit_group;");
            // A prefetch to regs
            #pragma unroll
            for (int p = 0; p < 2; ++p) {
                int idx = tid + p * 256;
                int row = idx >> 3, seg = idx & 7;
                const float* ptr =
                    Ab + (size_t)row * 256 + (c + 1) * 64 + seg * 8;
                pre[p * 2]     = *(const float4*)ptr;
                pre[p * 2 + 1] = *(const float4*)(ptr + 4);
            }
        }
        const uint32_t sAc = sb + SB_A + ((c & 1) << 13);
        const uint32_t sBc = sb + SB_B + ((c & 1) << 15);
        #pragma unroll
        for (int kk = 0; kk < 4; ++kk) {
            uint32_t a0[4], a1[4];
            {
                int rowA = wr * 32 + rowoffA;
                ldmx4(a0, sAc + rowA * 128 + ((((kk << 1) + selA) ^ x7) << 4));
                ldmx4(a1, sAc + (rowA + 16) * 128 +
                              ((((kk << 1) + selA) ^ x7) << 4));
            }
            uint32_t bf[4][4];
            #pragma unroll
            for (int nt2 = 0; nt2 < 4; ++nt2) {
                int rowB = wc * 64 + nt2 * 16 + rowoffB;
                ldmx4(bf[nt2], sBc + rowB * 128 +
                               ((((kk << 1) + selB) ^ x7) << 4));
            }
            #pragma unroll
            for (int nt2 = 0; nt2 < 4; ++nt2) {
                mma_f16(acc[0][nt2 * 2],     a0, bf[nt2][0], bf[nt2][1]);
                mma_f16(acc[0][nt2 * 2 + 1], a0, bf[nt2][2], bf[nt2][3]);
                mma_f16(acc[1][nt2 * 2],     a1, bf[nt2][0], bf[nt2][1]);
                mma_f16(acc[1][nt2 * 2 + 1], a1, bf[nt2][2], bf[nt2][3]);
            }
        }
        __syncthreads();
        if (c < 3) {
            char* dst = smem + SB_A + (((c + 1) & 1) << 13);
            #pragma unroll
            for (int p = 0; p < 2; ++p) {
                int idx = tid + p * 256;
                int row = idx >> 3, seg = idx & 7;
                float4 v0 = pre[p * 2], v1 = pre[p * 2 + 1];
                uint4 u = make_uint4(pack_h2(v0.x, v0.y), pack_h2(v0.z, v0.w),
                                     pack_h2(v1.x, v1.y), pack_h2(v1.z, v1.w));
                *(uint4*)(dst + row * 128 + ((seg ^ (row & 7)) << 4)) = u;
            }
            asm volatile("cp.async.wait_group 0;" ::: "memory");
            __syncthreads();
        }
    }
    __syncthreads();   // B stage buffers (64KB @0) now dead -> reuse as staging

    // ---- Wb B-fragments for pass C (per warp: k-half slice) ----
    const int mtile = w >> 1, khalf = w & 1;
    uint32_t bw0[8], bw1[8];
    #pragma unroll
    for (int kc = 0; kc < 8; ++kc) {
        int k0 = khalf * 128 + kc * 16 + 2 * tig;
        bw0[kc] = pack_h2(Wb[(k0    ) * 8 + g], Wb[(k0 + 1) * 8 + g]);
        bw1[kc] = pack_h2(Wb[(k0 + 8) * 8 + g], Wb[(k0 + 9) * 8 + g]);
    }

    // ---- pass A: stage fp16(acc + Hs) into SB_B, swizzled ----
    char* stg = smem + SB_B;     // 64 rows x 512B = 32KB, fits the 64KB region
    #pragma unroll
    for (int mt = 0; mt < 2; ++mt) {
        const int rl = wr * 32 + mt * 16 + g;   // rl & 7 == g
        #pragma unroll
        for (int nt = 0; nt < 8; ++nt) {
            const int cl = wc * 64 + nt * 8 + 2 * tig;
            float2 hs = *(const float2*)(sHs + cl);
            uint32_t u0 = pack_h2(acc[mt][nt][0] + hs.x, acc[mt][nt][1] + hs.y);
            uint32_t u1 = pack_h2(acc[mt][nt][2] + hs.x, acc[mt][nt][3] + hs.y);
            const int chunk = wc * 8 + nt;
            *(uint32_t*)(stg + rl * 512 + ((chunk ^ g) << 4) + 4 * tig) = u0;
            *(uint32_t*)(stg + (rl + 8) * 512 + ((chunk ^ g) << 4) + 4 * tig) = u1;
        }
    }
    __syncthreads();

    // ---- pass B: coalesced +Hd, ReLU, e_new store; relu'd fp16 in place --
    {
        const float* hdb = Hd + (((size_t)(b << 8) + j0) << 8);
        float* eb = e_new + (size_t)m0 * 256;
        #pragma unroll
        for (int p = 0; p < 16; ++p) {
            int idx = p * 256 + tid;
            int r = idx >> 6, c4 = idx & 63;
            uint32_t soff = r * 512 + (((c4 >> 1) ^ (r & 7)) << 4) + (c4 & 1) * 8;
            uint2 hv = *(uint2*)(stg + soff);
            float2 f0 = __half22float2(*(__half2*)&hv.x);
            float2 f1 = __half22float2(*(__half2*)&hv.y);
            float4 hd4 = *(const float4*)(hdb + (size_t)r * 256 + c4 * 4);
            float x0 = fmaxf(f0.x + hd4.x, 0.0f);
            float x1 = fmaxf(f0.y + hd4.y, 0.0f);
            float x2 = fmaxf(f1.x + hd4.z, 0.0f);
            float x3 = fmaxf(f1.y + hd4.w, 0.0f);
            *(float4*)(eb + (size_t)r * 256 + c4 * 4) =
                make_float4(x0, x1, x2, x3);
            uint2 wb;
            wb.x = pack_h2(x0, x1);
            wb.y = pack_h2(x2, x3);
            *(uint2*)(stg + soff) = wb;
        }
    }
    __syncthreads();

    // ---- pass C: bias = relu'd x @ Wb via mma from staging ----
    {
        float bc4[4] = {0.0f, 0.0f, 0.0f, 0.0f};
        #pragma unroll
        for (int kk = 0; kk < 8; ++kk) {
            uint32_t a[4];
            int rowA = mtile * 16 + rowoffA;
            ldmx4(a, sb + SB_B + rowA * 512 +
                     (((khalf * 16 + kk * 2 + selA) ^ x7) << 4));
            mma_f16(bc4, a, bw0[kk], bw1[kk]);
        }
        float* sbw = sbias + khalf * 512;
        int rl = mtile * 16 + g;
        sbw[rl * 8 + 2 * tig]           = bc4[0];
        sbw[rl * 8 + 2 * tig + 1]       = bc4[1];
        sbw[(rl + 8) * 8 + 2 * tig]     = bc4[2];
        sbw[(rl + 8) * 8 + 2 * tig + 1] = bc4[3];
    }
    __syncthreads();
    #pragma unroll
    for (int q = 0; q < 2; ++q) {
        int t = tid + q * 256;
        int r = t & 63, hh = t >> 6;
        float v = sbias[r * 8 + hh] + sbias[512 + r * 8 + hh];
        bias[((((size_t)b * 8 + hh) * 256 + i) << 8) + j0 + r] = v;
    }
}

// ---------------- fp16 MMA GEMM: 64x64 tile, 256 thr (8 warps 2x4) ------
template <int OP, bool RES>
__global__ __launch_bounds__(256) void gemm_mma64(
    const float* __restrict__ A, const __half* __restrict__ Wh,
    const float* __restrict__ bias, const float* __restrict__ res,
    float* __restrict__ out, int K, int N)
{
    extern __shared__ char sm2[];
    const uint32_t sb = smem_u32(sm2);
    const int tid = threadIdx.x;
    const int w = tid >> 5, lane = tid & 31;
    const int g = lane >> 2, tig = lane & 3, x7 = lane & 7;
    const int wr = w >> 2, wc = w & 3;
    const int m0 = blockIdx.y * 64, n0 = blockIdx.x * 64;
    const int NC = K >> 6;

    const float*  Ab = A + (size_t)m0 * K;
    const __half* Bb = Wh + (size_t)n0 * K;
    const int arow = tid >> 2;
    const int cpair = tid & 3;

    #pragma unroll
    for (int p = 0; p < 2; ++p) {
        int idx = tid + p * 256;
        int r = idx >> 3, ch = idx & 7;
        cp16(sb + 16384 + r * 128 + ((ch ^ (r & 7)) << 4),
             Bb + (size_t)r * K + ch * 8);
    }
    asm volatile("cp.async.commit_group;");
    #pragma unroll
    for (int q = 0; q < 2; ++q) {
        int ch = cpair * 2 + q;
        const float* p = Ab + (size_t)arow * K + ch * 8;
        float4 v0 = *(const float4*)p;
        float4 v1 = *(const float4*)(p + 4);
        uint4 u = make_uint4(pack_h2(v0.x, v0.y), pack_h2(v0.z, v0.w),
                             pack_h2(v1.x, v1.y), pack_h2(v1.z, v1.w));
        *(uint4*)(sm2 + arow * 128 + ((ch ^ (arow & 7)) << 4)) = u;
    }
    asm volatile("cp.async.wait_group 0;" ::: "memory");
    __syncthreads();

    const int rowoffA = x7 + (((lane >> 3) & 1) << 3);
    const int selA = lane >> 4;
    const int rowoffB = x7 + ((lane >> 4) << 3);
    const int selB = (lane >> 3) & 1;

    float acc[2][2][4] = {};
    float4 pre[4];

    for (int c = 0; c < NC; ++c) {
        if (c + 1 < NC) {
            #pragma unroll
            for (int p = 0; p < 2; ++p) {
                int idx = tid + p * 256;
                int r = idx >> 3, ch = idx & 7;
                cp16(sb + 16384 + (((c + 1) & 1) << 13) + r * 128 +
                         ((ch ^ (r & 7)) << 4),
                     Bb + (size_t)r * K + (c + 1) * 64 + ch * 8);
            }
            asm volatile("cp.async.commit_group;");
            #pragma unroll
            for (int q = 0; q < 2; ++q) {
                int ch = cpair * 2 + q;
                const float* p = Ab + (size_t)arow * K + (c + 1) * 64 + ch * 8;
                pre[q * 2]     = *(const float4*)p;
                pre[q * 2 + 1] = *(const float4*)(p + 4);
            }
        }
        const uint32_t sA = sb + ((c & 1) << 13);
        const uint32_t sB = sb + 16384 + ((c & 1) << 13);
        #pragma unroll
        for (int kk = 0; kk < 4; ++kk) {
            uint32_t a0[4], a1[4];
            int rA = wr * 32 + rowoffA;
            ldmx4(a0, sA + rA * 128 + ((((kk << 1) + selA) ^ x7) << 4));
            ldmx4(a1, sA + (rA + 16) * 128 + ((((kk << 1) + selA) ^ x7) << 4));
            uint32_t bf[4];
            int rB = wc * 16 + rowoffB;
            ldmx4(bf, sB + rB * 128 + ((((kk << 1) + selB) ^ x7) << 4));
            mma_f16(acc[0][0], a0, bf[0], bf[1]);
            mma_f16(acc[0][1], a0, bf[2], bf[3]);
            mma_f16(acc[1][0], a1, bf[0], bf[1]);
            mma_f16(acc[1][1], a1, bf[2], bf[3]);
        }
        __syncthreads();
        if (c + 1 < NC) {
            char* dst = sm2 + (((c + 1) & 1) << 13);
            #pragma unroll
            for (int q = 0; q < 2; ++q) {
                int ch = cpair * 2 + q;
                float4 v0 = pre[q * 2], v1 = pre[q * 2 + 1];
                uint4 u = make_uint4(pack_h2(v0.x, v0.y), pack_h2(v0.z, v0.w),
                                     pack_h2(v1.x, v1.y), pack_h2(v1.z, v1.w));
                *(uint4*)(dst + arow * 128 + ((ch ^ (arow & 7)) << 4)) = u;
            }
            asm volatile("cp.async.wait_group 0;" ::: "memory");
            __syncthreads();
        }
    }

    #pragma unroll
    for (int mt = 0; mt < 2; ++mt) {
        #pragma unroll
        for (int rh = 0; rh < 2; ++rh) {
            int rl = wr * 32 + mt * 16 + rh * 8 + g;
            float* orow = out + (size_t)(m0 + rl) * N + n0;
            const float* rrow = RES ? res + (size_t)(m0 + rl) * N + n0 : nullptr;
            #pragma unroll
            for (int nh = 0; nh < 2; ++nh) {
                int cl = wc * 16 + nh * 8 + 2 * tig;
                float x0 = acc[mt][nh][rh * 2 + 0] + __ldg(bias + n0 + cl);
                float x1 = acc[mt][nh][rh * 2 + 1] + __ldg(bias + n0 + cl + 1);
                if (OP == 1) { x0 = gelu_exact(x0); x1 = gelu_exact(x1); }
                if (RES) {
                    float2 rv = *(const float2*)(rrow + cl);
                    x0 += rv.x; x1 += rv.y;
                }
                *(float2*)(orow + cl) = make_float2(x0, x1);
            }
        }
    }
}

// ---------------- LayerNorm ----------------
__global__ __launch_bounds__(256) void ln_kernel(
    const float* __restrict__ in, const float* __restrict__ g,
    const float* __restrict__ b, float* __restrict__ out)
{
    int row = blockIdx.x;
    int t = threadIdx.x;
    float v = in[(size_t)row * 256 + t];
    __shared__ float red[8];

    float s = v;
    #pragma unroll
    for (int o = 16; o; o >>= 1) s += __shfl_xor_sync(0xffffffffu, s, o);
    if ((t & 31) == 0) red[t >> 5] = s;
    __syncthreads();
    float mean = (red[0] + red[1] + red[2] + red[3] +
                  red[4] + red[5] + red[6] + red[7]) * (1.0f / 256.0f);
    float d = v - mean;
    __syncthreads();
    s = d * d;
    #pragma unroll
    for (int o = 16; o; o >>= 1) s += __shfl_xor_sync(0xffffffffu, s, o);
    if ((t & 31) == 0) red[t >> 5] = s;
    __syncthreads();
    float var = (red[0] + red[1] + red[2] + red[3] +
                 red[4] + red[5] + red[6] + red[7]) * (1.0f / 256.0f);
    out[(size_t)row * 256 + t] = d * rsqrtf(var + 1e-5f) * g[t] + b[t];
}

// ---------------- attention kernel: fp16 k/v smem, 16 rows x 16 lanes ----
// grid: ((b*8+h)*16 + tile), 256 threads; tile = 16 query rows.
__global__ __launch_bounds__(256, 2) void attn_kernel(
    const float* __restrict__ qkv, const float* __restrict__ bias,
    const float* __restrict__ bb, float* __restrict__ o)
{
    extern __shared__ float sm[];
    __half2* ks2 = (__half2*)sm;                 // [256][17]
    __half2* vs2 = ks2 + 256 * 17;               // [256][17]
    float*   qs  = (float*)(vs2 + 256 * 17);     // [16][33]

    const int tid = threadIdx.x;
    const int tile = blockIdx.x & 15;
    const int bh = blockIdx.x >> 4;
    const int b = bh >> 3, hh = bh & 7;
    const int i0 = tile * 16;
    const float bbv = bb[hh];

    #pragma unroll
    for (int it = 0; it < 16; ++it) {
        int idx = tid + it * 256;
        int j = idx >> 4, d2 = idx & 15;
        const float* base = qkv + (size_t)(b * 256 + j) * 768 + hh * 32 + d2 * 2;
        float2 kk = *(const float2*)(base + 256);
        float2 vv = *(const float2*)(base + 512);
        ks2[j * 17 + d2] = __float22half2_rn(kk);
        vs2[j * 17 + d2] = __float22half2_rn(vv);
    }
    #pragma unroll
    for (int it = 0; it < 2; ++it) {
        int idx = tid + it * 256;
        int r = idx >> 5, d = idx & 31;
        qs[r * 33 + d] = qkv[(size_t)(b * 256 + i0 + r) * 768 + hh * 32 + d];
    }
    __syncthreads();

    const int r = tid >> 4, s = tid & 15;
    const int i = i0 + r;
    const float* brow = bias + ((((size_t)b * 8 + hh) * 256 + i) << 8);

    float q[32];
    #pragma unroll
    for (int d = 0; d < 32; ++d) q[d] = qs[r * 33 + d];

    float sc[16];
    float mx = -1e30f;
    #pragma unroll
    for (int jj = 0; jj < 16; ++jj) {
        int j = jj * 16 + s;
        const __half2* kp = ks2 + j * 17;
        float a = 0.0f;
        #pragma unroll
        for (int d2 = 0; d2 < 16; ++d2) {
            float2 kf = __half22float2(kp[d2]);
            a += q[2 * d2] * kf.x + q[2 * d2 + 1] * kf.y;
        }
        a = a * 0.17677669529663687f + brow[j] + bbv;
        sc[jj] = a;
        mx = fmaxf(mx, a);
    }
    #pragma unroll
    for (int off = 8; off; off >>= 1)
        mx = fmaxf(mx, __shfl_xor_sync(0xffffffffu, mx, off));

    float sum = 0.0f;
    #pragma unroll
    for (int jj = 0; jj < 16; ++jj) {
        sc[jj] = __expf(sc[jj] - mx);
        sum += sc[jj];
    }
    #pragma unroll
    for (int off = 8; off; off >>= 1)
        sum += __shfl_xor_sync(0xffffffffu, sum, off);
    float inv = 1.0f / sum;

    float oacc[32] = {};
    #pragma unroll
    for (int jj = 0; jj < 16; ++jj) {
        int j = jj * 16 + s;
        float wgt = sc[jj];
        const __half2* vp = vs2 + j * 17;
        #pragma unroll
        for (int d2 = 0; d2 < 16; ++d2) {
            float2 vf = __half22float2(vp[d2]);
            oacc[2 * d2]     += wgt * vf.x;
            oacc[2 * d2 + 1] += wgt * vf.y;
        }
    }

    float w2[2];
    #pragma unroll
    for (int d = 0; d < 32; ++d) {
        float t = oacc[d];
        t += __shfl_xor_sync(0xffffffffu, t, 1);
        t += __shfl_xor_sync(0xffffffffu, t, 2);
        t += __shfl_xor_sync(0xffffffffu, t, 4);
        t += __shfl_xor_sync(0xffffffffu, t, 8);
        if ((d >> 1) == s) w2[d & 1] = t;
    }
    *(float2*)(o + ((size_t)(b * 256 + i)) * 256 + hh * 32 + s * 2) =
        make_float2(w2[0] * inv, w2[1] * inv);
}

// ---------------- launch ----------------
extern "C" void kernel_launch(void* const* d_in, const int* in_sizes, int n_in,
                              void* d_out, int out_size)
{
    (void)in_sizes; (void)n_in; (void)out_size;
    const float* h    = (const float*)d_in[0];
    const float* e    = (const float*)d_in[1];
    const float* We   = (const float*)d_in[2];
    const float* be   = (const float*)d_in[3];
    const float* Ws   = (const float*)d_in[4];
    const float* bs   = (const float*)d_in[5];
    const float* Wd   = (const float*)d_in[6];
    const float* bd   = (const float*)d_in[7];
    const float* Wb   = (const float*)d_in[8];
    const float* bb   = (const float*)d_in[9];
    const float* ln1g = (const float*)d_in[10];
    const float* ln1b = (const float*)d_in[11];
    const float* Wqkv = (const float*)d_in[12];
    const float* bqkv = (const float*)d_in[13];
    const float* Wo   = (const float*)d_in[14];
    const float* bo   = (const float*)d_in[15];
    const float* ln2g = (const float*)d_in[16];
    const float* ln2b = (const float*)d_in[17];
    const float* W1   = (const float*)d_in[18];
    const float* b1   = (const float*)d_in[19];
    const float* W2   = (const float*)d_in[20];
    const float* b2   = (const float*)d_in[21];

    float* out_h2 = (float*)d_out;
    float* out_e  = out_h2 + (size_t)BN * DD;

    float *pHs, *pHd, *px1, *pqkv, *pbias, *po, *ph1, *py, *pf;
    __half *pWeTh, *pWqkvTh, *pWoTh, *pW1Th, *pW2Th;
    cudaGetSymbolAddress((void**)&pHs,     g_Hs);
    cudaGetSymbolAddress((void**)&pHd,     g_Hd);
    cudaGetSymbolAddress((void**)&px1,     g_x1);
    cudaGetSymbolAddress((void**)&pqkv,    g_qkv);
    cudaGetSymbolAddress((void**)&pbias,   g_bias);
    cudaGetSymbolAddress((void**)&po,      g_o);
    cudaGetSymbolAddress((void**)&ph1,     g_h1);
    cudaGetSymbolAddress((void**)&py,      g_y);
    cudaGetSymbolAddress((void**)&pf,      g_ffn);
    cudaGetSymbolAddress((void**)&pWeTh,   g_WeTh);
    cudaGetSymbolAddress((void**)&pWqkvTh, g_WqkvTh);
    cudaGetSymbolAddress((void**)&pWoTh,   g_WoTh);
    cudaGetSymbolAddress((void**)&pW1Th,   g_W1Th);
    cudaGetSymbolAddress((void**)&pW2Th,   g_W2Th);

    // #1-3: prep (edge kernel is launch #4 so ncu -s captures it)
    transpose_all<<<832, 256>>>(We, Wqkv, Wo, W1, W2,
                                pWeTh, pWqkvTh, pWoTh, pW1Th, pW2Th);
    gemm_hsd<<<dim3(8, 16, 2), 256>>>(h, Ws, bs, Wd, bd, be, pHs, pHd);
    ln_kernel<<<BN, 256>>>(h, ln1g, ln1b, px1);

    // #4: edge update + attention bias (2 CTAs/SM)
    cudaFuncSetAttribute(edge_mma_kernel,
                         cudaFuncAttributeMaxDynamicSharedMemorySize,
                         SM_EDGE_TOTAL);
    edge_mma_kernel<<<4096, 256, SM_EDGE_TOTAL>>>(
        e, pWeTh, pHs, pHd, Wb, out_e, pbias);

    // attention path
    gemm_mma64<0, false><<<dim3(12, 16), 256, 32768>>>(
        px1, pWqkvTh, bqkv, nullptr, pqkv, 256, 768);
    attn_kernel<<<512, 256, 36928>>>(pqkv, pbias, bb, po);

    // output proj + residual
    gemm_mma64<0, true><<<dim3(4, 16), 256, 32768>>>(
        po, pWoTh, bo, h, ph1, 256, 256);

    // FFN
    ln_kernel<<<BN, 256>>>(ph1, ln2g, ln2b, py);
    gemm_mma64<1, false><<<dim3(16, 16), 256, 32768>>>(
        py, pW1Th, b1, nullptr, pf, 256, 1024);
    gemm_mma64<0, true><<<dim3(4, 16), 256, 32768>>>(
        pf, pW2Th, b2, ph1, out_h2, 1024, 256);
}

// round 14
// speedup vs baseline: 4.8638x; 1.0303x over previous
#include <cuda_runtime.h>
#include <cuda_fp16.h>
#include <math.h>
#include <stdint.h>

// Shapes (fixed): B=4, N=256, D=256, H=8, HD=32, DFF=1024
#define BN 1024
#define DD 256

// ---------------- scratch ----------------
__device__ __align__(16) float  g_Hs[BN * DD];    // Hs + bs + be
__device__ __align__(16) float  g_Hd[BN * DD];
__device__ __align__(16) float  g_x1[BN * DD];
__device__ __align__(16) float  g_qkv[BN * 768];
__device__ __align__(16) __half g_biash[4 * 8 * 256 * 256];
__device__ __align__(16) float  g_o[BN * DD];
__device__ __align__(16) float  g_h1[BN * DD];
__device__ __align__(16) float  g_y[BN * DD];
__device__ __align__(16) float  g_ffn[BN * 1024];
__device__ __align__(16) __half g_WeTh[DD * DD];
__device__ __align__(16) __half g_WqkvTh[768 * DD];
__device__ __align__(16) __half g_WoTh[DD * DD];
__device__ __align__(16) __half g_W1Th[1024 * DD];
__device__ __align__(16) __half g_W2Th[DD * 1024];
__device__ __align__(16) __half g_WsTh[DD * DD];
__device__ __align__(16) __half g_WdTh[DD * DD];

// ---------------- helpers ----------------
__device__ __forceinline__ uint32_t smem_u32(const void* p) {
    uint32_t a;
    asm("{ .reg .u64 t; cvta.to.shared.u64 t, %1; cvt.u32.u64 %0, t; }"
        : "=r"(a) : "l"(p));
    return a;
}
__device__ __forceinline__ void cp16(uint32_t dst, const void* src) {
    asm volatile("cp.async.cg.shared.global [%0], [%1], 16;"
                 :: "r"(dst), "l"(src));
}
__device__ __forceinline__ void ldmx4(uint32_t* r, uint32_t addr) {
    asm volatile(
        "ldmatrix.sync.aligned.m8n8.x4.shared.b16 {%0,%1,%2,%3}, [%4];"
        : "=r"(r[0]), "=r"(r[1]), "=r"(r[2]), "=r"(r[3]) : "r"(addr));
}
__device__ __forceinline__ void mma_f16(float* c, const uint32_t* a,
                                        uint32_t b0, uint32_t b1) {
    asm volatile(
        "mma.sync.aligned.m16n8k16.row.col.f32.f16.f16.f32 "
        "{%0,%1,%2,%3}, {%4,%5,%6,%7}, {%8,%9}, {%0,%1,%2,%3};"
        : "+f"(c[0]), "+f"(c[1]), "+f"(c[2]), "+f"(c[3])
        : "r"(a[0]), "r"(a[1]), "r"(a[2]), "r"(a[3]), "r"(b0), "r"(b1));
}
__device__ __forceinline__ uint32_t pack_h2(float x, float y) {
    __half2 h = __float22half2_rn(make_float2(x, y));
    return *reinterpret_cast<uint32_t*>(&h);
}
__device__ __forceinline__ float gelu_exact(float x) {
    return 0.5f * x * (1.0f + erff(x * 0.70710678118654752f));
}

// ---------------- tiled weight transpose+fp16 (coalesced) ----------------
__global__ __launch_bounds__(256) void transpose_all(
    const float* __restrict__ We,  const float* __restrict__ Wqkv,
    const float* __restrict__ Wo,  const float* __restrict__ W1,
    const float* __restrict__ W2,  const float* __restrict__ Ws,
    const float* __restrict__ Wd,
    __half* __restrict__ oWe,  __half* __restrict__ oWqkv,
    __half* __restrict__ oWo,  __half* __restrict__ oW1,
    __half* __restrict__ oW2,  __half* __restrict__ oWs,
    __half* __restrict__ oWd)
{
    __shared__ float s[32][33];
    int bid = blockIdx.x;
    const float* in; __half* out; int K, N, t;
    if (bid < 64)        { in = We;   out = oWe;   K = 256;  N = 256;  t = bid; }
    else if (bid < 256)  { in = Wqkv; out = oWqkv; K = 256;  N = 768;  t = bid - 64; }
    else if (bid < 320)  { in = Wo;   out = oWo;   K = 256;  N = 256;  t = bid - 256; }
    else if (bid < 576)  { in = W1;   out = oW1;   K = 256;  N = 1024; t = bid - 320; }
    else if (bid < 832)  { in = W2;   out = oW2;   K = 1024; N = 256;  t = bid - 576; }
    else if (bid < 896)  { in = Ws;   out = oWs;   K = 256;  N = 256;  t = bid - 832; }
    else                 { in = Wd;   out = oWd;   K = 256;  N = 256;  t = bid - 896; }
    const int ntn = N >> 5;
    const int k0 = (t / ntn) << 5, n0 = (t % ntn) << 5;
    const int r = threadIdx.x >> 5, c = threadIdx.x & 31;
    #pragma unroll
    for (int q = 0; q < 4; ++q)
        s[r + q * 8][c] = in[(size_t)(k0 + r + q * 8) * N + n0 + c];
    __syncthreads();
    #pragma unroll
    for (int q = 0; q < 4; ++q)
        out[(size_t)(n0 + r + q * 8) * K + k0 + c] =
            __float2half_rn(s[c][r + q * 8]);
}

// ---------------- edge kernel: 64x256 tile, 256 thr, 2 CTAs/SM ----------
// smem: B 2x32KB @0 (reused as 32KB epilogue staging), A 2x8KB @65536,
//       sHs @81920, sbias @82944
#define SB_B     0
#define SB_A     65536
#define SM_SHS   81920
#define SM_SBIAS 82944
#define SM_EDGE_TOTAL 91136

__global__ __launch_bounds__(256, 2) void edge_mma_kernel(
    const float* __restrict__ e, const __half* __restrict__ WeTh,
    const float* __restrict__ Hs, const float* __restrict__ Hd,
    const float* __restrict__ Wb,
    float* __restrict__ e_new, __half* __restrict__ bias)
{
    extern __shared__ char smem[];
    const uint32_t sb = smem_u32(smem);
    float* sHs   = (float*)(smem + SM_SHS);
    float* sbias = (float*)(smem + SM_SBIAS);

    const int tid = threadIdx.x;
    const int w = tid >> 5, lane = tid & 31;
    const int g = lane >> 2, tig = lane & 3, x7 = lane & 7;
    const int wr = w >> 2, wc = w & 3;     // 2 row-groups x 4 col-groups

    const int m0 = blockIdx.x * 64;
    const int b = m0 >> 16, i = (m0 >> 8) & 255, j0 = m0 & 255;

    // ---- B chunk 0 (256 n-rows x 64 k) via cp.async ----
    #pragma unroll
    for (int it = 0; it < 8; ++it) {
        int idx = tid + it * 256;
        int r = idx >> 3, ch = idx & 7;
        cp16(sb + SB_B + r * 128 + ((ch ^ (r & 7)) << 4),
             WeTh + (size_t)r * 256 + ch * 8);
    }
    asm volatile("cp.async.commit_group;");

    // ---- A chunk 0: LDG fp32 -> fp16 STS (64 rows x 64 k) ----
    const float* Ab = e + (size_t)m0 * 256;
    #pragma unroll
    for (int p = 0; p < 2; ++p) {
        int idx = tid + p * 256;
        int row = idx >> 3, seg = idx & 7;
        const float* ptr = Ab + (size_t)row * 256 + seg * 8;
        float4 v0 = *(const float4*)ptr;
        float4 v1 = *(const float4*)(ptr + 4);
        uint4 u = make_uint4(pack_h2(v0.x, v0.y), pack_h2(v0.z, v0.w),
                             pack_h2(v1.x, v1.y), pack_h2(v1.z, v1.w));
        *(uint4*)(smem + SB_A + row * 128 + ((seg ^ (row & 7)) << 4)) = u;
    }

    // ---- tables ----
    sHs[tid] = Hs[(((size_t)(b << 8) + i) << 8) + tid];   // bs+be pre-folded

    asm volatile("cp.async.wait_group 0;" ::: "memory");
    __syncthreads();

    const int rowoffA = x7 + (((lane >> 3) & 1) << 3);
    const int selA = lane >> 4;
    const int rowoffB = x7 + ((lane >> 4) << 3);
    const int selB = (lane >> 3) & 1;

    float acc[2][8][4] = {};
    float4 pre[4];

    for (int c = 0; c < 4; ++c) {
        if (c < 3) {
            // B prefetch to stage^1
            #pragma unroll
            for (int it = 0; it < 8; ++it) {
                int idx = tid + it * 256;
                int r = idx >> 3, ch = idx & 7;
                cp16(sb + SB_B + (((c + 1) & 1) << 15) + r * 128 +
                         ((ch ^ (r & 7)) << 4),
                     WeTh + (size_t)r * 256 + (c + 1) * 64 + ch * 8);
            }
            asm volatile("cp.async.commit_group;");
            // A prefetch to regs
            #pragma unroll
            for (int p = 0; p < 2; ++p) {
                int idx = tid + p * 256;
                int row = idx >> 3, seg = idx & 7;
                const float* ptr =
                    Ab + (size_t)row * 256 + (c + 1) * 64 + seg * 8;
                pre[p * 2]     = *(const float4*)ptr;
                pre[p * 2 + 1] = *(const float4*)(ptr + 4);
            }
        }
        const uint32_t sAc = sb + SB_A + ((c & 1) << 13);
        const uint32_t sBc = sb + SB_B + ((c & 1) << 15);
        #pragma unroll
        for (int kk = 0; kk < 4; ++kk) {
            uint32_t a0[4], a1[4];
            {
                int rowA = wr * 32 + rowoffA;
                ldmx4(a0, sAc + rowA * 128 + ((((kk << 1) + selA) ^ x7) << 4));
                ldmx4(a1, sAc + (rowA + 16) * 128 +
                              ((((kk << 1) + selA) ^ x7) << 4));
            }
            uint32_t bf[4][4];
            #pragma unroll
            for (int nt2 = 0; nt2 < 4; ++nt2) {
                int rowB = wc * 64 + nt2 * 16 + rowoffB;
                ldmx4(bf[nt2], sBc + rowB * 128 +
                               ((((kk << 1) + selB) ^ x7) << 4));
            }
            #pragma unroll
            for (int nt2 = 0; nt2 < 4; ++nt2) {
                mma_f16(acc[0][nt2 * 2],     a0, bf[nt2][0], bf[nt2][1]);
                mma_f16(acc[0][nt2 * 2 + 1], a0, bf[nt2][2], bf[nt2][3]);
                mma_f16(acc[1][nt2 * 2],     a1, bf[nt2][0], bf[nt2][1]);
                mma_f16(acc[1][nt2 * 2 + 1], a1, bf[nt2][2], bf[nt2][3]);
            }
        }
        __syncthreads();
        if (c < 3) {
            char* dst = smem + SB_A + (((c + 1) & 1) << 13);
            #pragma unroll
            for (int p = 0; p < 2; ++p) {
                int idx = tid + p * 256;
                int row = idx >> 3, seg = idx & 7;
                float4 v0 = pre[p * 2], v1 = pre[p * 2 + 1];
                uint4 u = make_uint4(pack_h2(v0.x, v0.y), pack_h2(v0.z, v0.w),
                                     pack_h2(v1.x, v1.y), pack_h2(v1.z, v1.w));
                *(uint4*)(dst + row * 128 + ((seg ^ (row & 7)) << 4)) = u;
            }
            asm volatile("cp.async.wait_group 0;" ::: "memory");
            __syncthreads();
        }
    }
    __syncthreads();   // B stage buffers (64KB @0) now dead -> reuse as staging

    // ---- Wb B-fragments for pass C (per warp: k-half slice) ----
    const int mtile = w >> 1, khalf = w & 1;
    uint32_t bw0[8], bw1[8];
    #pragma unroll
    for (int kc = 0; kc < 8; ++kc) {
        int k0 = khalf * 128 + kc * 16 + 2 * tig;
        bw0[kc] = pack_h2(Wb[(k0    ) * 8 + g], Wb[(k0 + 1) * 8 + g]);
        bw1[kc] = pack_h2(Wb[(k0 + 8) * 8 + g], Wb[(k0 + 9) * 8 + g]);
    }

    // ---- pass A: stage fp16(acc + Hs) into SB_B, swizzled ----
    char* stg = smem + SB_B;     // 64 rows x 512B = 32KB
    #pragma unroll
    for (int mt = 0; mt < 2; ++mt) {
        const int rl = wr * 32 + mt * 16 + g;   // rl & 7 == g
        #pragma unroll
        for (int nt = 0; nt < 8; ++nt) {
            const int cl = wc * 64 + nt * 8 + 2 * tig;
            float2 hs = *(const float2*)(sHs + cl);
            uint32_t u0 = pack_h2(acc[mt][nt][0] + hs.x, acc[mt][nt][1] + hs.y);
            uint32_t u1 = pack_h2(acc[mt][nt][2] + hs.x, acc[mt][nt][3] + hs.y);
            const int chunk = wc * 8 + nt;
            *(uint32_t*)(stg + rl * 512 + ((chunk ^ g) << 4) + 4 * tig) = u0;
            *(uint32_t*)(stg + (rl + 8) * 512 + ((chunk ^ g) << 4) + 4 * tig) = u1;
        }
    }
    __syncthreads();

    // ---- pass B: coalesced +Hd, ReLU, e_new store; relu'd fp16 in place --
    {
        const float* hdb = Hd + (((size_t)(b << 8) + j0) << 8);
        float* eb = e_new + (size_t)m0 * 256;
        #pragma unroll
        for (int p = 0; p < 16; ++p) {
            int idx = p * 256 + tid;
            int r = idx >> 6, c4 = idx & 63;
            uint32_t soff = r * 512 + (((c4 >> 1) ^ (r & 7)) << 4) + (c4 & 1) * 8;
            uint2 hv = *(uint2*)(stg + soff);
            float2 f0 = __half22float2(*(__half2*)&hv.x);
            float2 f1 = __half22float2(*(__half2*)&hv.y);
            float4 hd4 = *(const float4*)(hdb + (size_t)r * 256 + c4 * 4);
            float x0 = fmaxf(f0.x + hd4.x, 0.0f);
            float x1 = fmaxf(f0.y + hd4.y, 0.0f);
            float x2 = fmaxf(f1.x + hd4.z, 0.0f);
            float x3 = fmaxf(f1.y + hd4.w, 0.0f);
            *(float4*)(eb + (size_t)r * 256 + c4 * 4) =
                make_float4(x0, x1, x2, x3);
            uint2 wb;
            wb.x = pack_h2(x0, x1);
            wb.y = pack_h2(x2, x3);
            *(uint2*)(stg + soff) = wb;
        }
    }
    __syncthreads();

    // ---- pass C: bias = relu'd x @ Wb via mma from staging ----
    {
        float bc4[4] = {0.0f, 0.0f, 0.0f, 0.0f};
        #pragma unroll
        for (int kk = 0; kk < 8; ++kk) {
            uint32_t a[4];
            int rowA = mtile * 16 + rowoffA;
            ldmx4(a, sb + SB_B + rowA * 512 +
                     (((khalf * 16 + kk * 2 + selA) ^ x7) << 4));
            mma_f16(bc4, a, bw0[kk], bw1[kk]);
        }
        float* sbw = sbias + khalf * 512;
        int rl = mtile * 16 + g;
        sbw[rl * 8 + 2 * tig]           = bc4[0];
        sbw[rl * 8 + 2 * tig + 1]       = bc4[1];
        sbw[(rl + 8) * 8 + 2 * tig]     = bc4[2];
        sbw[(rl + 8) * 8 + 2 * tig + 1] = bc4[3];
    }
    __syncthreads();
    #pragma unroll
    for (int q = 0; q < 2; ++q) {
        int t = tid + q * 256;
        int r = t & 63, hh = t >> 6;
        float v = sbias[r * 8 + hh] + sbias[512 + r * 8 + hh];
        bias[((((size_t)b * 8 + hh) * 256 + i) << 8) + j0 + r] =
            __float2half_rn(v);
    }
}

// ---------------- fp16 MMA GEMM: 64x64 tile, 256 thr (8 warps 2x4) ------
// out = op(A@Wh^T + bias [+bias2]) [+res]
template <int OP, bool RES>
__global__ __launch_bounds__(256) void gemm_mma64(
    const float* __restrict__ A, const __half* __restrict__ Wh,
    const float* __restrict__ bias, const float* __restrict__ bias2,
    const float* __restrict__ res,
    float* __restrict__ out, int K, int N)
{
    extern __shared__ char sm2[];
    const uint32_t sb = smem_u32(sm2);
    const int tid = threadIdx.x;
    const int w = tid >> 5, lane = tid & 31;
    const int g = lane >> 2, tig = lane & 3, x7 = lane & 7;
    const int wr = w >> 2, wc = w & 3;
    const int m0 = blockIdx.y * 64, n0 = blockIdx.x * 64;
    const int NC = K >> 6;

    const float*  Ab = A + (size_t)m0 * K;
    const __half* Bb = Wh + (size_t)n0 * K;
    const int arow = tid >> 2;
    const int cpair = tid & 3;

    #pragma unroll
    for (int p = 0; p < 2; ++p) {
        int idx = tid + p * 256;
        int r = idx >> 3, ch = idx & 7;
        cp16(sb + 16384 + r * 128 + ((ch ^ (r & 7)) << 4),
             Bb + (size_t)r * K + ch * 8);
    }
    asm volatile("cp.async.commit_group;");
    #pragma unroll
    for (int q = 0; q < 2; ++q) {
        int ch = cpair * 2 + q;
        const float* p = Ab + (size_t)arow * K + ch * 8;
        float4 v0 = *(const float4*)p;
        float4 v1 = *(const float4*)(p + 4);
        uint4 u = make_uint4(pack_h2(v0.x, v0.y), pack_h2(v0.z, v0.w),
                             pack_h2(v1.x, v1.y), pack_h2(v1.z, v1.w));
        *(uint4*)(sm2 + arow * 128 + ((ch ^ (arow & 7)) << 4)) = u;
    }
    asm volatile("cp.async.wait_group 0;" ::: "memory");
    __syncthreads();

    const int rowoffA = x7 + (((lane >> 3) & 1) << 3);
    const int selA = lane >> 4;
    const int rowoffB = x7 + ((lane >> 4) << 3);
    const int selB = (lane >> 3) & 1;

    float acc[2][2][4] = {};
    float4 pre[4];

    for (int c = 0; c < NC; ++c) {
        if (c + 1 < NC) {
            #pragma unroll
            for (int p = 0; p < 2; ++p) {
                int idx = tid + p * 256;
                int r = idx >> 3, ch = idx & 7;
                cp16(sb + 16384 + (((c + 1) & 1) << 13) + r * 128 +
                         ((ch ^ (r & 7)) << 4),
                     Bb + (size_t)r * K + (c + 1) * 64 + ch * 8);
            }
            asm volatile("cp.async.commit_group;");
            #pragma unroll
            for (int q = 0; q < 2; ++q) {
                int ch = cpair * 2 + q;
                const float* p = Ab + (size_t)arow * K + (c + 1) * 64 + ch * 8;
                pre[q * 2]     = *(const float4*)p;
                pre[q * 2 + 1] = *(const float4*)(p + 4);
            }
        }
        const uint32_t sA = sb + ((c & 1) << 13);
        const uint32_t sB = sb + 16384 + ((c & 1) << 13);
        #pragma unroll
        for (int kk = 0; kk < 4; ++kk) {
            uint32_t a0[4], a1[4];
            int rA = wr * 32 + rowoffA;
            ldmx4(a0, sA + rA * 128 + ((((kk << 1) + selA) ^ x7) << 4));
            ldmx4(a1, sA + (rA + 16) * 128 + ((((kk << 1) + selA) ^ x7) << 4));
            uint32_t bf[4];
            int rB = wc * 16 + rowoffB;
            ldmx4(bf, sB + rB * 128 + ((((kk << 1) + selB) ^ x7) << 4));
            mma_f16(acc[0][0], a0, bf[0], bf[1]);
            mma_f16(acc[0][1], a0, bf[2], bf[3]);
            mma_f16(acc[1][0], a1, bf[0], bf[1]);
            mma_f16(acc[1][1], a1, bf[2], bf[3]);
        }
        __syncthreads();
        if (c + 1 < NC) {
            char* dst = sm2 + (((c + 1) & 1) << 13);
            #pragma unroll
            for (int q = 0; q < 2; ++q) {
                int ch = cpair * 2 + q;
                float4 v0 = pre[q * 2], v1 = pre[q * 2 + 1];
                uint4 u = make_uint4(pack_h2(v0.x, v0.y), pack_h2(v0.z, v0.w),
                                     pack_h2(v1.x, v1.y), pack_h2(v1.z, v1.w));
                *(uint4*)(dst + arow * 128 + ((ch ^ (arow & 7)) << 4)) = u;
            }
            asm volatile("cp.async.wait_group 0;" ::: "memory");
            __syncthreads();
        }
    }

    #pragma unroll
    for (int mt = 0; mt < 2; ++mt) {
        #pragma unroll
        for (int rh = 0; rh < 2; ++rh) {
            int rl = wr * 32 + mt * 16 + rh * 8 + g;
            float* orow = out + (size_t)(m0 + rl) * N + n0;
            const float* rrow = RES ? res + (size_t)(m0 + rl) * N + n0 : nullptr;
            #pragma unroll
            for (int nh = 0; nh < 2; ++nh) {
                int cl = wc * 16 + nh * 8 + 2 * tig;
                float b0 = __ldg(bias + n0 + cl);
                float b1 = __ldg(bias + n0 + cl + 1);
                if (bias2) {
                    b0 += __ldg(bias2 + n0 + cl);
                    b1 += __ldg(bias2 + n0 + cl + 1);
                }
                float x0 = acc[mt][nh][rh * 2 + 0] + b0;
                float x1 = acc[mt][nh][rh * 2 + 1] + b1;
                if (OP == 1) { x0 = gelu_exact(x0); x1 = gelu_exact(x1); }
                if (RES) {
                    float2 rv = *(const float2*)(rrow + cl);
                    x0 += rv.x; x1 += rv.y;
                }
                *(float2*)(orow + cl) = make_float2(x0, x1);
            }
        }
    }
}

// ---------------- LayerNorm ----------------
__global__ __launch_bounds__(256) void ln_kernel(
    const float* __restrict__ in, const float* __restrict__ g,
    const float* __restrict__ b, float* __restrict__ out)
{
    int row = blockIdx.x;
    int t = threadIdx.x;
    float v = in[(size_t)row * 256 + t];
    __shared__ float red[8];

    float s = v;
    #pragma unroll
    for (int o = 16; o; o >>= 1) s += __shfl_xor_sync(0xffffffffu, s, o);
    if ((t & 31) == 0) red[t >> 5] = s;
    __syncthreads();
    float mean = (red[0] + red[1] + red[2] + red[3] +
                  red[4] + red[5] + red[6] + red[7]) * (1.0f / 256.0f);
    float d = v - mean;
    __syncthreads();
    s = d * d;
    #pragma unroll
    for (int o = 16; o; o >>= 1) s += __shfl_xor_sync(0xffffffffu, s, o);
    if ((t & 31) == 0) red[t >> 5] = s;
    __syncthreads();
    float var = (red[0] + red[1] + red[2] + red[3] +
                 red[4] + red[5] + red[6] + red[7]) * (1.0f / 256.0f);
    out[(size_t)row * 256 + t] = d * rsqrtf(var + 1e-5f) * g[t] + b[t];
}

// ---------------- attention kernel: fp16 k/v smem, fp16 bias -------------
__global__ __launch_bounds__(256, 2) void attn_kernel(
    const float* __restrict__ qkv, const __half* __restrict__ bias,
    const float* __restrict__ bb, float* __restrict__ o)
{
    extern __shared__ float sm[];
    __half2* ks2 = (__half2*)sm;                 // [256][17]
    __half2* vs2 = ks2 + 256 * 17;               // [256][17]
    float*   qs  = (float*)(vs2 + 256 * 17);     // [16][33]

    const int tid = threadIdx.x;
    const int tile = blockIdx.x & 15;
    const int bh = blockIdx.x >> 4;
    const int b = bh >> 3, hh = bh & 7;
    const int i0 = tile * 16;
    const float bbv = bb[hh];

    #pragma unroll
    for (int it = 0; it < 16; ++it) {
        int idx = tid + it * 256;
        int j = idx >> 4, d2 = idx & 15;
        const float* base = qkv + (size_t)(b * 256 + j) * 768 + hh * 32 + d2 * 2;
        float2 kk = *(const float2*)(base + 256);
        float2 vv = *(const float2*)(base + 512);
        ks2[j * 17 + d2] = __float22half2_rn(kk);
        vs2[j * 17 + d2] = __float22half2_rn(vv);
    }
    #pragma unroll
    for (int it = 0; it < 2; ++it) {
        int idx = tid + it * 256;
        int r = idx >> 5, d = idx & 31;
        qs[r * 33 + d] = qkv[(size_t)(b * 256 + i0 + r) * 768 + hh * 32 + d];
    }
    __syncthreads();

    const int r = tid >> 4, s = tid & 15;
    const int i = i0 + r;
    const __half* brow = bias + ((((size_t)b * 8 + hh) * 256 + i) << 8);

    float q[32];
    #pragma unroll
    for (int d = 0; d < 32; ++d) q[d] = qs[r * 33 + d];

    float sc[16];
    float mx = -1e30f;
    #pragma unroll
    for (int jj = 0; jj < 16; ++jj) {
        int j = jj * 16 + s;
        const __half2* kp = ks2 + j * 17;
        float a = 0.0f;
        #pragma unroll
        for (int d2 = 0; d2 < 16; ++d2) {
            float2 kf = __half22float2(kp[d2]);
            a += q[2 * d2] * kf.x + q[2 * d2 + 1] * kf.y;
        }
        a = a * 0.17677669529663687f + __half2float(brow[j]) + bbv;
        sc[jj] = a;
        mx = fmaxf(mx, a);
    }
    #pragma unroll
    for (int off = 8; off; off >>= 1)
        mx = fmaxf(mx, __shfl_xor_sync(0xffffffffu, mx, off));

    float sum = 0.0f;
    #pragma unroll
    for (int jj = 0; jj < 16; ++jj) {
        sc[jj] = __expf(sc[jj] - mx);
        sum += sc[jj];
    }
    #pragma unroll
    for (int off = 8; off; off >>= 1)
        sum += __shfl_xor_sync(0xffffffffu, sum, off);
    float inv = 1.0f / sum;

    float oacc[32] = {};
    #pragma unroll
    for (int jj = 0; jj < 16; ++jj) {
        int j = jj * 16 + s;
        float wgt = sc[jj];
        const __half2* vp = vs2 + j * 17;
        #pragma unroll
        for (int d2 = 0; d2 < 16; ++d2) {
            float2 vf = __half22float2(vp[d2]);
            oacc[2 * d2]     += wgt * vf.x;
            oacc[2 * d2 + 1] += wgt * vf.y;
        }
    }

    float w2[2];
    #pragma unroll
    for (int d = 0; d < 32; ++d) {
        float t = oacc[d];
        t += __shfl_xor_sync(0xffffffffu, t, 1);
        t += __shfl_xor_sync(0xffffffffu, t, 2);
        t += __shfl_xor_sync(0xffffffffu, t, 4);
        t += __shfl_xor_sync(0xffffffffu, t, 8);
        if ((d >> 1) == s) w2[d & 1] = t;
    }
    *(float2*)(o + ((size_t)(b * 256 + i)) * 256 + hh * 32 + s * 2) =
        make_float2(w2[0] * inv, w2[1] * inv);
}

// ---------------- launch ----------------
extern "C" void kernel_launch(void* const* d_in, const int* in_sizes, int n_in,
                              void* d_out, int out_size)
{
    (void)in_sizes; (void)n_in; (void)out_size;
    const float* h    = (const float*)d_in[0];
    const float* e    = (const float*)d_in[1];
    const float* We   = (const float*)d_in[2];
    const float* be   = (const float*)d_in[3];
    const float* Ws   = (const float*)d_in[4];
    const float* bs   = (const float*)d_in[5];
    const float* Wd   = (const float*)d_in[6];
    const float* bd   = (const float*)d_in[7];
    const float* Wb   = (const float*)d_in[8];
    const float* bb   = (const float*)d_in[9];
    const float* ln1g = (const float*)d_in[10];
    const float* ln1b = (const float*)d_in[11];
    const float* Wqkv = (const float*)d_in[12];
    const float* bqkv = (const float*)d_in[13];
    const float* Wo   = (const float*)d_in[14];
    const float* bo   = (const float*)d_in[15];
    const float* ln2g = (const float*)d_in[16];
    const float* ln2b = (const float*)d_in[17];
    const float* W1   = (const float*)d_in[18];
    const float* b1   = (const float*)d_in[19];
    const float* W2   = (const float*)d_in[20];
    const float* b2   = (const float*)d_in[21];

    float* out_h2 = (float*)d_out;
    float* out_e  = out_h2 + (size_t)BN * DD;

    float *pHs, *pHd, *px1, *pqkv, *po, *ph1, *py, *pf;
    __half *pbiash, *pWeTh, *pWqkvTh, *pWoTh, *pW1Th, *pW2Th, *pWsTh, *pWdTh;
    cudaGetSymbolAddress((void**)&pHs,     g_Hs);
    cudaGetSymbolAddress((void**)&pHd,     g_Hd);
    cudaGetSymbolAddress((void**)&px1,     g_x1);
    cudaGetSymbolAddress((void**)&pqkv,    g_qkv);
    cudaGetSymbolAddress((void**)&pbiash,  g_biash);
    cudaGetSymbolAddress((void**)&po,      g_o);
    cudaGetSymbolAddress((void**)&ph1,     g_h1);
    cudaGetSymbolAddress((void**)&py,      g_y);
    cudaGetSymbolAddress((void**)&pf,      g_ffn);
    cudaGetSymbolAddress((void**)&pWeTh,   g_WeTh);
    cudaGetSymbolAddress((void**)&pWqkvTh, g_WqkvTh);
    cudaGetSymbolAddress((void**)&pWoTh,   g_WoTh);
    cudaGetSymbolAddress((void**)&pW1Th,   g_W1Th);
    cudaGetSymbolAddress((void**)&pW2Th,   g_W2Th);
    cudaGetSymbolAddress((void**)&pWsTh,   g_WsTh);
    cudaGetSymbolAddress((void**)&pWdTh,   g_WdTh);

    // #1-3: prep (edge kernel is launch #4 so ncu -s captures it)
    transpose_all<<<960, 256>>>(We, Wqkv, Wo, W1, W2, Ws, Wd,
                                pWeTh, pWqkvTh, pWoTh, pW1Th, pW2Th,
                                pWsTh, pWdTh);
    gemm_mma64<0, false><<<dim3(4, 16), 256, 32768>>>(
        h, pWsTh, bs, be, nullptr, pHs, 256, 256);
    gemm_mma64<0, false><<<dim3(4, 16), 256, 32768>>>(
        h, pWdTh, bd, nullptr, nullptr, pHd, 256, 256);

    // #4: edge update + attention bias (2 CTAs/SM)
    cudaFuncSetAttribute(edge_mma_kernel,
                         cudaFuncAttributeMaxDynamicSharedMemorySize,
                         SM_EDGE_TOTAL);
    edge_mma_kernel<<<4096, 256, SM_EDGE_TOTAL>>>(
        e, pWeTh, pHs, pHd, Wb, out_e, pbiash);

    // attention path
    ln_kernel<<<BN, 256>>>(h, ln1g, ln1b, px1);
    gemm_mma64<0, false><<<dim3(12, 16), 256, 32768>>>(
        px1, pWqkvTh, bqkv, nullptr, nullptr, pqkv, 256, 768);
    attn_kernel<<<512, 256, 36928>>>(pqkv, pbiash, bb, po);

    // output proj + residual
    gemm_mma64<0, true><<<dim3(4, 16), 256, 32768>>>(
        po, pWoTh, bo, nullptr, h, ph1, 256, 256);

    // FFN
    ln_kernel<<<BN, 256>>>(ph1, ln2g, ln2b, py);
    gemm_mma64<1, false><<<dim3(16, 16), 256, 32768>>>(
        py, pW1Th, b1, nullptr, nullptr, pf, 256, 1024);
    gemm_mma64<0, true><<<dim3(4, 16), 256, 32768>>>(
        pf, pW2Th, b2, nullptr, ph1, out_h2, 1024, 256);
}

// round 15
// speedup vs baseline: 5.0389x; 1.0360x over previous
#include <cuda_runtime.h>
#include <cuda_fp16.h>
#include <math.h>
#include <stdint.h>

// Shapes (fixed): B=4, N=256, D=256, H=8, HD=32, DFF=1024
#define BN 1024
#define DD 256

// ---------------- scratch ----------------
__device__ __align__(16) float  g_Hs[BN * DD];    // Hs + bs + be
__device__ __align__(16) float  g_Hd[BN * DD];
__device__ __align__(16) float  g_x1[BN * DD];
__device__ __align__(16) float  g_qkv[BN * 768];
__device__ __align__(16) __half g_biash[4 * 8 * 256 * 256];
__device__ __align__(16) float  g_o[BN * DD];
__device__ __align__(16) float  g_h1[BN * DD];
__device__ __align__(16) float  g_y[BN * DD];
__device__ __align__(16) float  g_ffn[BN * 1024];
__device__ __align__(16) __half g_WeTh[DD * DD];
__device__ __align__(16) __half g_WqkvTh[768 * DD];
__device__ __align__(16) __half g_WoTh[DD * DD];
__device__ __align__(16) __half g_W1Th[1024 * DD];
__device__ __align__(16) __half g_W2Th[DD * 1024];
__device__ __align__(16) __half g_WsTh[DD * DD];
__device__ __align__(16) __half g_WdTh[DD * DD];

// ---------------- streams/events (created at load time, pre-baseline) ----
struct EdgeStreams {
    cudaStream_t s2;
    cudaEvent_t evT, evD, evQ;
    EdgeStreams() {
        cudaStreamCreateWithFlags(&s2, cudaStreamNonBlocking);
        cudaEventCreateWithFlags(&evT, cudaEventDisableTiming);
        cudaEventCreateWithFlags(&evD, cudaEventDisableTiming);
        cudaEventCreateWithFlags(&evQ, cudaEventDisableTiming);
    }
};
static EdgeStreams g_str;

// ---------------- helpers ----------------
__device__ __forceinline__ uint32_t smem_u32(const void* p) {
    uint32_t a;
    asm("{ .reg .u64 t; cvta.to.shared.u64 t, %1; cvt.u32.u64 %0, t; }"
        : "=r"(a) : "l"(p));
    return a;
}
__device__ __forceinline__ void cp16(uint32_t dst, const void* src) {
    asm volatile("cp.async.cg.shared.global [%0], [%1], 16;"
                 :: "r"(dst), "l"(src));
}
__device__ __forceinline__ void ldmx4(uint32_t* r, uint32_t addr) {
    asm volatile(
        "ldmatrix.sync.aligned.m8n8.x4.shared.b16 {%0,%1,%2,%3}, [%4];"
        : "=r"(r[0]), "=r"(r[1]), "=r"(r[2]), "=r"(r[3]) : "r"(addr));
}
__device__ __forceinline__ void mma_f16(float* c, const uint32_t* a,
                                        uint32_t b0, uint32_t b1) {
    asm volatile(
        "mma.sync.aligned.m16n8k16.row.col.f32.f16.f16.f32 "
        "{%0,%1,%2,%3}, {%4,%5,%6,%7}, {%8,%9}, {%0,%1,%2,%3};"
        : "+f"(c[0]), "+f"(c[1]), "+f"(c[2]), "+f"(c[3])
        : "r"(a[0]), "r"(a[1]), "r"(a[2]), "r"(a[3]), "r"(b0), "r"(b1));
}
__device__ __forceinline__ uint32_t pack_h2(float x, float y) {
    __half2 h = __float22half2_rn(make_float2(x, y));
    return *reinterpret_cast<uint32_t*>(&h);
}
__device__ __forceinline__ float gelu_exact(float x) {
    return 0.5f * x * (1.0f + erff(x * 0.70710678118654752f));
}

// ---------------- tiled weight transpose+fp16 (coalesced) ----------------
__global__ __launch_bounds__(256) void transpose_all(
    const float* __restrict__ We,  const float* __restrict__ Wqkv,
    const float* __restrict__ Wo,  const float* __restrict__ W1,
    const float* __restrict__ W2,  const float* __restrict__ Ws,
    const float* __restrict__ Wd,
    __half* __restrict__ oWe,  __half* __restrict__ oWqkv,
    __half* __restrict__ oWo,  __half* __restrict__ oW1,
    __half* __restrict__ oW2,  __half* __restrict__ oWs,
    __half* __restrict__ oWd)
{
    __shared__ float s[32][33];
    int bid = blockIdx.x;
    const float* in; __half* out; int K, N, t;
    if (bid < 64)        { in = We;   out = oWe;   K = 256;  N = 256;  t = bid; }
    else if (bid < 256)  { in = Wqkv; out = oWqkv; K = 256;  N = 768;  t = bid - 64; }
    else if (bid < 320)  { in = Wo;   out = oWo;   K = 256;  N = 256;  t = bid - 256; }
    else if (bid < 576)  { in = W1;   out = oW1;   K = 256;  N = 1024; t = bid - 320; }
    else if (bid < 832)  { in = W2;   out = oW2;   K = 1024; N = 256;  t = bid - 576; }
    else if (bid < 896)  { in = Ws;   out = oWs;   K = 256;  N = 256;  t = bid - 832; }
    else                 { in = Wd;   out = oWd;   K = 256;  N = 256;  t = bid - 896; }
    const int ntn = N >> 5;
    const int k0 = (t / ntn) << 5, n0 = (t % ntn) << 5;
    const int r = threadIdx.x >> 5, c = threadIdx.x & 31;
    #pragma unroll
    for (int q = 0; q < 4; ++q)
        s[r + q * 8][c] = in[(size_t)(k0 + r + q * 8) * N + n0 + c];
    __syncthreads();
    #pragma unroll
    for (int q = 0; q < 4; ++q)
        out[(size_t)(n0 + r + q * 8) * K + k0 + c] =
            __float2half_rn(s[c][r + q * 8]);
}

// ---------------- edge kernel: 64x256 tile, 256 thr, 2 CTAs/SM ----------
#define SB_B     0
#define SB_A     65536
#define SM_SHS   81920
#define SM_SBIAS 82944
#define SM_EDGE_TOTAL 91136

__global__ __launch_bounds__(256, 2) void edge_mma_kernel(
    const float* __restrict__ e, const __half* __restrict__ WeTh,
    const float* __restrict__ Hs, const float* __restrict__ Hd,
    const float* __restrict__ Wb,
    float* __restrict__ e_new, __half* __restrict__ bias)
{
    extern __shared__ char smem[];
    const uint32_t sb = smem_u32(smem);
    float* sHs   = (float*)(smem + SM_SHS);
    float* sbias = (float*)(smem + SM_SBIAS);

    const int tid = threadIdx.x;
    const int w = tid >> 5, lane = tid & 31;
    const int g = lane >> 2, tig = lane & 3, x7 = lane & 7;
    const int wr = w >> 2, wc = w & 3;

    const int m0 = blockIdx.x * 64;
    const int b = m0 >> 16, i = (m0 >> 8) & 255, j0 = m0 & 255;

    // ---- B chunk 0 (256 n-rows x 64 k) via cp.async ----
    #pragma unroll
    for (int it = 0; it < 8; ++it) {
        int idx = tid + it * 256;
        int r = idx >> 3, ch = idx & 7;
        cp16(sb + SB_B + r * 128 + ((ch ^ (r & 7)) << 4),
             WeTh + (size_t)r * 256 + ch * 8);
    }
    asm volatile("cp.async.commit_group;");

    // ---- A chunk 0: LDG fp32 -> fp16 STS (64 rows x 64 k) ----
    const float* Ab = e + (size_t)m0 * 256;
    #pragma unroll
    for (int p = 0; p < 2; ++p) {
        int idx = tid + p * 256;
        int row = idx >> 3, seg = idx & 7;
        const float* ptr = Ab + (size_t)row * 256 + seg * 8;
        float4 v0 = *(const float4*)ptr;
        float4 v1 = *(const float4*)(ptr + 4);
        uint4 u = make_uint4(pack_h2(v0.x, v0.y), pack_h2(v0.z, v0.w),
                             pack_h2(v1.x, v1.y), pack_h2(v1.z, v1.w));
        *(uint4*)(smem + SB_A + row * 128 + ((seg ^ (row & 7)) << 4)) = u;
    }

    // ---- tables ----
    sHs[tid] = Hs[(((size_t)(b << 8) + i) << 8) + tid];

    asm volatile("cp.async.wait_group 0;" ::: "memory");
    __syncthreads();

    const int rowoffA = x7 + (((lane >> 3) & 1) << 3);
    const int selA = lane >> 4;
    const int rowoffB = x7 + ((lane >> 4) << 3);
    const int selB = (lane >> 3) & 1;

    float acc[2][8][4] = {};
    float4 pre[4];

    for (int c = 0; c < 4; ++c) {
        if (c < 3) {
            #pragma unroll
            for (int it = 0; it < 8; ++it) {
                int idx = tid + it * 256;
                int r = idx >> 3, ch = idx & 7;
                cp16(sb + SB_B + (((c + 1) & 1) << 15) + r * 128 +
                         ((ch ^ (r & 7)) << 4),
                     WeTh + (size_t)r * 256 + (c + 1) * 64 + ch * 8);
            }
            asm volatile("cp.async.commit_group;");
            #pragma unroll
            for (int p = 0; p < 2; ++p) {
                int idx = tid + p * 256;
                int row = idx >> 3, seg = idx & 7;
                const float* ptr =
                    Ab + (size_t)row * 256 + (c + 1) * 64 + seg * 8;
                pre[p * 2]     = *(const float4*)ptr;
                pre[p * 2 + 1] = *(const float4*)(ptr + 4);
            }
        }
        const uint32_t sAc = sb + SB_A + ((c & 1) << 13);
        const uint32_t sBc = sb + SB_B + ((c & 1) << 15);
        #pragma unroll
        for (int kk = 0; kk < 4; ++kk) {
            uint32_t a0[4], a1[4];
            {
                int rowA = wr * 32 + rowoffA;
                ldmx4(a0, sAc + rowA * 128 + ((((kk << 1) + selA) ^ x7) << 4));
                ldmx4(a1, sAc + (rowA + 16) * 128 +
                              ((((kk << 1) + selA) ^ x7) << 4));
            }
            uint32_t bf[4][4];
            #pragma unroll
            for (int nt2 = 0; nt2 < 4; ++nt2) {
                int rowB = wc * 64 + nt2 * 16 + rowoffB;
                ldmx4(bf[nt2], sBc + rowB * 128 +
                               ((((kk << 1) + selB) ^ x7) << 4));
            }
            #pragma unroll
            for (int nt2 = 0; nt2 < 4; ++nt2) {
                mma_f16(acc[0][nt2 * 2],     a0, bf[nt2][0], bf[nt2][1]);
                mma_f16(acc[0][nt2 * 2 + 1], a0, bf[nt2][2], bf[nt2][3]);
                mma_f16(acc[1][nt2 * 2],     a1, bf[nt2][0], bf[nt2][1]);
                mma_f16(acc[1][nt2 * 2 + 1], a1, bf[nt2][2], bf[nt2][3]);
            }
        }
        __syncthreads();
        if (c < 3) {
            char* dst = smem + SB_A + (((c + 1) & 1) << 13);
            #pragma unroll
            for (int p = 0; p < 2; ++p) {
                int idx = tid + p * 256;
                int row = idx >> 3, seg = idx & 7;
                float4 v0 = pre[p * 2], v1 = pre[p * 2 + 1];
                uint4 u = make_uint4(pack_h2(v0.x, v0.y), pack_h2(v0.z, v0.w),
                                     pack_h2(v1.x, v1.y), pack_h2(v1.z, v1.w));
                *(uint4*)(dst + row * 128 + ((seg ^ (row & 7)) << 4)) = u;
            }
            asm volatile("cp.async.wait_group 0;" ::: "memory");
            __syncthreads();
        }
    }
    __syncthreads();   // B stage buffers (64KB @0) now dead -> staging

    const int mtile = w >> 1, khalf = w & 1;
    uint32_t bw0[8], bw1[8];
    #pragma unroll
    for (int kc = 0; kc < 8; ++kc) {
        int k0 = khalf * 128 + kc * 16 + 2 * tig;
        bw0[kc] = pack_h2(Wb[(k0    ) * 8 + g], Wb[(k0 + 1) * 8 + g]);
        bw1[kc] = pack_h2(Wb[(k0 + 8) * 8 + g], Wb[(k0 + 9) * 8 + g]);
    }

    // ---- pass A: stage fp16(acc + Hs) into SB_B, swizzled ----
    char* stg = smem + SB_B;
    #pragma unroll
    for (int mt = 0; mt < 2; ++mt) {
        const int rl = wr * 32 + mt * 16 + g;
        #pragma unroll
        for (int nt = 0; nt < 8; ++nt) {
            const int cl = wc * 64 + nt * 8 + 2 * tig;
            float2 hs = *(const float2*)(sHs + cl);
            uint32_t u0 = pack_h2(acc[mt][nt][0] + hs.x, acc[mt][nt][1] + hs.y);
            uint32_t u1 = pack_h2(acc[mt][nt][2] + hs.x, acc[mt][nt][3] + hs.y);
            const int chunk = wc * 8 + nt;
            *(uint32_t*)(stg + rl * 512 + ((chunk ^ g) << 4) + 4 * tig) = u0;
            *(uint32_t*)(stg + (rl + 8) * 512 + ((chunk ^ g) << 4) + 4 * tig) = u1;
        }
    }
    __syncthreads();

    // ---- pass B: coalesced +Hd, ReLU, e_new store; relu'd fp16 in place --
    {
        const float* hdb = Hd + (((size_t)(b << 8) + j0) << 8);
        float* eb = e_new + (size_t)m0 * 256;
        #pragma unroll
        for (int p = 0; p < 16; ++p) {
            int idx = p * 256 + tid;
            int r = idx >> 6, c4 = idx & 63;
            uint32_t soff = r * 512 + (((c4 >> 1) ^ (r & 7)) << 4) + (c4 & 1) * 8;
            uint2 hv = *(uint2*)(stg + soff);
            float2 f0 = __half22float2(*(__half2*)&hv.x);
            float2 f1 = __half22float2(*(__half2*)&hv.y);
            float4 hd4 = *(const float4*)(hdb + (size_t)r * 256 + c4 * 4);
            float x0 = fmaxf(f0.x + hd4.x, 0.0f);
            float x1 = fmaxf(f0.y + hd4.y, 0.0f);
            float x2 = fmaxf(f1.x + hd4.z, 0.0f);
            float x3 = fmaxf(f1.y + hd4.w, 0.0f);
            *(float4*)(eb + (size_t)r * 256 + c4 * 4) =
                make_float4(x0, x1, x2, x3);
            uint2 wb;
            wb.x = pack_h2(x0, x1);
            wb.y = pack_h2(x2, x3);
            *(uint2*)(stg + soff) = wb;
        }
    }
    __syncthreads();

    // ---- pass C: bias = relu'd x @ Wb via mma from staging ----
    {
        float bc4[4] = {0.0f, 0.0f, 0.0f, 0.0f};
        #pragma unroll
        for (int kk = 0; kk < 8; ++kk) {
            uint32_t a[4];
            int rowA = mtile * 16 + rowoffA;
            ldmx4(a, sb + SB_B + rowA * 512 +
                     (((khalf * 16 + kk * 2 + selA) ^ x7) << 4));
            mma_f16(bc4, a, bw0[kk], bw1[kk]);
        }
        float* sbw = sbias + khalf * 512;
        int rl = mtile * 16 + g;
        sbw[rl * 8 + 2 * tig]           = bc4[0];
        sbw[rl * 8 + 2 * tig + 1]       = bc4[1];
        sbw[(rl + 8) * 8 + 2 * tig]     = bc4[2];
        sbw[(rl + 8) * 8 + 2 * tig + 1] = bc4[3];
    }
    __syncthreads();
    #pragma unroll
    for (int q = 0; q < 2; ++q) {
        int t = tid + q * 256;
        int r = t & 63, hh = t >> 6;
        float v = sbias[r * 8 + hh] + sbias[512 + r * 8 + hh];
        bias[((((size_t)b * 8 + hh) * 256 + i) << 8) + j0 + r] =
            __float2half_rn(v);
    }
}

// ---------------- fp16 MMA GEMM: 64x64 tile, 256 thr (8 warps 2x4) ------
template <int OP, bool RES>
__global__ __launch_bounds__(256) void gemm_mma64(
    const float* __restrict__ A, const __half* __restrict__ Wh,
    const float* __restrict__ bias, const float* __restrict__ bias2,
    const float* __restrict__ res,
    float* __restrict__ out, int K, int N)
{
    extern __shared__ char sm2[];
    const uint32_t sb = smem_u32(sm2);
    const int tid = threadIdx.x;
    const int w = tid >> 5, lane = tid & 31;
    const int g = lane >> 2, tig = lane & 3, x7 = lane & 7;
    const int wr = w >> 2, wc = w & 3;
    const int m0 = blockIdx.y * 64, n0 = blockIdx.x * 64;
    const int NC = K >> 6;

    const float*  Ab = A + (size_t)m0 * K;
    const __half* Bb = Wh + (size_t)n0 * K;
    const int arow = tid >> 2;
    const int cpair = tid & 3;

    #pragma unroll
    for (int p = 0; p < 2; ++p) {
        int idx = tid + p * 256;
        int r = idx >> 3, ch = idx & 7;
        cp16(sb + 16384 + r * 128 + ((ch ^ (r & 7)) << 4),
             Bb + (size_t)r * K + ch * 8);
    }
    asm volatile("cp.async.commit_group;");
    #pragma unroll
    for (int q = 0; q < 2; ++q) {
        int ch = cpair * 2 + q;
        const float* p = Ab + (size_t)arow * K + ch * 8;
        float4 v0 = *(const float4*)p;
        float4 v1 = *(const float4*)(p + 4);
        uint4 u = make_uint4(pack_h2(v0.x, v0.y), pack_h2(v0.z, v0.w),
                             pack_h2(v1.x, v1.y), pack_h2(v1.z, v1.w));
        *(uint4*)(sm2 + arow * 128 + ((ch ^ (arow & 7)) << 4)) = u;
    }
    asm volatile("cp.async.wait_group 0;" ::: "memory");
    __syncthreads();

    const int rowoffA = x7 + (((lane >> 3) & 1) << 3);
    const int selA = lane >> 4;
    const int rowoffB = x7 + ((lane >> 4) << 3);
    const int selB = (lane >> 3) & 1;

    float acc[2][2][4] = {};
    float4 pre[4];

    for (int c = 0; c < NC; ++c) {
        if (c + 1 < NC) {
            #pragma unroll
            for (int p = 0; p < 2; ++p) {
                int idx = tid + p * 256;
                int r = idx >> 3, ch = idx & 7;
                cp16(sb + 16384 + (((c + 1) & 1) << 13) + r * 128 +
                         ((ch ^ (r & 7)) << 4),
                     Bb + (size_t)r * K + (c + 1) * 64 + ch * 8);
            }
            asm volatile("cp.async.commit_group;");
            #pragma unroll
            for (int q = 0; q < 2; ++q) {
                int ch = cpair * 2 + q;
                const float* p = Ab + (size_t)arow * K + (c + 1) * 64 + ch * 8;
                pre[q * 2]     = *(const float4*)p;
                pre[q * 2 + 1] = *(const float4*)(p + 4);
            }
        }
        const uint32_t sA = sb + ((c & 1) << 13);
        const uint32_t sB = sb + 16384 + ((c & 1) << 13);
        #pragma unroll
        for (int kk = 0; kk < 4; ++kk) {
            uint32_t a0[4], a1[4];
            int rA = wr * 32 + rowoffA;
            ldmx4(a0, sA + rA * 128 + ((((kk << 1) + selA) ^ x7) << 4));
            ldmx4(a1, sA + (rA + 16) * 128 + ((((kk << 1) + selA) ^ x7) << 4));
            uint32_t bf[4];
            int rB = wc * 16 + rowoffB;
            ldmx4(bf, sB + rB * 128 + ((((kk << 1) + selB) ^ x7) << 4));
            mma_f16(acc[0][0], a0, bf[0], bf[1]);
            mma_f16(acc[0][1], a0, bf[2], bf[3]);
            mma_f16(acc[1][0], a1, bf[0], bf[1]);
            mma_f16(acc[1][1], a1, bf[2], bf[3]);
        }
        __syncthreads();
        if (c + 1 < NC) {
            char* dst = sm2 + (((c + 1) & 1) << 13);
            #pragma unroll
            for (int q = 0; q < 2; ++q) {
                int ch = cpair * 2 + q;
                float4 v0 = pre[q * 2], v1 = pre[q * 2 + 1];
                uint4 u = make_uint4(pack_h2(v0.x, v0.y), pack_h2(v0.z, v0.w),
                                     pack_h2(v1.x, v1.y), pack_h2(v1.z, v1.w));
                *(uint4*)(dst + arow * 128 + ((ch ^ (arow & 7)) << 4)) = u;
            }
            asm volatile("cp.async.wait_group 0;" ::: "memory");
            __syncthreads();
        }
    }

    #pragma unroll
    for (int mt = 0; mt < 2; ++mt) {
        #pragma unroll
        for (int rh = 0; rh < 2; ++rh) {
            int rl = wr * 32 + mt * 16 + rh * 8 + g;
            float* orow = out + (size_t)(m0 + rl) * N + n0;
            const float* rrow = RES ? res + (size_t)(m0 + rl) * N + n0 : nullptr;
            #pragma unroll
            for (int nh = 0; nh < 2; ++nh) {
                int cl = wc * 16 + nh * 8 + 2 * tig;
                float b0 = __ldg(bias + n0 + cl);
                float b1 = __ldg(bias + n0 + cl + 1);
                if (bias2) {
                    b0 += __ldg(bias2 + n0 + cl);
                    b1 += __ldg(bias2 + n0 + cl + 1);
                }
                float x0 = acc[mt][nh][rh * 2 + 0] + b0;
                float x1 = acc[mt][nh][rh * 2 + 1] + b1;
                if (OP == 1) { x0 = gelu_exact(x0); x1 = gelu_exact(x1); }
                if (RES) {
                    float2 rv = *(const float2*)(rrow + cl);
                    x0 += rv.x; x1 += rv.y;
                }
                *(float2*)(orow + cl) = make_float2(x0, x1);
            }
        }
    }
}

// ---------------- LayerNorm ----------------
__global__ __launch_bounds__(256) void ln_kernel(
    const float* __restrict__ in, const float* __restrict__ g,
    const float* __restrict__ b, float* __restrict__ out)
{
    int row = blockIdx.x;
    int t = threadIdx.x;
    float v = in[(size_t)row * 256 + t];
    __shared__ float red[8];

    float s = v;
    #pragma unroll
    for (int o = 16; o; o >>= 1) s += __shfl_xor_sync(0xffffffffu, s, o);
    if ((t & 31) == 0) red[t >> 5] = s;
    __syncthreads();
    float mean = (red[0] + red[1] + red[2] + red[3] +
                  red[4] + red[5] + red[6] + red[7]) * (1.0f / 256.0f);
    float d = v - mean;
    __syncthreads();
    s = d * d;
    #pragma unroll
    for (int o = 16; o; o >>= 1) s += __shfl_xor_sync(0xffffffffu, s, o);
    if ((t & 31) == 0) red[t >> 5] = s;
    __syncthreads();
    float var = (red[0] + red[1] + red[2] + red[3] +
                 red[4] + red[5] + red[6] + red[7]) * (1.0f / 256.0f);
    out[(size_t)row * 256 + t] = d * rsqrtf(var + 1e-5f) * g[t] + b[t];
}

// ---------------- attention kernel: fp16 k/v smem, fp16 bias -------------
__global__ __launch_bounds__(256, 2) void attn_kernel(
    const float* __restrict__ qkv, const __half* __restrict__ bias,
    const float* __restrict__ bb, float* __restrict__ o)
{
    extern __shared__ float sm[];
    __half2* ks2 = (__half2*)sm;                 // [256][17]
    __half2* vs2 = ks2 + 256 * 17;               // [256][17]
    float*   qs  = (float*)(vs2 + 256 * 17);     // [16][33]

    const int tid = threadIdx.x;
    const int tile = blockIdx.x & 15;
    const int bh = blockIdx.x >> 4;
    const int b = bh >> 3, hh = bh & 7;
    const int i0 = tile * 16;
    const float bbv = bb[hh];

    #pragma unroll
    for (int it = 0; it < 16; ++it) {
        int idx = tid + it * 256;
        int j = idx >> 4, d2 = idx & 15;
        const float* base = qkv + (size_t)(b * 256 + j) * 768 + hh * 32 + d2 * 2;
        float2 kk = *(const float2*)(base + 256);
        float2 vv = *(const float2*)(base + 512);
        ks2[j * 17 + d2] = __float22half2_rn(kk);
        vs2[j * 17 + d2] = __float22half2_rn(vv);
    }
    #pragma unroll
    for (int it = 0; it < 2; ++it) {
        int idx = tid + it * 256;
        int r = idx >> 5, d = idx & 31;
        qs[r * 33 + d] = qkv[(size_t)(b * 256 + i0 + r) * 768 + hh * 32 + d];
    }
    __syncthreads();

    const int r = tid >> 4, s = tid & 15;
    const int i = i0 + r;
    const __half* brow = bias + ((((size_t)b * 8 + hh) * 256 + i) << 8);

    float q[32];
    #pragma unroll
    for (int d = 0; d < 32; ++d) q[d] = qs[r * 33 + d];

    float sc[16];
    float mx = -1e30f;
    #pragma unroll
    for (int jj = 0; jj < 16; ++jj) {
        int j = jj * 16 + s;
        const __half2* kp = ks2 + j * 17;
        float a = 0.0f;
        #pragma unroll
        for (int d2 = 0; d2 < 16; ++d2) {
            float2 kf = __half22float2(kp[d2]);
            a += q[2 * d2] * kf.x + q[2 * d2 + 1] * kf.y;
        }
        a = a * 0.17677669529663687f + __half2float(brow[j]) + bbv;
        sc[jj] = a;
        mx = fmaxf(mx, a);
    }
    #pragma unroll
    for (int off = 8; off; off >>= 1)
        mx = fmaxf(mx, __shfl_xor_sync(0xffffffffu, mx, off));

    float sum = 0.0f;
    #pragma unroll
    for (int jj = 0; jj < 16; ++jj) {
        sc[jj] = __expf(sc[jj] - mx);
        sum += sc[jj];
    }
    #pragma unroll
    for (int off = 8; off; off >>= 1)
        sum += __shfl_xor_sync(0xffffffffu, sum, off);
    float inv = 1.0f / sum;

    float oacc[32] = {};
    #pragma unroll
    for (int jj = 0; jj < 16; ++jj) {
        int j = jj * 16 + s;
        float wgt = sc[jj];
        const __half2* vp = vs2 + j * 17;
        #pragma unroll
        for (int d2 = 0; d2 < 16; ++d2) {
            float2 vf = __half22float2(vp[d2]);
            oacc[2 * d2]     += wgt * vf.x;
            oacc[2 * d2 + 1] += wgt * vf.y;
        }
    }

    float w2[2];
    #pragma unroll
    for (int d = 0; d < 32; ++d) {
        float t = oacc[d];
        t += __shfl_xor_sync(0xffffffffu, t, 1);
        t += __shfl_xor_sync(0xffffffffu, t, 2);
        t += __shfl_xor_sync(0xffffffffu, t, 4);
        t += __shfl_xor_sync(0xffffffffu, t, 8);
        if ((d >> 1) == s) w2[d & 1] = t;
    }
    *(float2*)(o + ((size_t)(b * 256 + i)) * 256 + hh * 32 + s * 2) =
        make_float2(w2[0] * inv, w2[1] * inv);
}

// ---------------- launch ----------------
extern "C" void kernel_launch(void* const* d_in, const int* in_sizes, int n_in,
                              void* d_out, int out_size)
{
    (void)in_sizes; (void)n_in; (void)out_size;
    const float* h    = (const float*)d_in[0];
    const float* e    = (const float*)d_in[1];
    const float* We   = (const float*)d_in[2];
    const float* be   = (const float*)d_in[3];
    const float* Ws   = (const float*)d_in[4];
    const float* bs   = (const float*)d_in[5];
    const float* Wd   = (const float*)d_in[6];
    const float* bd   = (const float*)d_in[7];
    const float* Wb   = (const float*)d_in[8];
    const float* bb   = (const float*)d_in[9];
    const float* ln1g = (const float*)d_in[10];
    const float* ln1b = (const float*)d_in[11];
    const float* Wqkv = (const float*)d_in[12];
    const float* bqkv = (const float*)d_in[13];
    const float* Wo   = (const float*)d_in[14];
    const float* bo   = (const float*)d_in[15];
    const float* ln2g = (const float*)d_in[16];
    const float* ln2b = (const float*)d_in[17];
    const float* W1   = (const float*)d_in[18];
    const float* b1   = (const float*)d_in[19];
    const float* W2   = (const float*)d_in[20];
    const float* b2   = (const float*)d_in[21];

    float* out_h2 = (float*)d_out;
    float* out_e  = out_h2 + (size_t)BN * DD;

    float *pHs, *pHd, *px1, *pqkv, *po, *ph1, *py, *pf;
    __half *pbiash, *pWeTh, *pWqkvTh, *pWoTh, *pW1Th, *pW2Th, *pWsTh, *pWdTh;
    cudaGetSymbolAddress((void**)&pHs,     g_Hs);
    cudaGetSymbolAddress((void**)&pHd,     g_Hd);
    cudaGetSymbolAddress((void**)&px1,     g_x1);
    cudaGetSymbolAddress((void**)&pqkv,    g_qkv);
    cudaGetSymbolAddress((void**)&pbiash,  g_biash);
    cudaGetSymbolAddress((void**)&po,      g_o);
    cudaGetSymbolAddress((void**)&ph1,     g_h1);
    cudaGetSymbolAddress((void**)&py,      g_y);
    cudaGetSymbolAddress((void**)&pf,      g_ffn);
    cudaGetSymbolAddress((void**)&pWeTh,   g_WeTh);
    cudaGetSymbolAddress((void**)&pWqkvTh, g_WqkvTh);
    cudaGetSymbolAddress((void**)&pWoTh,   g_WoTh);
    cudaGetSymbolAddress((void**)&pW1Th,   g_W1Th);
    cudaGetSymbolAddress((void**)&pW2Th,   g_W2Th);
    cudaGetSymbolAddress((void**)&pWsTh,   g_WsTh);
    cudaGetSymbolAddress((void**)&pWdTh,   g_WdTh);

    cudaStream_t s0 = 0;
    cudaStream_t s2 = g_str.s2;

    // ---- main stream: transpose -> Hs ----
    transpose_all<<<960, 256, 0, s0>>>(We, Wqkv, Wo, W1, W2, Ws, Wd,
                                       pWeTh, pWqkvTh, pWoTh, pW1Th, pW2Th,
                                       pWsTh, pWdTh);
    cudaEventRecord(g_str.evT, s0);
    gemm_mma64<0, false><<<dim3(4, 16), 256, 32768, s0>>>(
        h, pWsTh, bs, be, nullptr, pHs, 256, 256);

    // ---- side stream: Hd, then ln1+qkv (overlap with edge) ----
    cudaStreamWaitEvent(s2, g_str.evT, 0);
    gemm_mma64<0, false><<<dim3(4, 16), 256, 32768, s2>>>(
        h, pWdTh, bd, nullptr, nullptr, pHd, 256, 256);
    cudaEventRecord(g_str.evD, s2);

    // ---- edge (needs Hs on s0, Hd via evD) ----
    cudaStreamWaitEvent(s0, g_str.evD, 0);
    cudaFuncSetAttribute(edge_mma_kernel,
                         cudaFuncAttributeMaxDynamicSharedMemorySize,
                         SM_EDGE_TOTAL);
    edge_mma_kernel<<<4096, 256, SM_EDGE_TOTAL, s0>>>(
        e, pWeTh, pHs, pHd, Wb, out_e, pbiash);

    // ---- side stream continues under edge: ln1 + qkv ----
    ln_kernel<<<BN, 256, 0, s2>>>(h, ln1g, ln1b, px1);
    gemm_mma64<0, false><<<dim3(12, 16), 256, 32768, s2>>>(
        px1, pWqkvTh, bqkv, nullptr, nullptr, pqkv, 256, 768);
    cudaEventRecord(g_str.evQ, s2);

    // ---- join: attention needs bias (s0) + qkv (s2) ----
    cudaStreamWaitEvent(s0, g_str.evQ, 0);
    attn_kernel<<<512, 256, 36928, s0>>>(pqkv, pbiash, bb, po);

    // output proj + residual
    gemm_mma64<0, true><<<dim3(4, 16), 256, 32768, s0>>>(
        po, pWoTh, bo, nullptr, h, ph1, 256, 256);

    // FFN
    ln_kernel<<<BN, 256, 0, s0>>>(ph1, ln2g, ln2b, py);
    gemm_mma64<1, false><<<dim3(16, 16), 256, 32768, s0>>>(
        py, pW1Th, b1, nullptr, nullptr, pf, 256, 1024);
    gemm_mma64<0, true><<<dim3(4, 16), 256, 32768, s0>>>(
        pf, pW2Th, b2, nullptr, ph1, out_h2, 1024, 256);
}